// round 1
// baseline (speedup 1.0000x reference)
#include <cuda_runtime.h>
#include <math.h>

// Problem constants
#define RTOT 8192     // QB*N tokens
#define DIMM 1024
#define HH 8
#define DD 128
#define NN 512
#define QBB 16
#define GCH 16        // gram split-K chunks (512 rows each)

// ---------------- static device scratch (no runtime allocation) ----------------
__device__ float d_fq[RTOT * DIMM];
__device__ float d_fk[RTOT * DIMM];
__device__ float d_fv[RTOT * DIMM];
__device__ float d_attb[RTOT * DIMM];
__device__ float d_mu[3][RTOT];
__device__ float d_rstd[3][RTOT];
__device__ float d_iqn[HH][RTOT];     // 1/||f_q row||
__device__ float d_ikn[HH][RTOT];     // 1/||f_k row||
__device__ float d_qr[HH][RTOT];      // variance ratio for q
__device__ float d_kr[HH][RTOT];      // variance ratio for k
__device__ float d_qmean[HH][RTOT];   // per-row mean of f_q head segment
__device__ float d_Cpart[HH * GCH][DD * DD];   // gram partials
__device__ float d_dscale[HH];                  // exp(-5*decorr_score)
__device__ float d_gpart[64][2 * DIMM];         // global-mean partials
__device__ float d_s1[HH];                      // cw + vw*dscale
__device__ float d_wws[HH];                     // ww
__device__ float d_M[HH * QBB][DD * DD];        // f_k^T diag(1/kn) f_v
__device__ float d_gv[HH * QBB][DD];            // sum_m kr[m] f_v[m,:]

__device__ __forceinline__ float warpsum(float v) {
#pragma unroll
    for (int o = 16; o; o >>= 1) v += __shfl_xor_sync(0xffffffffu, v, o);
    return v;
}

// ---------------- 1. per-row LayerNorm statistics for q,k,v ----------------
__global__ void rowstats_kernel(const float* __restrict__ q,
                                const float* __restrict__ k,
                                const float* __restrict__ v) {
    int idx = blockIdx.x;
    int t = idx >> 13;            // /8192 -> tensor id
    int r = idx & (RTOT - 1);
    const float* A = (t == 0) ? q : (t == 1) ? k : v;
    float4 x = ((const float4*)(A + (size_t)r * DIMM))[threadIdx.x];  // 256*4=1024
    float s = x.x + x.y + x.z + x.w;
    float sq = x.x * x.x + x.y * x.y + x.z * x.z + x.w * x.w;
    __shared__ float sh[16];
    s = warpsum(s); sq = warpsum(sq);
    int w = threadIdx.x >> 5, lane = threadIdx.x & 31;
    if (lane == 0) { sh[w] = s; sh[8 + w] = sq; }
    __syncthreads();
    if (threadIdx.x == 0) {
        float S = 0.f, SQ = 0.f;
#pragma unroll
        for (int i = 0; i < 8; i++) { S += sh[i]; SQ += sh[8 + i]; }
        float mu = S * (1.f / DIMM);
        float var = SQ * (1.f / DIMM) - mu * mu;
        d_mu[t][r] = mu;
        d_rstd[t][r] = rsqrtf(var + 1e-5f);
    }
}

// ---------------- 2. fused LN + projection GEMM: F = LN(X) @ W^T ----------------
// 128x128 tile, BK=8, 256 threads, 8x8 per thread.
__global__ void __launch_bounds__(256) proj_kernel(const float* __restrict__ X,
                                                   const float* __restrict__ W,
                                                   const float* __restrict__ lng,
                                                   const float* __restrict__ lnb,
                                                   int which) {
    __shared__ float As[8][128];
    __shared__ float Bs[8][128];
    float* C = (which == 0) ? d_fq : (which == 1) ? d_fk : d_fv;
    const float* mu = d_mu[which];
    const float* rstd = d_rstd[which];

    int tid = threadIdx.x;
    int m0 = blockIdx.y * 128, n0 = blockIdx.x * 128;
    int ty = tid >> 4, tx = tid & 15;
    int lrow = tid >> 1, lk4 = (tid & 1) << 2;

    float acc[8][8] = {};
    float muv = mu[m0 + lrow], rsv = rstd[m0 + lrow];
    const float* Arow = X + (size_t)(m0 + lrow) * DIMM;
    const float* Brow = W + (size_t)(n0 + lrow) * DIMM;

    for (int k0 = 0; k0 < DIMM; k0 += 8) {
        float4 a = *(const float4*)(Arow + k0 + lk4);
        float4 g4 = *(const float4*)(lng + k0 + lk4);
        float4 b4 = *(const float4*)(lnb + k0 + lk4);
        As[lk4 + 0][lrow] = (a.x - muv) * rsv * g4.x + b4.x;
        As[lk4 + 1][lrow] = (a.y - muv) * rsv * g4.y + b4.y;
        As[lk4 + 2][lrow] = (a.z - muv) * rsv * g4.z + b4.z;
        As[lk4 + 3][lrow] = (a.w - muv) * rsv * g4.w + b4.w;
        float4 b = *(const float4*)(Brow + k0 + lk4);
        Bs[lk4 + 0][lrow] = b.x;
        Bs[lk4 + 1][lrow] = b.y;
        Bs[lk4 + 2][lrow] = b.z;
        Bs[lk4 + 3][lrow] = b.w;
        __syncthreads();
#pragma unroll
        for (int kk = 0; kk < 8; kk++) {
            float ar[8], br[8];
            *(float4*)(ar)     = *(const float4*)(&As[kk][ty * 8]);
            *(float4*)(ar + 4) = *(const float4*)(&As[kk][ty * 8 + 4]);
            *(float4*)(br)     = *(const float4*)(&Bs[kk][tx * 8]);
            *(float4*)(br + 4) = *(const float4*)(&Bs[kk][tx * 8 + 4]);
#pragma unroll
            for (int i = 0; i < 8; i++)
#pragma unroll
                for (int j = 0; j < 8; j++) acc[i][j] += ar[i] * br[j];
        }
        __syncthreads();
    }
#pragma unroll
    for (int i = 0; i < 8; i++) {
        float* crow = C + (size_t)(m0 + ty * 8 + i) * DIMM + n0 + tx * 8;
        *(float4*)(crow)     = make_float4(acc[i][0], acc[i][1], acc[i][2], acc[i][3]);
        *(float4*)(crow + 4) = make_float4(acc[i][4], acc[i][5], acc[i][6], acc[i][7]);
    }
}

// ---------------- 3. per-(head,row) stats: norms, means, variance ratios ----------------
__global__ void headstats_kernel() {
    int r = blockIdx.x;
    int w = threadIdx.x >> 5, lane = threadIdx.x & 31;
    // f_q
    {
        float4 x = *(const float4*)(d_fq + (size_t)r * DIMM + w * DD + lane * 4);
        float s = x.x + x.y + x.z + x.w;
        float sq = x.x * x.x + x.y * x.y + x.z * x.z + x.w * x.w;
        s = warpsum(s); sq = warpsum(sq);
        if (lane == 0) {
            float mean = s * (1.f / DD);
            float var = (sq - s * s * (1.f / DD)) * (1.f / (DD - 1));
            d_iqn[w][r] = rsqrtf(sq);
            d_qmean[w][r] = mean;
            d_qr[w][r] = 2.f * fminf(var, 1.f) / (var + 1.f);
        }
    }
    // f_k
    {
        float4 x = *(const float4*)(d_fk + (size_t)r * DIMM + w * DD + lane * 4);
        float s = x.x + x.y + x.z + x.w;
        float sq = x.x * x.x + x.y * x.y + x.z * x.z + x.w * x.w;
        s = warpsum(s); sq = warpsum(sq);
        if (lane == 0) {
            float var = (sq - s * s * (1.f / DD)) * (1.f / (DD - 1));
            d_ikn[w][r] = rsqrtf(sq);
            d_kr[w][r] = 2.f * fminf(var, 1.f) / (var + 1.f);
        }
    }
}

// ---------------- 4. Gram matrix partials: C_h += qc^T qc over 512-row chunk ----------------
__global__ void __launch_bounds__(256) grampart_kernel() {
    int ch = blockIdx.x;     // 0..15
    int h = blockIdx.y;      // 0..7
    int r0 = ch * 512;
    __shared__ float s[8][128];
    int tid = threadIdx.x;
    int ty = tid >> 4, tx = tid & 15;
    int lrow = tid >> 5, lcol = (tid & 31) << 2;
    float acc[8][8] = {};
    for (int t = 0; t < 64; t++) {
        int rb = r0 + t * 8;
        float m = d_qmean[h][rb + lrow];
        float4 xv = *(const float4*)(d_fq + (size_t)(rb + lrow) * DIMM + h * DD + lcol);
        s[lrow][lcol + 0] = xv.x - m;
        s[lrow][lcol + 1] = xv.y - m;
        s[lrow][lcol + 2] = xv.z - m;
        s[lrow][lcol + 3] = xv.w - m;
        __syncthreads();
#pragma unroll
        for (int rr = 0; rr < 8; rr++) {
            float ra[8], rb_[8];
            *(float4*)(ra)      = *(const float4*)(&s[rr][ty * 8]);
            *(float4*)(ra + 4)  = *(const float4*)(&s[rr][ty * 8 + 4]);
            *(float4*)(rb_)     = *(const float4*)(&s[rr][tx * 8]);
            *(float4*)(rb_ + 4) = *(const float4*)(&s[rr][tx * 8 + 4]);
#pragma unroll
            for (int i = 0; i < 8; i++)
#pragma unroll
                for (int j = 0; j < 8; j++) acc[i][j] += ra[i] * rb_[j];
        }
        __syncthreads();
    }
    float* out = d_Cpart[h * GCH + ch];
#pragma unroll
    for (int i = 0; i < 8; i++) {
        float* row = out + (ty * 8 + i) * DD + tx * 8;
        *(float4*)(row)     = make_float4(acc[i][0], acc[i][1], acc[i][2], acc[i][3]);
        *(float4*)(row + 4) = make_float4(acc[i][4], acc[i][5], acc[i][6], acc[i][7]);
    }
}

// ---------------- 5. reduce gram partials -> off-diag Frobenius -> decorr scale ----------------
__global__ void creduce_kernel() {
    int h = blockIdx.x;
    float ssum = 0.f;
    for (int i = threadIdx.x; i < DD * DD; i += 256) {
        float c = 0.f;
#pragma unroll
        for (int p = 0; p < GCH; p++) c += d_Cpart[h * GCH + p][i];
        if ((i / DD) != (i % DD)) ssum += c * c;
    }
    __shared__ float sh[8];
    ssum = warpsum(ssum);
    int w = threadIdx.x >> 5, lane = threadIdx.x & 31;
    if (lane == 0) sh[w] = ssum;
    __syncthreads();
    if (threadIdx.x == 0) {
        float S = 0.f;
#pragma unroll
        for (int i = 0; i < 8; i++) S += sh[i];
        float fro = sqrtf(S) * (1.f / RTOT);         // ||offdiag(Csum/8192)||_F
        float score = fro * (1.f / (128.f * 128.f));
        d_dscale[h] = expf(-5.f * score);
    }
}

// ---------------- 6. global column-sum partials over f_q / f_k ----------------
__global__ void gpart_kernel() {
    int b = blockIdx.x;   // 64 blocks, 128 rows each
    int r0 = b * 128;
    int t = threadIdx.x;
    float sq[4] = {}, sk[4] = {};
    for (int row = 0; row < 128; row++) {
        const float* fq = d_fq + (size_t)(r0 + row) * DIMM;
        const float* fk = d_fk + (size_t)(r0 + row) * DIMM;
#pragma unroll
        for (int c = 0; c < 4; c++) {
            sq[c] += fq[t + c * 256];
            sk[c] += fk[t + c * 256];
        }
    }
#pragma unroll
    for (int c = 0; c < 4; c++) {
        d_gpart[b][t + c * 256] = sq[c];
        d_gpart[b][DIMM + t + c * 256] = sk[c];
    }
}

// ---------------- 7. weight-predictor MLP + per-head scalars ----------------
__global__ void wp_kernel(const float* __restrict__ w1, const float* __restrict__ b1,
                          const float* __restrict__ lng, const float* __restrict__ lnb,
                          const float* __restrict__ w2, const float* __restrict__ b2) {
    __shared__ float qg[DIMM], kg[DIMM];
    __shared__ float h1[HH][DD];
    __shared__ float logits[HH][3];
    int tid = threadIdx.x;
    for (int i = tid; i < DIMM; i += 256) {
        float s = 0.f, s2 = 0.f;
        for (int b = 0; b < 64; b++) { s += d_gpart[b][i]; s2 += d_gpart[b][DIMM + i]; }
        qg[i] = s * (1.f / RTOT);
        kg[i] = s2 * (1.f / RTOT);
    }
    __syncthreads();
    for (int idx = tid; idx < HH * DD; idx += 256) {
        int h = idx / DD, i = idx % DD;
        float s = b1[i];
        const float* wr = w1 + i * 256;
#pragma unroll 4
        for (int j = 0; j < 128; j++) s += qg[h * 128 + j] * wr[j];
#pragma unroll 4
        for (int j = 0; j < 128; j++) s += kg[h * 128 + j] * wr[128 + j];
        h1[h][i] = s;
    }
    __syncthreads();
    int w = tid >> 5, lane = tid & 31;
    if (w < 8) {
        float s = 0.f, sq = 0.f;
        for (int i = lane; i < DD; i += 32) { float v = h1[w][i]; s += v; sq += v * v; }
        s = warpsum(s); sq = warpsum(sq);
        float mean = s * (1.f / DD);
        float var = sq * (1.f / DD) - mean * mean;
        float rs = rsqrtf(var + 1e-5f);
        for (int i = lane; i < DD; i += 32) {
            float v = (h1[w][i] - mean) * rs * lng[i] + lnb[i];
            h1[w][i] = fmaxf(v, 0.f);
        }
    }
    __syncthreads();
    if (tid < 24) {
        int h = tid / 3, c = tid % 3;
        float s = b2[c];
        const float* wr = w2 + c * DD;
        for (int i = 0; i < DD; i++) s += h1[h][i] * wr[i];
        logits[h][c] = s;
    }
    __syncthreads();
    if (tid < 8) {
        float a = logits[tid][0], b = logits[tid][1], c = logits[tid][2];
        float m = fmaxf(a, fmaxf(b, c));
        float ea = expf(a - m), eb = expf(b - m), ec = expf(c - m);
        float inv = 1.f / (ea + eb + ec);
        d_s1[tid] = ea * inv + eb * inv * d_dscale[tid];
        d_wws[tid] = ec * inv;
    }
}

// ---------------- 8. per-(h,qi): M = f_k^T diag(1/kn) f_v  and  g = sum kr*f_v ----------------
__global__ void __launch_bounds__(256) kvm_kernel() {
    int blk = blockIdx.x;          // 0..127
    int h = blk >> 4, qi = blk & 15;
    int r0 = qi * NN;
    int co = h * DD;
    __shared__ float ks[8][128], vs[8][128];
    __shared__ float krs[8];
    int tid = threadIdx.x;
    int ty = tid >> 4, tx = tid & 15;
    int lrow = tid >> 5, lcol = (tid & 31) << 2;
    float acc[8][8] = {};
    float gacc = 0.f;
    for (int t = 0; t < 64; t++) {
        int rb = r0 + t * 8;
        float sc = d_ikn[h][rb + lrow];
        float4 kv = *(const float4*)(d_fk + (size_t)(rb + lrow) * DIMM + co + lcol);
        ks[lrow][lcol + 0] = kv.x * sc;
        ks[lrow][lcol + 1] = kv.y * sc;
        ks[lrow][lcol + 2] = kv.z * sc;
        ks[lrow][lcol + 3] = kv.w * sc;
        float4 vv = *(const float4*)(d_fv + (size_t)(rb + lrow) * DIMM + co + lcol);
        *(float4*)(&vs[lrow][lcol]) = vv;
        if (tid < 8) krs[tid] = d_kr[h][rb + tid];
        __syncthreads();
#pragma unroll
        for (int rr = 0; rr < 8; rr++) {
            float ra[8], rb_[8];
            *(float4*)(ra)      = *(const float4*)(&ks[rr][ty * 8]);
            *(float4*)(ra + 4)  = *(const float4*)(&ks[rr][ty * 8 + 4]);
            *(float4*)(rb_)     = *(const float4*)(&vs[rr][tx * 8]);
            *(float4*)(rb_ + 4) = *(const float4*)(&vs[rr][tx * 8 + 4]);
#pragma unroll
            for (int i = 0; i < 8; i++)
#pragma unroll
                for (int j = 0; j < 8; j++) acc[i][j] += ra[i] * rb_[j];
        }
        if (tid < 128) {
#pragma unroll
            for (int rr = 0; rr < 8; rr++) gacc += krs[rr] * vs[rr][tid];
        }
        __syncthreads();
    }
    float* Mout = d_M[blk];
#pragma unroll
    for (int i = 0; i < 8; i++) {
        float* row = Mout + (ty * 8 + i) * DD + tx * 8;
        *(float4*)(row)     = make_float4(acc[i][0], acc[i][1], acc[i][2], acc[i][3]);
        *(float4*)(row + 4) = make_float4(acc[i][4], acc[i][5], acc[i][6], acc[i][7]);
    }
    if (tid < 128) d_gv[blk][tid] = gacc;
}

// ---------------- 9. attention out: att = diag(s1/qn) f_q M + ww qr g^T ----------------
__global__ void __launch_bounds__(256) attout_kernel() {
    int blk = blockIdx.y;          // (h,qi) 0..127
    int mt = blockIdx.x;           // row tile 0..3
    int h = blk >> 4, qi = blk & 15;
    int r0 = qi * NN + mt * 128;
    int co = h * DD;
    __shared__ float As[8][128];
    __shared__ float Bs[8][128];
    int tid = threadIdx.x;
    int ty = tid >> 4, tx = tid & 15;
    int lrow = tid >> 1, lk4 = (tid & 1) << 2;
    float acc[8][8] = {};
    const float* Mp = d_M[blk];
    const float* Aq = d_fq + (size_t)(r0 + lrow) * DIMM + co;
    for (int k0 = 0; k0 < DD; k0 += 8) {
        float4 a = *(const float4*)(Aq + k0 + lk4);
        As[lk4 + 0][lrow] = a.x;
        As[lk4 + 1][lrow] = a.y;
        As[lk4 + 2][lrow] = a.z;
        As[lk4 + 3][lrow] = a.w;
        float4 b = *(const float4*)(Mp + (k0 + (tid >> 5)) * DD + ((tid & 31) << 2));
        *(float4*)(&Bs[tid >> 5][(tid & 31) << 2]) = b;
        __syncthreads();
#pragma unroll
        for (int kk = 0; kk < 8; kk++) {
            float ar[8], br[8];
            *(float4*)(ar)     = *(const float4*)(&As[kk][ty * 8]);
            *(float4*)(ar + 4) = *(const float4*)(&As[kk][ty * 8 + 4]);
            *(float4*)(br)     = *(const float4*)(&Bs[kk][tx * 8]);
            *(float4*)(br + 4) = *(const float4*)(&Bs[kk][tx * 8 + 4]);
#pragma unroll
            for (int i = 0; i < 8; i++)
#pragma unroll
                for (int j = 0; j < 8; j++) acc[i][j] += ar[i] * br[j];
        }
        __syncthreads();
    }
    float s1 = d_s1[h], ww = d_wws[h];
    float gvr[8];
#pragma unroll
    for (int j = 0; j < 8; j++) gvr[j] = d_gv[blk][tx * 8 + j];
#pragma unroll
    for (int i = 0; i < 8; i++) {
        int r = r0 + ty * 8 + i;
        float f1 = s1 * d_iqn[h][r];
        float f2 = ww * d_qr[h][r];
        float o[8];
#pragma unroll
        for (int j = 0; j < 8; j++) o[j] = f1 * acc[i][j] + f2 * gvr[j];
        float* crow = d_attb + (size_t)r * DIMM + co + tx * 8;
        *(float4*)(crow)     = make_float4(o[0], o[1], o[2], o[3]);
        *(float4*)(crow + 4) = make_float4(o[4], o[5], o[6], o[7]);
    }
}

// ---------------- 10. final projection: out = att @ w_out^T + b_out ----------------
__global__ void __launch_bounds__(256) outproj_kernel(const float* __restrict__ W,
                                                      const float* __restrict__ bias,
                                                      float* __restrict__ C) {
    __shared__ float As[8][128];
    __shared__ float Bs[8][128];
    int tid = threadIdx.x;
    int m0 = blockIdx.y * 128, n0 = blockIdx.x * 128;
    int ty = tid >> 4, tx = tid & 15;
    int lrow = tid >> 1, lk4 = (tid & 1) << 2;
    float acc[8][8] = {};
    const float* Arow = d_attb + (size_t)(m0 + lrow) * DIMM;
    const float* Brow = W + (size_t)(n0 + lrow) * DIMM;
    for (int k0 = 0; k0 < DIMM; k0 += 8) {
        float4 a = *(const float4*)(Arow + k0 + lk4);
        As[lk4 + 0][lrow] = a.x;
        As[lk4 + 1][lrow] = a.y;
        As[lk4 + 2][lrow] = a.z;
        As[lk4 + 3][lrow] = a.w;
        float4 b = *(const float4*)(Brow + k0 + lk4);
        Bs[lk4 + 0][lrow] = b.x;
        Bs[lk4 + 1][lrow] = b.y;
        Bs[lk4 + 2][lrow] = b.z;
        Bs[lk4 + 3][lrow] = b.w;
        __syncthreads();
#pragma unroll
        for (int kk = 0; kk < 8; kk++) {
            float ar[8], br[8];
            *(float4*)(ar)     = *(const float4*)(&As[kk][ty * 8]);
            *(float4*)(ar + 4) = *(const float4*)(&As[kk][ty * 8 + 4]);
            *(float4*)(br)     = *(const float4*)(&Bs[kk][tx * 8]);
            *(float4*)(br + 4) = *(const float4*)(&Bs[kk][tx * 8 + 4]);
#pragma unroll
            for (int i = 0; i < 8; i++)
#pragma unroll
                for (int j = 0; j < 8; j++) acc[i][j] += ar[i] * br[j];
        }
        __syncthreads();
    }
#pragma unroll
    for (int i = 0; i < 8; i++) {
        float* crow = C + (size_t)(m0 + ty * 8 + i) * DIMM + n0 + tx * 8;
        float b0 = bias[n0 + tx * 8 + 0], b1 = bias[n0 + tx * 8 + 1];
        float b2 = bias[n0 + tx * 8 + 2], b3 = bias[n0 + tx * 8 + 3];
        float b4 = bias[n0 + tx * 8 + 4], b5 = bias[n0 + tx * 8 + 5];
        float b6 = bias[n0 + tx * 8 + 6], b7 = bias[n0 + tx * 8 + 7];
        *(float4*)(crow)     = make_float4(acc[i][0] + b0, acc[i][1] + b1, acc[i][2] + b2, acc[i][3] + b3);
        *(float4*)(crow + 4) = make_float4(acc[i][4] + b4, acc[i][5] + b5, acc[i][6] + b6, acc[i][7] + b7);
    }
}

// ---------------- launch ----------------
extern "C" void kernel_launch(void* const* d_in, const int* in_sizes, int n_in,
                              void* d_out, int out_size) {
    const float* q      = (const float*)d_in[0];
    const float* k      = (const float*)d_in[1];
    const float* v      = (const float*)d_in[2];
    const float* ln_g   = (const float*)d_in[3];
    const float* ln_b   = (const float*)d_in[4];
    const float* w_in   = (const float*)d_in[5];
    const float* wp_w1  = (const float*)d_in[6];
    const float* wp_b1  = (const float*)d_in[7];
    const float* wp_lng = (const float*)d_in[8];
    const float* wp_lnb = (const float*)d_in[9];
    const float* wp_w2  = (const float*)d_in[10];
    const float* wp_b2  = (const float*)d_in[11];
    const float* w_out  = (const float*)d_in[12];
    const float* b_out  = (const float*)d_in[13];
    float* out = (float*)d_out;

    rowstats_kernel<<<3 * RTOT, 256>>>(q, k, v);

    dim3 gproj(DIMM / 128, RTOT / 128);   // (8, 64)
    proj_kernel<<<gproj, 256>>>(q, w_in, ln_g, ln_b, 0);
    proj_kernel<<<gproj, 256>>>(k, w_in, ln_g, ln_b, 1);
    proj_kernel<<<gproj, 256>>>(v, w_in, ln_g, ln_b, 2);

    headstats_kernel<<<RTOT, 256>>>();

    dim3 ggram(GCH, HH);
    grampart_kernel<<<ggram, 256>>>();
    creduce_kernel<<<HH, 256>>>();

    gpart_kernel<<<64, 256>>>();
    wp_kernel<<<1, 256>>>(wp_w1, wp_b1, wp_lng, wp_lnb, wp_w2, wp_b2);

    kvm_kernel<<<HH * QBB, 256>>>();

    dim3 gatt(4, HH * QBB);
    attout_kernel<<<gatt, 256>>>();

    outproj_kernel<<<gproj, 256>>>(w_out, b_out, out);
}

// round 7
// speedup vs baseline: 2.3610x; 2.3610x over previous
#include <cuda_runtime.h>
#include <cuda_bf16.h>
#include <math.h>
#include <stdint.h>

// Problem constants
#define RTOT 8192     // QB*N tokens
#define DIMM 1024
#define HH 8
#define DD 128
#define NN 512
#define QBB 16
#define GCH 16        // gram split-K chunks (512 rows each)

// ---------------- static device scratch (no runtime allocation) ----------------
__device__ __nv_bfloat16 d_xh[3][RTOT * DIMM];   // LN(x) hi bf16 (q,k,v)
__device__ __nv_bfloat16 d_xl[3][RTOT * DIMM];   // LN(x) lo residual
__device__ __nv_bfloat16 d_oh[RTOT * DIMM];      // att output hi
__device__ __nv_bfloat16 d_ol[RTOT * DIMM];      // att output lo
__device__ __nv_bfloat16 d_wih[DIMM * DIMM], d_wil[DIMM * DIMM];  // w_in split
__device__ __nv_bfloat16 d_woh[DIMM * DIMM], d_wol[DIMM * DIMM];  // w_out split
__device__ float d_fq[RTOT * DIMM];
__device__ float d_fk[RTOT * DIMM];
__device__ float d_fv[RTOT * DIMM];
__device__ float d_iqn[HH][RTOT];
__device__ float d_ikn[HH][RTOT];
__device__ float d_qr[HH][RTOT];
__device__ float d_kr[HH][RTOT];
__device__ float d_qmean[HH][RTOT];
__device__ float d_Cpart[HH * GCH][DD * DD];
__device__ float d_dscale[HH];
__device__ float d_gpart[64][2 * DIMM];
__device__ float d_s1[HH];
__device__ float d_wws[HH];
__device__ float d_M[HH * QBB][DD * DD];
__device__ float d_gv[HH * QBB][DD];

__device__ __forceinline__ float warpsum(float v) {
#pragma unroll
    for (int o = 16; o; o >>= 1) v += __shfl_xor_sync(0xffffffffu, v, o);
    return v;
}

__device__ __forceinline__ uint32_t smem_u32(const void* p) {
    uint32_t a;
    asm("{ .reg .u64 t; cvta.to.shared.u64 t, %1; cvt.u32.u64 %0, t; }" : "=r"(a) : "l"(p));
    return a;
}

// split 4 fp32 -> bf16 hi (truncate) packed in uint2, bf16 lo (rn residual) in uint2
__device__ __forceinline__ void split4(float x0, float x1, float x2, float x3,
                                       uint2& h, uint2& l) {
    uint32_t u0 = __float_as_uint(x0), u1 = __float_as_uint(x1);
    uint32_t u2 = __float_as_uint(x2), u3 = __float_as_uint(x3);
    h.x = (u0 >> 16) | (u1 & 0xFFFF0000u);
    h.y = (u2 >> 16) | (u3 & 0xFFFF0000u);
    float l0 = x0 - __uint_as_float(u0 & 0xFFFF0000u);
    float l1 = x1 - __uint_as_float(u1 & 0xFFFF0000u);
    float l2 = x2 - __uint_as_float(u2 & 0xFFFF0000u);
    float l3 = x3 - __uint_as_float(u3 & 0xFFFF0000u);
    asm("cvt.rn.bf16x2.f32 %0, %1, %2;" : "=r"(l.x) : "f"(l1), "f"(l0));
    asm("cvt.rn.bf16x2.f32 %0, %1, %2;" : "=r"(l.y) : "f"(l3), "f"(l2));
}

// ---------------- fused rowstats + LayerNorm + bf16 split ----------------
__global__ void lnconv_kernel(const float* __restrict__ q, const float* __restrict__ k,
                              const float* __restrict__ v,
                              const float* __restrict__ lng, const float* __restrict__ lnb) {
    int idx = blockIdx.x;
    int t = idx >> 13;
    int r = idx & (RTOT - 1);
    const float* A = (t == 0) ? q : (t == 1) ? k : v;
    int tid = threadIdx.x;
    float4 x = ((const float4*)(A + (size_t)r * DIMM))[tid];
    float s = x.x + x.y + x.z + x.w;
    float sq = x.x * x.x + x.y * x.y + x.z * x.z + x.w * x.w;
    __shared__ float sh[16];
    __shared__ float smu, srs;
    s = warpsum(s); sq = warpsum(sq);
    int w = tid >> 5, lane = tid & 31;
    if (lane == 0) { sh[w] = s; sh[8 + w] = sq; }
    __syncthreads();
    if (tid == 0) {
        float S = 0.f, SQ = 0.f;
#pragma unroll
        for (int i = 0; i < 8; i++) { S += sh[i]; SQ += sh[8 + i]; }
        float mu = S * (1.f / DIMM);
        float var = SQ * (1.f / DIMM) - mu * mu;
        smu = mu;
        srs = rsqrtf(var + 1e-5f);
    }
    __syncthreads();
    float mu = smu, rs = srs;
    float4 g = ((const float4*)lng)[tid];
    float4 b = ((const float4*)lnb)[tid];
    float y0 = (x.x - mu) * rs * g.x + b.x;
    float y1 = (x.y - mu) * rs * g.y + b.y;
    float y2 = (x.z - mu) * rs * g.z + b.z;
    float y3 = (x.w - mu) * rs * g.w + b.w;
    uint2 hv, lv;
    split4(y0, y1, y2, y3, hv, lv);
    ((uint2*)(d_xh[t] + (size_t)r * DIMM))[tid] = hv;
    ((uint2*)(d_xl[t] + (size_t)r * DIMM))[tid] = lv;
}

// ---------------- weight convert: w_in rows 0-1023, w_out rows 1024-2047 ----------------
__global__ void wconv_kernel(const float* __restrict__ w_in, const float* __restrict__ w_out) {
    int row = blockIdx.x;
    int tid = threadIdx.x;
    const float* src;
    __nv_bfloat16 *H, *L;
    if (row < DIMM) {
        src = w_in + (size_t)row * DIMM;
        H = d_wih + (size_t)row * DIMM;
        L = d_wil + (size_t)row * DIMM;
    } else {
        src = w_out + (size_t)(row - DIMM) * DIMM;
        H = d_woh + (size_t)(row - DIMM) * DIMM;
        L = d_wol + (size_t)(row - DIMM) * DIMM;
    }
    float4 x = ((const float4*)src)[tid];
    uint2 hv, lv;
    split4(x.x, x.y, x.z, x.w, hv, lv);
    ((uint2*)H)[tid] = hv;
    ((uint2*)L)[tid] = lv;
}

// =====================================================================
//  bf16x3 mma.sync GEMM: C[8192x1024] = A @ B^T   (A,B pre-split hi/lo)
//  CTA tile 128x128, K stages of 64, 2-stage cp.async pipeline
// =====================================================================
__device__ __forceinline__ void cp16(uint32_t dst, const void* src) {
    asm volatile("cp.async.cg.shared.global [%0], [%1], 16;\n" :: "r"(dst), "l"(src));
}
__device__ __forceinline__ void ldsm_x4(uint32_t* r, uint32_t a) {
    asm volatile("ldmatrix.sync.aligned.m8n8.x4.shared.b16 {%0,%1,%2,%3}, [%4];\n"
                 : "=r"(r[0]), "=r"(r[1]), "=r"(r[2]), "=r"(r[3]) : "r"(a));
}
__device__ __forceinline__ void mma_bf16(float* d, const uint32_t* a, const uint32_t* b) {
    asm volatile(
        "mma.sync.aligned.m16n8k16.row.col.f32.bf16.bf16.f32 "
        "{%0,%1,%2,%3}, {%4,%5,%6,%7}, {%8,%9}, {%0,%1,%2,%3};\n"
        : "+f"(d[0]), "+f"(d[1]), "+f"(d[2]), "+f"(d[3])
        : "r"(a[0]), "r"(a[1]), "r"(a[2]), "r"(a[3]), "r"(b[0]), "r"(b[1]));
}

static constexpr int MM_STAGE = 65536;          // 4 parts x 16KB (128x64 bf16)
static constexpr int MM_SMEM = 2 * MM_STAGE;    // 128 KB

__device__ __forceinline__ void mm_fill(uint32_t sb, int s, int kb,
                                        const char* const* gsrc, int frow, int fc) {
    uint32_t scol = (uint32_t)((fc ^ (frow & 7)) << 4);
#pragma unroll
    for (int p = 0; p < 4; p++) {
        uint32_t base = sb + s * MM_STAGE + p * 16384 + frow * 128 + scol;
        const char* src = gsrc[p] + (size_t)frow * 2048 + fc * 16 + kb * 128;
#pragma unroll
        for (int i = 0; i < 4; i++)
            cp16(base + i * 32 * 128, src + (size_t)i * 32 * 2048);
    }
    asm volatile("cp.async.commit_group;\n");
}

template <bool DO_BIAS>
__device__ __forceinline__ void mm_body(
    const __nv_bfloat16* __restrict__ Ah, const __nv_bfloat16* __restrict__ Al,
    const __nv_bfloat16* __restrict__ Bh, const __nv_bfloat16* __restrict__ Bl,
    float* __restrict__ C, const float* __restrict__ bias) {
    extern __shared__ char smem[];
    int tid = threadIdx.x, lane = tid & 31, wid = tid >> 5;
    int wm = wid >> 2, wn = wid & 3;     // 2x4 warp grid
    int m0 = blockIdx.y * 128, n0 = blockIdx.x * 128;
    uint32_t sb = smem_u32(smem);
    int frow = tid >> 3, fc = tid & 7;
    int la7 = lane & 7;

    const char* gsrc[4];
    gsrc[0] = (const char*)(Ah + (size_t)m0 * DIMM);
    gsrc[1] = (const char*)(Al + (size_t)m0 * DIMM);
    gsrc[2] = (const char*)(Bh + (size_t)n0 * DIMM);
    gsrc[3] = (const char*)(Bl + (size_t)n0 * DIMM);

    float acc[4][4][4];
#pragma unroll
    for (int i = 0; i < 4; i++)
#pragma unroll
        for (int j = 0; j < 4; j++)
#pragma unroll
            for (int q = 0; q < 4; q++) acc[i][j][q] = 0.f;

    mm_fill(sb, 0, 0, gsrc, frow, fc);

    for (int kb = 0; kb < 16; kb++) {
        int s = kb & 1;
        if (kb + 1 < 16) {
            mm_fill(sb, (kb + 1) & 1, kb + 1, gsrc, frow, fc);
            asm volatile("cp.async.wait_group 1;\n");
        } else {
            asm volatile("cp.async.wait_group 0;\n");
        }
        __syncthreads();

        uint32_t bAh = sb + s * MM_STAGE;
        uint32_t bAl = bAh + 16384;
        uint32_t bBh = bAh + 32768;
        uint32_t bBl = bAh + 49152;
#pragma unroll
        for (int kc = 0; kc < 4; kc++) {
            uint32_t ah[4][4], al[4][4];
            int chA = kc * 2 + (lane >> 4);
            uint32_t sA = (uint32_t)((chA ^ la7) << 4);
#pragma unroll
            for (int mi = 0; mi < 4; mi++) {
                int row = wm * 64 + mi * 16 + la7 + ((lane >> 3) & 1) * 8;
                uint32_t off = (uint32_t)row * 128 + sA;
                ldsm_x4(ah[mi], bAh + off);
                ldsm_x4(al[mi], bAl + off);
            }
            uint32_t bh[4][2], bl[4][2];
            int chB = kc * 2 + ((lane >> 3) & 1);
            uint32_t sB = (uint32_t)((chB ^ la7) << 4);
#pragma unroll
            for (int nh = 0; nh < 2; nh++) {
                int row = wn * 32 + nh * 16 + la7 + (lane >> 4) * 8;
                uint32_t off = (uint32_t)row * 128 + sB;
                uint32_t r[4];
                ldsm_x4(r, bBh + off);
                bh[2 * nh][0] = r[0]; bh[2 * nh][1] = r[1];
                bh[2 * nh + 1][0] = r[2]; bh[2 * nh + 1][1] = r[3];
                ldsm_x4(r, bBl + off);
                bl[2 * nh][0] = r[0]; bl[2 * nh][1] = r[1];
                bl[2 * nh + 1][0] = r[2]; bl[2 * nh + 1][1] = r[3];
            }
#pragma unroll
            for (int mi = 0; mi < 4; mi++)
#pragma unroll
                for (int ni = 0; ni < 4; ni++) {
                    mma_bf16(acc[mi][ni], ah[mi], bh[ni]);
                    mma_bf16(acc[mi][ni], al[mi], bh[ni]);
                    mma_bf16(acc[mi][ni], ah[mi], bl[ni]);
                }
        }
        __syncthreads();
    }

    // epilogue
#pragma unroll
    for (int mi = 0; mi < 4; mi++) {
        int r0 = m0 + wm * 64 + mi * 16 + (lane >> 2);
#pragma unroll
        for (int ni = 0; ni < 4; ni++) {
            int c = n0 + wn * 32 + ni * 8 + (lane & 3) * 2;
            float2 v0 = make_float2(acc[mi][ni][0], acc[mi][ni][1]);
            float2 v1 = make_float2(acc[mi][ni][2], acc[mi][ni][3]);
            if (DO_BIAS) {
                float b0 = bias[c], b1 = bias[c + 1];
                v0.x += b0; v0.y += b1;
                v1.x += b0; v1.y += b1;
            }
            *(float2*)(C + (size_t)r0 * DIMM + c) = v0;
            *(float2*)(C + (size_t)(r0 + 8) * DIMM + c) = v1;
        }
    }
}

__global__ void __launch_bounds__(256, 1) mm_proj_kernel() {
    int which = blockIdx.z;
    float* C = (which == 0) ? d_fq : (which == 1) ? d_fk : d_fv;
    mm_body<false>(d_xh[which], d_xl[which], d_wih, d_wil, C, nullptr);
}

__global__ void __launch_bounds__(256, 1) mm_out_kernel(const float* __restrict__ bias,
                                                        float* __restrict__ out) {
    mm_body<true>(d_oh, d_ol, d_woh, d_wol, out, bias);
}

// ---------------- per-(head,row) stats ----------------
__global__ void headstats_kernel() {
    int r = blockIdx.x;
    int w = threadIdx.x >> 5, lane = threadIdx.x & 31;
    {
        float4 x = *(const float4*)(d_fq + (size_t)r * DIMM + w * DD + lane * 4);
        float s = x.x + x.y + x.z + x.w;
        float sq = x.x * x.x + x.y * x.y + x.z * x.z + x.w * x.w;
        s = warpsum(s); sq = warpsum(sq);
        if (lane == 0) {
            float mean = s * (1.f / DD);
            float var = (sq - s * s * (1.f / DD)) * (1.f / (DD - 1));
            d_iqn[w][r] = rsqrtf(sq);
            d_qmean[w][r] = mean;
            d_qr[w][r] = 2.f * fminf(var, 1.f) / (var + 1.f);
        }
    }
    {
        float4 x = *(const float4*)(d_fk + (size_t)r * DIMM + w * DD + lane * 4);
        float s = x.x + x.y + x.z + x.w;
        float sq = x.x * x.x + x.y * x.y + x.z * x.z + x.w * x.w;
        s = warpsum(s); sq = warpsum(sq);
        if (lane == 0) {
            float var = (sq - s * s * (1.f / DD)) * (1.f / (DD - 1));
            d_ikn[w][r] = rsqrtf(sq);
            d_kr[w][r] = 2.f * fminf(var, 1.f) / (var + 1.f);
        }
    }
}

// ---------------- Gram matrix partials ----------------
__global__ void __launch_bounds__(256) grampart_kernel() {
    int ch = blockIdx.x;
    int h = blockIdx.y;
    int r0 = ch * 512;
    __shared__ float s[8][128];
    int tid = threadIdx.x;
    int ty = tid >> 4, tx = tid & 15;
    int lrow = tid >> 5, lcol = (tid & 31) << 2;
    float acc[8][8] = {};
    for (int t = 0; t < 64; t++) {
        int rb = r0 + t * 8;
        float m = d_qmean[h][rb + lrow];
        float4 xv = *(const float4*)(d_fq + (size_t)(rb + lrow) * DIMM + h * DD + lcol);
        s[lrow][lcol + 0] = xv.x - m;
        s[lrow][lcol + 1] = xv.y - m;
        s[lrow][lcol + 2] = xv.z - m;
        s[lrow][lcol + 3] = xv.w - m;
        __syncthreads();
#pragma unroll
        for (int rr = 0; rr < 8; rr++) {
            float ra[8], rb_[8];
            *(float4*)(ra)      = *(const float4*)(&s[rr][ty * 8]);
            *(float4*)(ra + 4)  = *(const float4*)(&s[rr][ty * 8 + 4]);
            *(float4*)(rb_)     = *(const float4*)(&s[rr][tx * 8]);
            *(float4*)(rb_ + 4) = *(const float4*)(&s[rr][tx * 8 + 4]);
#pragma unroll
            for (int i = 0; i < 8; i++)
#pragma unroll
                for (int j = 0; j < 8; j++) acc[i][j] += ra[i] * rb_[j];
        }
        __syncthreads();
    }
    float* out = d_Cpart[h * GCH + ch];
#pragma unroll
    for (int i = 0; i < 8; i++) {
        float* row = out + (ty * 8 + i) * DD + tx * 8;
        *(float4*)(row)     = make_float4(acc[i][0], acc[i][1], acc[i][2], acc[i][3]);
        *(float4*)(row + 4) = make_float4(acc[i][4], acc[i][5], acc[i][6], acc[i][7]);
    }
}

// ---------------- reduce gram partials ----------------
__global__ void creduce_kernel() {
    int h = blockIdx.x;
    float ssum = 0.f;
    for (int i = threadIdx.x; i < DD * DD; i += 256) {
        float c = 0.f;
#pragma unroll
        for (int p = 0; p < GCH; p++) c += d_Cpart[h * GCH + p][i];
        if ((i / DD) != (i % DD)) ssum += c * c;
    }
    __shared__ float sh[8];
    ssum = warpsum(ssum);
    int w = threadIdx.x >> 5, lane = threadIdx.x & 31;
    if (lane == 0) sh[w] = ssum;
    __syncthreads();
    if (threadIdx.x == 0) {
        float S = 0.f;
#pragma unroll
        for (int i = 0; i < 8; i++) S += sh[i];
        float fro = sqrtf(S) * (1.f / RTOT);
        float score = fro * (1.f / (128.f * 128.f));
        d_dscale[h] = expf(-5.f * score);
    }
}

// ---------------- global column-sum partials ----------------
__global__ void gpart_kernel() {
    int b = blockIdx.x;
    int r0 = b * 128;
    int t = threadIdx.x;
    float sq[4] = {}, sk[4] = {};
    for (int row = 0; row < 128; row++) {
        const float* fq = d_fq + (size_t)(r0 + row) * DIMM;
        const float* fk = d_fk + (size_t)(r0 + row) * DIMM;
#pragma unroll
        for (int c = 0; c < 4; c++) {
            sq[c] += fq[t + c * 256];
            sk[c] += fk[t + c * 256];
        }
    }
#pragma unroll
    for (int c = 0; c < 4; c++) {
        d_gpart[b][t + c * 256] = sq[c];
        d_gpart[b][DIMM + t + c * 256] = sk[c];
    }
}

// ---------------- weight-predictor MLP ----------------
__global__ void wp_kernel(const float* __restrict__ w1, const float* __restrict__ b1,
                          const float* __restrict__ lng, const float* __restrict__ lnb,
                          const float* __restrict__ w2, const float* __restrict__ b2) {
    __shared__ float qg[DIMM], kg[DIMM];
    __shared__ float h1[HH][DD];
    __shared__ float logits[HH][3];
    int tid = threadIdx.x;
    for (int i = tid; i < DIMM; i += 256) {
        float s = 0.f, s2 = 0.f;
        for (int b = 0; b < 64; b++) { s += d_gpart[b][i]; s2 += d_gpart[b][DIMM + i]; }
        qg[i] = s * (1.f / RTOT);
        kg[i] = s2 * (1.f / RTOT);
    }
    __syncthreads();
    for (int idx = tid; idx < HH * DD; idx += 256) {
        int h = idx / DD, i = idx % DD;
        float s = b1[i];
        const float* wr = w1 + i * 256;
#pragma unroll 4
        for (int j = 0; j < 128; j++) s += qg[h * 128 + j] * wr[j];
#pragma unroll 4
        for (int j = 0; j < 128; j++) s += kg[h * 128 + j] * wr[128 + j];
        h1[h][i] = s;
    }
    __syncthreads();
    int w = tid >> 5, lane = tid & 31;
    if (w < 8) {
        float s = 0.f, sq = 0.f;
        for (int i = lane; i < DD; i += 32) { float v = h1[w][i]; s += v; sq += v * v; }
        s = warpsum(s); sq = warpsum(sq);
        float mean = s * (1.f / DD);
        float var = sq * (1.f / DD) - mean * mean;
        float rs = rsqrtf(var + 1e-5f);
        for (int i = lane; i < DD; i += 32) {
            float vv = (h1[w][i] - mean) * rs * lng[i] + lnb[i];
            h1[w][i] = fmaxf(vv, 0.f);
        }
    }
    __syncthreads();
    if (tid < 24) {
        int h = tid / 3, c = tid % 3;
        float s = b2[c];
        const float* wr = w2 + c * DD;
        for (int i = 0; i < DD; i++) s += h1[h][i] * wr[i];
        logits[h][c] = s;
    }
    __syncthreads();
    if (tid < 8) {
        float a = logits[tid][0], b = logits[tid][1], c = logits[tid][2];
        float m = fmaxf(a, fmaxf(b, c));
        float ea = expf(a - m), eb = expf(b - m), ec = expf(c - m);
        float inv = 1.f / (ea + eb + ec);
        d_s1[tid] = ea * inv + eb * inv * d_dscale[tid];
        d_wws[tid] = ec * inv;
    }
}

// ---------------- per-(h,qi): M = f_k^T diag(1/kn) f_v and g ----------------
__global__ void __launch_bounds__(256) kvm_kernel() {
    int blk = blockIdx.x;
    int h = blk >> 4, qi = blk & 15;
    int r0 = qi * NN;
    int co = h * DD;
    __shared__ float ks[8][128], vs[8][128];
    __shared__ float krs[8];
    int tid = threadIdx.x;
    int ty = tid >> 4, tx = tid & 15;
    int lrow = tid >> 5, lcol = (tid & 31) << 2;
    float acc[8][8] = {};
    float gacc = 0.f;
    for (int t = 0; t < 64; t++) {
        int rb = r0 + t * 8;
        float sc = d_ikn[h][rb + lrow];
        float4 kv = *(const float4*)(d_fk + (size_t)(rb + lrow) * DIMM + co + lcol);
        ks[lrow][lcol + 0] = kv.x * sc;
        ks[lrow][lcol + 1] = kv.y * sc;
        ks[lrow][lcol + 2] = kv.z * sc;
        ks[lrow][lcol + 3] = kv.w * sc;
        float4 vv = *(const float4*)(d_fv + (size_t)(rb + lrow) * DIMM + co + lcol);
        *(float4*)(&vs[lrow][lcol]) = vv;
        if (tid < 8) krs[tid] = d_kr[h][rb + tid];
        __syncthreads();
#pragma unroll
        for (int rr = 0; rr < 8; rr++) {
            float ra[8], rb_[8];
            *(float4*)(ra)      = *(const float4*)(&ks[rr][ty * 8]);
            *(float4*)(ra + 4)  = *(const float4*)(&ks[rr][ty * 8 + 4]);
            *(float4*)(rb_)     = *(const float4*)(&vs[rr][tx * 8]);
            *(float4*)(rb_ + 4) = *(const float4*)(&vs[rr][tx * 8 + 4]);
#pragma unroll
            for (int i = 0; i < 8; i++)
#pragma unroll
                for (int j = 0; j < 8; j++) acc[i][j] += ra[i] * rb_[j];
        }
        if (tid < 128) {
#pragma unroll
            for (int rr = 0; rr < 8; rr++) gacc += krs[rr] * vs[rr][tid];
        }
        __syncthreads();
    }
    float* Mout = d_M[blk];
#pragma unroll
    for (int i = 0; i < 8; i++) {
        float* row = Mout + (ty * 8 + i) * DD + tx * 8;
        *(float4*)(row)     = make_float4(acc[i][0], acc[i][1], acc[i][2], acc[i][3]);
        *(float4*)(row + 4) = make_float4(acc[i][4], acc[i][5], acc[i][6], acc[i][7]);
    }
    if (tid < 128) d_gv[blk][tid] = gacc;
}

// ---------------- attention out: writes bf16 hi/lo directly ----------------
__global__ void __launch_bounds__(256) attout_kernel() {
    int blk = blockIdx.y;
    int mt = blockIdx.x;
    int h = blk >> 4, qi = blk & 15;
    int r0 = qi * NN + mt * 128;
    int co = h * DD;
    __shared__ float As[8][128];
    __shared__ float Bs[8][128];
    int tid = threadIdx.x;
    int ty = tid >> 4, tx = tid & 15;
    int lrow = tid >> 1, lk4 = (tid & 1) << 2;
    float acc[8][8] = {};
    const float* Mp = d_M[blk];
    const float* Aq = d_fq + (size_t)(r0 + lrow) * DIMM + co;
    for (int k0 = 0; k0 < DD; k0 += 8) {
        float4 a = *(const float4*)(Aq + k0 + lk4);
        As[lk4 + 0][lrow] = a.x;
        As[lk4 + 1][lrow] = a.y;
        As[lk4 + 2][lrow] = a.z;
        As[lk4 + 3][lrow] = a.w;
        float4 b = *(const float4*)(Mp + (k0 + (tid >> 5)) * DD + ((tid & 31) << 2));
        *(float4*)(&Bs[tid >> 5][(tid & 31) << 2]) = b;
        __syncthreads();
#pragma unroll
        for (int kk = 0; kk < 8; kk++) {
            float ar[8], br[8];
            *(float4*)(ar)     = *(const float4*)(&As[kk][ty * 8]);
            *(float4*)(ar + 4) = *(const float4*)(&As[kk][ty * 8 + 4]);
            *(float4*)(br)     = *(const float4*)(&Bs[kk][tx * 8]);
            *(float4*)(br + 4) = *(const float4*)(&Bs[kk][tx * 8 + 4]);
#pragma unroll
            for (int i = 0; i < 8; i++)
#pragma unroll
                for (int j = 0; j < 8; j++) acc[i][j] += ar[i] * br[j];
        }
        __syncthreads();
    }
    float s1 = d_s1[h], ww = d_wws[h];
    float gvr[8];
#pragma unroll
    for (int j = 0; j < 8; j++) gvr[j] = d_gv[blk][tx * 8 + j];
#pragma unroll
    for (int i = 0; i < 8; i++) {
        int r = r0 + ty * 8 + i;
        float f1 = s1 * d_iqn[h][r];
        float f2 = ww * d_qr[h][r];
        float o[8];
#pragma unroll
        for (int j = 0; j < 8; j++) o[j] = f1 * acc[i][j] + f2 * gvr[j];
        size_t base = (size_t)r * DIMM + co + tx * 8;
        uint2 h0, l0, h1v, l1v;
        split4(o[0], o[1], o[2], o[3], h0, l0);
        split4(o[4], o[5], o[6], o[7], h1v, l1v);
        uint4 hv = make_uint4(h0.x, h0.y, h1v.x, h1v.y);
        uint4 lv = make_uint4(l0.x, l0.y, l1v.x, l1v.y);
        *(uint4*)(d_oh + base) = hv;
        *(uint4*)(d_ol + base) = lv;
    }
}

// ---------------- launch ----------------
extern "C" void kernel_launch(void* const* d_in, const int* in_sizes, int n_in,
                              void* d_out, int out_size) {
    const float* q      = (const float*)d_in[0];
    const float* k      = (const float*)d_in[1];
    const float* v      = (const float*)d_in[2];
    const float* ln_g   = (const float*)d_in[3];
    const float* ln_b   = (const float*)d_in[4];
    const float* w_in   = (const float*)d_in[5];
    const float* wp_w1  = (const float*)d_in[6];
    const float* wp_b1  = (const float*)d_in[7];
    const float* wp_lng = (const float*)d_in[8];
    const float* wp_lnb = (const float*)d_in[9];
    const float* wp_w2  = (const float*)d_in[10];
    const float* wp_b2  = (const float*)d_in[11];
    const float* w_out  = (const float*)d_in[12];
    const float* b_out  = (const float*)d_in[13];
    float* out = (float*)d_out;

    cudaFuncSetAttribute(mm_proj_kernel, cudaFuncAttributeMaxDynamicSharedMemorySize, MM_SMEM);
    cudaFuncSetAttribute(mm_out_kernel, cudaFuncAttributeMaxDynamicSharedMemorySize, MM_SMEM);

    lnconv_kernel<<<3 * RTOT, 256>>>(q, k, v, ln_g, ln_b);
    wconv_kernel<<<2 * DIMM, 256>>>(w_in, w_out);

    dim3 gproj(DIMM / 128, RTOT / 128, 3);   // (8, 64, 3)
    mm_proj_kernel<<<gproj, 256, MM_SMEM>>>();

    headstats_kernel<<<RTOT, 256>>>();

    dim3 ggram(GCH, HH);
    grampart_kernel<<<ggram, 256>>>();
    creduce_kernel<<<HH, 256>>>();

    gpart_kernel<<<64, 256>>>();
    wp_kernel<<<1, 256>>>(wp_w1, wp_b1, wp_lng, wp_lnb, wp_w2, wp_b2);

    kvm_kernel<<<HH * QBB, 256>>>();

    dim3 gatt(4, HH * QBB);
    attout_kernel<<<gatt, 256>>>();

    dim3 gout(DIMM / 128, RTOT / 128);       // (8, 64)
    mm_out_kernel<<<gout, 256, MM_SMEM>>>(b_out, out);
}

// round 8
// speedup vs baseline: 2.5494x; 1.0798x over previous
#include <cuda_runtime.h>
#include <cuda_bf16.h>
#include <math.h>
#include <stdint.h>

// Problem constants
#define RTOT 8192     // QB*N tokens
#define DIMM 1024
#define HH 8
#define DD 128
#define NN 512
#define QBB 16
#define GCH 16        // gram split-K chunks (512 rows each)

// ---------------- static device scratch (no runtime allocation) ----------------
__device__ __nv_bfloat16 d_xh[3][RTOT * DIMM];   // LN(x) hi bf16 (q,k,v)
__device__ __nv_bfloat16 d_xl[3][RTOT * DIMM];   // LN(x) lo residual
__device__ __nv_bfloat16 d_oh[RTOT * DIMM];      // att output hi
__device__ __nv_bfloat16 d_ol[RTOT * DIMM];      // att output lo
__device__ __nv_bfloat16 d_wih[DIMM * DIMM], d_wil[DIMM * DIMM];  // w_in split
__device__ __nv_bfloat16 d_woh[DIMM * DIMM], d_wol[DIMM * DIMM];  // w_out split
__device__ __nv_bfloat16 d_fqh[RTOT * DIMM], d_fql[RTOT * DIMM];  // f_q split
__device__ __nv_bfloat16 d_fkh[RTOT * DIMM], d_fkl[RTOT * DIMM];  // f_k split
__device__ __nv_bfloat16 d_qch[RTOT * DIMM], d_qcl[RTOT * DIMM];  // q centered split
__device__ __nv_bfloat16 d_vth[RTOT * DIMM], d_vtl[RTOT * DIMM];  // ikn-scaled v split
__device__ __nv_bfloat16 d_Mh[HH * QBB * DD * DD], d_Ml[HH * QBB * DD * DD];
__device__ float d_fq[RTOT * DIMM];
__device__ float d_fk[RTOT * DIMM];
__device__ float d_fv[RTOT * DIMM];
__device__ float d_iqn[HH][RTOT];
__device__ float d_ikn[HH][RTOT];
__device__ float d_qr[HH][RTOT];
__device__ float d_kr[HH][RTOT];
__device__ float d_qmean[HH][RTOT];
__device__ float d_Cpart[HH * GCH][DD * DD];
__device__ float d_dscale[HH];
__device__ float d_gpart[64][2 * DIMM];
__device__ float d_s1[HH];
__device__ float d_wws[HH];
__device__ float d_gv[HH * QBB][DD];

__device__ __forceinline__ float warpsum(float v) {
#pragma unroll
    for (int o = 16; o; o >>= 1) v += __shfl_xor_sync(0xffffffffu, v, o);
    return v;
}

__device__ __forceinline__ uint32_t smem_u32(const void* p) {
    uint32_t a;
    asm("{ .reg .u64 t; cvta.to.shared.u64 t, %1; cvt.u32.u64 %0, t; }" : "=r"(a) : "l"(p));
    return a;
}

// split fp32 -> bf16 hi (truncate) + bf16 lo (rn residual)
__device__ __forceinline__ void split4(float x0, float x1, float x2, float x3,
                                       uint2& h, uint2& l) {
    uint32_t u0 = __float_as_uint(x0), u1 = __float_as_uint(x1);
    uint32_t u2 = __float_as_uint(x2), u3 = __float_as_uint(x3);
    h.x = (u0 >> 16) | (u1 & 0xFFFF0000u);
    h.y = (u2 >> 16) | (u3 & 0xFFFF0000u);
    float l0 = x0 - __uint_as_float(u0 & 0xFFFF0000u);
    float l1 = x1 - __uint_as_float(u1 & 0xFFFF0000u);
    float l2 = x2 - __uint_as_float(u2 & 0xFFFF0000u);
    float l3 = x3 - __uint_as_float(u3 & 0xFFFF0000u);
    asm("cvt.rn.bf16x2.f32 %0, %1, %2;" : "=r"(l.x) : "f"(l1), "f"(l0));
    asm("cvt.rn.bf16x2.f32 %0, %1, %2;" : "=r"(l.y) : "f"(l3), "f"(l2));
}
__device__ __forceinline__ void split2(float x0, float x1, uint32_t& h, uint32_t& l) {
    uint32_t u0 = __float_as_uint(x0), u1 = __float_as_uint(x1);
    h = (u0 >> 16) | (u1 & 0xFFFF0000u);
    float l0 = x0 - __uint_as_float(u0 & 0xFFFF0000u);
    float l1 = x1 - __uint_as_float(u1 & 0xFFFF0000u);
    asm("cvt.rn.bf16x2.f32 %0, %1, %2;" : "=r"(l) : "f"(l1), "f"(l0));
}

__device__ __forceinline__ void cp16(uint32_t dst, const void* src) {
    asm volatile("cp.async.cg.shared.global [%0], [%1], 16;\n" :: "r"(dst), "l"(src));
}
__device__ __forceinline__ void ldsm_x4(uint32_t* r, uint32_t a) {
    asm volatile("ldmatrix.sync.aligned.m8n8.x4.shared.b16 {%0,%1,%2,%3}, [%4];\n"
                 : "=r"(r[0]), "=r"(r[1]), "=r"(r[2]), "=r"(r[3]) : "r"(a));
}
__device__ __forceinline__ void ldsm_x4_t(uint32_t* r, uint32_t a) {
    asm volatile("ldmatrix.sync.aligned.m8n8.x4.trans.shared.b16 {%0,%1,%2,%3}, [%4];\n"
                 : "=r"(r[0]), "=r"(r[1]), "=r"(r[2]), "=r"(r[3]) : "r"(a));
}
__device__ __forceinline__ void mma_bf16(float* d, const uint32_t* a, const uint32_t* b) {
    asm volatile(
        "mma.sync.aligned.m16n8k16.row.col.f32.bf16.bf16.f32 "
        "{%0,%1,%2,%3}, {%4,%5,%6,%7}, {%8,%9}, {%0,%1,%2,%3};\n"
        : "+f"(d[0]), "+f"(d[1]), "+f"(d[2]), "+f"(d[3])
        : "r"(a[0]), "r"(a[1]), "r"(a[2]), "r"(a[3]), "r"(b[0]), "r"(b[1]));
}

// ---------------- fused rowstats + LayerNorm + bf16 split ----------------
__global__ void lnconv_kernel(const float* __restrict__ q, const float* __restrict__ k,
                              const float* __restrict__ v,
                              const float* __restrict__ lng, const float* __restrict__ lnb) {
    int idx = blockIdx.x;
    int t = idx >> 13;
    int r = idx & (RTOT - 1);
    const float* A = (t == 0) ? q : (t == 1) ? k : v;
    int tid = threadIdx.x;
    float4 x = ((const float4*)(A + (size_t)r * DIMM))[tid];
    float s = x.x + x.y + x.z + x.w;
    float sq = x.x * x.x + x.y * x.y + x.z * x.z + x.w * x.w;
    __shared__ float sh[16];
    __shared__ float smu, srs;
    s = warpsum(s); sq = warpsum(sq);
    int w = tid >> 5, lane = tid & 31;
    if (lane == 0) { sh[w] = s; sh[8 + w] = sq; }
    __syncthreads();
    if (tid == 0) {
        float S = 0.f, SQ = 0.f;
#pragma unroll
        for (int i = 0; i < 8; i++) { S += sh[i]; SQ += sh[8 + i]; }
        float mu = S * (1.f / DIMM);
        float var = SQ * (1.f / DIMM) - mu * mu;
        smu = mu;
        srs = rsqrtf(var + 1e-5f);
    }
    __syncthreads();
    float mu = smu, rs = srs;
    float4 g = ((const float4*)lng)[tid];
    float4 b = ((const float4*)lnb)[tid];
    float y0 = (x.x - mu) * rs * g.x + b.x;
    float y1 = (x.y - mu) * rs * g.y + b.y;
    float y2 = (x.z - mu) * rs * g.z + b.z;
    float y3 = (x.w - mu) * rs * g.w + b.w;
    uint2 hv, lv;
    split4(y0, y1, y2, y3, hv, lv);
    ((uint2*)(d_xh[t] + (size_t)r * DIMM))[tid] = hv;
    ((uint2*)(d_xl[t] + (size_t)r * DIMM))[tid] = lv;
}

// ---------------- weight convert ----------------
__global__ void wconv_kernel(const float* __restrict__ w_in, const float* __restrict__ w_out) {
    int row = blockIdx.x;
    int tid = threadIdx.x;
    const float* src;
    __nv_bfloat16 *H, *L;
    if (row < DIMM) {
        src = w_in + (size_t)row * DIMM;
        H = d_wih + (size_t)row * DIMM;
        L = d_wil + (size_t)row * DIMM;
    } else {
        src = w_out + (size_t)(row - DIMM) * DIMM;
        H = d_woh + (size_t)(row - DIMM) * DIMM;
        L = d_wol + (size_t)(row - DIMM) * DIMM;
    }
    float4 x = ((const float4*)src)[tid];
    uint2 hv, lv;
    split4(x.x, x.y, x.z, x.w, hv, lv);
    ((uint2*)H)[tid] = hv;
    ((uint2*)L)[tid] = lv;
}

// =====================================================================
//  big GEMM: C[8192x1024] = A @ B^T, bf16x3, 3-stage cp.async pipeline
// =====================================================================
static constexpr int MM_STAGE = 65536;
static constexpr int MM_SMEM = 3 * MM_STAGE;    // 192 KB

__device__ __forceinline__ void mm_fill(uint32_t sb, int s, int kb,
                                        const char* const* gsrc, int frow, int fc) {
    uint32_t scol = (uint32_t)((fc ^ (frow & 7)) << 4);
#pragma unroll
    for (int p = 0; p < 4; p++) {
        uint32_t base = sb + s * MM_STAGE + p * 16384 + frow * 128 + scol;
        const char* src = gsrc[p] + (size_t)frow * 2048 + fc * 16 + kb * 128;
#pragma unroll
        for (int i = 0; i < 4; i++)
            cp16(base + i * 32 * 128, src + (size_t)i * 32 * 2048);
    }
    asm volatile("cp.async.commit_group;\n");
}

template <bool DO_BIAS, bool WSPLIT>
__device__ __forceinline__ void mm_body(
    const __nv_bfloat16* __restrict__ Ah, const __nv_bfloat16* __restrict__ Al,
    const __nv_bfloat16* __restrict__ Bh, const __nv_bfloat16* __restrict__ Bl,
    float* __restrict__ C, const float* __restrict__ bias,
    __nv_bfloat16* __restrict__ SH, __nv_bfloat16* __restrict__ SL) {
    extern __shared__ char smem[];
    int tid = threadIdx.x, lane = tid & 31, wid = tid >> 5;
    int wm = wid >> 2, wn = wid & 3;
    int m0 = blockIdx.y * 128, n0 = blockIdx.x * 128;
    uint32_t sb = smem_u32(smem);
    int frow = tid >> 3, fc = tid & 7;
    int la7 = lane & 7;

    const char* gsrc[4];
    gsrc[0] = (const char*)(Ah + (size_t)m0 * DIMM);
    gsrc[1] = (const char*)(Al + (size_t)m0 * DIMM);
    gsrc[2] = (const char*)(Bh + (size_t)n0 * DIMM);
    gsrc[3] = (const char*)(Bl + (size_t)n0 * DIMM);

    float acc[4][4][4];
#pragma unroll
    for (int i = 0; i < 4; i++)
#pragma unroll
        for (int j = 0; j < 4; j++)
#pragma unroll
            for (int q = 0; q < 4; q++) acc[i][j][q] = 0.f;

    mm_fill(sb, 0, 0, gsrc, frow, fc);
    mm_fill(sb, 1, 1, gsrc, frow, fc);

    for (int kb = 0; kb < 16; kb++) {
        if (kb < 15) asm volatile("cp.async.wait_group 1;\n");
        else         asm volatile("cp.async.wait_group 0;\n");
        __syncthreads();
        if (kb + 2 < 16) mm_fill(sb, (kb + 2) % 3, kb + 2, gsrc, frow, fc);

        int s = kb % 3;
        uint32_t bAh = sb + s * MM_STAGE;
        uint32_t bAl = bAh + 16384;
        uint32_t bBh = bAh + 32768;
        uint32_t bBl = bAh + 49152;
#pragma unroll
        for (int kc = 0; kc < 4; kc++) {
            uint32_t ah[4][4], al[4][4];
            int chA = kc * 2 + (lane >> 4);
            uint32_t sA = (uint32_t)((chA ^ la7) << 4);
#pragma unroll
            for (int mi = 0; mi < 4; mi++) {
                int row = wm * 64 + mi * 16 + la7 + ((lane >> 3) & 1) * 8;
                uint32_t off = (uint32_t)row * 128 + sA;
                ldsm_x4(ah[mi], bAh + off);
                ldsm_x4(al[mi], bAl + off);
            }
            uint32_t bh[4][2], bl[4][2];
            int chB = kc * 2 + ((lane >> 3) & 1);
            uint32_t sB = (uint32_t)((chB ^ la7) << 4);
#pragma unroll
            for (int nh = 0; nh < 2; nh++) {
                int row = wn * 32 + nh * 16 + la7 + (lane >> 4) * 8;
                uint32_t off = (uint32_t)row * 128 + sB;
                uint32_t r[4];
                ldsm_x4(r, bBh + off);
                bh[2 * nh][0] = r[0]; bh[2 * nh][1] = r[1];
                bh[2 * nh + 1][0] = r[2]; bh[2 * nh + 1][1] = r[3];
                ldsm_x4(r, bBl + off);
                bl[2 * nh][0] = r[0]; bl[2 * nh][1] = r[1];
                bl[2 * nh + 1][0] = r[2]; bl[2 * nh + 1][1] = r[3];
            }
#pragma unroll
            for (int mi = 0; mi < 4; mi++)
#pragma unroll
                for (int ni = 0; ni < 4; ni++) {
                    mma_bf16(acc[mi][ni], ah[mi], bh[ni]);
                    mma_bf16(acc[mi][ni], al[mi], bh[ni]);
                    mma_bf16(acc[mi][ni], ah[mi], bl[ni]);
                }
        }
        __syncthreads();
    }

#pragma unroll
    for (int mi = 0; mi < 4; mi++) {
        int r0 = m0 + wm * 64 + mi * 16 + (lane >> 2);
#pragma unroll
        for (int ni = 0; ni < 4; ni++) {
            int c = n0 + wn * 32 + ni * 8 + (lane & 3) * 2;
            float2 v0 = make_float2(acc[mi][ni][0], acc[mi][ni][1]);
            float2 v1 = make_float2(acc[mi][ni][2], acc[mi][ni][3]);
            if (DO_BIAS) {
                float b0 = bias[c], b1 = bias[c + 1];
                v0.x += b0; v0.y += b1;
                v1.x += b0; v1.y += b1;
            }
            *(float2*)(C + (size_t)r0 * DIMM + c) = v0;
            *(float2*)(C + (size_t)(r0 + 8) * DIMM + c) = v1;
            if (WSPLIT) {
                uint32_t hh, ll;
                split2(v0.x, v0.y, hh, ll);
                *(uint32_t*)(SH + (size_t)r0 * DIMM + c) = hh;
                *(uint32_t*)(SL + (size_t)r0 * DIMM + c) = ll;
                split2(v1.x, v1.y, hh, ll);
                *(uint32_t*)(SH + (size_t)(r0 + 8) * DIMM + c) = hh;
                *(uint32_t*)(SL + (size_t)(r0 + 8) * DIMM + c) = ll;
            }
        }
    }
}

__global__ void __launch_bounds__(256, 1) mm_proj_kernel() {
    int which = blockIdx.z;
    if (which == 0)
        mm_body<false, true>(d_xh[0], d_xl[0], d_wih, d_wil, d_fq, nullptr, d_fqh, d_fql);
    else if (which == 1)
        mm_body<false, true>(d_xh[1], d_xl[1], d_wih, d_wil, d_fk, nullptr, d_fkh, d_fkl);
    else
        mm_body<false, false>(d_xh[2], d_xl[2], d_wih, d_wil, d_fv, nullptr, nullptr, nullptr);
}

__global__ void __launch_bounds__(256, 1) mm_out_kernel(const float* __restrict__ bias,
                                                        float* __restrict__ out) {
    mm_body<true, false>(d_oh, d_ol, d_woh, d_wol, out, bias, nullptr, nullptr);
}

// =====================================================================
//  A^T B tensor-core kernel: C[128x128] = sum_{n<512} A[n][d] * B[n][e]
//  A,B bf16 hi/lo, row stride = DIMM elements. 272B-padded smem rows.
// =====================================================================
static constexpr int ATB_MAT = 64 * 272;       // 17408
static constexpr int ATB_STG = 4 * ATB_MAT;    // 69632
static constexpr int ATB_SMEM = 2 * ATB_STG;   // 139264

__device__ __forceinline__ void atb_fill(uint32_t sb, int s, int c,
        const __nv_bfloat16* Ah, const __nv_bfloat16* Al,
        const __nv_bfloat16* Bh, const __nv_bfloat16* Bl) {
    int tid = threadIdx.x;
    const __nv_bfloat16* srcs[4] = {Ah, Al, Bh, Bl};
#pragma unroll
    for (int p = 0; p < 4; p++) {
        uint32_t base = sb + s * ATB_STG + p * ATB_MAT;
        const __nv_bfloat16* src = srcs[p];
#pragma unroll
        for (int i = 0; i < 4; i++) {
            int id = tid + i * 256;
            int row = id >> 4, c16 = id & 15;
            cp16(base + row * 272 + c16 * 16,
                 src + (size_t)(c * 64 + row) * DIMM + c16 * 8);
        }
    }
    asm volatile("cp.async.commit_group;\n");
}

__device__ __forceinline__ void atb_compute(uint32_t sb, int s, float acc[4][4][4],
                                            int wm, int wn, int lane) {
    uint32_t bA  = sb + s * ATB_STG;
    uint32_t bAl = bA + ATB_MAT;
    uint32_t bB  = bA + 2 * ATB_MAT;
    uint32_t bBl = bA + 3 * ATB_MAT;
    int la7 = lane & 7;
    int arow = ((lane >> 4) << 3) + la7;             // A: k-subrow
    int acol = (((lane >> 3) & 1) << 3);             // A: m offset
    int brow = (((lane >> 3) & 1) << 3) + la7;       // B: k-subrow
    int bcol = ((lane >> 4) << 3);                   // B: n offset
#pragma unroll
    for (int kc = 0; kc < 4; kc++) {
        uint32_t ah[4][4], al[4][4];
#pragma unroll
        for (int mi = 0; mi < 4; mi++) {
            uint32_t off = (uint32_t)(kc * 16 + arow) * 272 +
                           (uint32_t)(wm * 64 + mi * 16 + acol) * 2;
            ldsm_x4_t(ah[mi], bA + off);
            ldsm_x4_t(al[mi], bAl + off);
        }
        uint32_t bh[4][2], bl[4][2];
#pragma unroll
        for (int nh = 0; nh < 2; nh++) {
            uint32_t off = (uint32_t)(kc * 16 + brow) * 272 +
                           (uint32_t)(wn * 32 + nh * 16 + bcol) * 2;
            uint32_t r[4];
            ldsm_x4_t(r, bB + off);
            bh[2 * nh][0] = r[0]; bh[2 * nh][1] = r[1];
            bh[2 * nh + 1][0] = r[2]; bh[2 * nh + 1][1] = r[3];
            ldsm_x4_t(r, bBl + off);
            bl[2 * nh][0] = r[0]; bl[2 * nh][1] = r[1];
            bl[2 * nh + 1][0] = r[2]; bl[2 * nh + 1][1] = r[3];
        }
#pragma unroll
        for (int mi = 0; mi < 4; mi++)
#pragma unroll
            for (int ni = 0; ni < 4; ni++) {
                mma_bf16(acc[mi][ni], ah[mi], bh[ni]);
                mma_bf16(acc[mi][ni], al[mi], bh[ni]);
                mma_bf16(acc[mi][ni], ah[mi], bl[ni]);
            }
    }
}

template <bool SPLIT_OUT>
__device__ __forceinline__ void atb_body(
        const __nv_bfloat16* Ah, const __nv_bfloat16* Al,
        const __nv_bfloat16* Bh, const __nv_bfloat16* Bl,
        float* Cf, __nv_bfloat16* Oh, __nv_bfloat16* Ol) {
    extern __shared__ char smem[];
    uint32_t sb = smem_u32(smem);
    int tid = threadIdx.x, lane = tid & 31, wid = tid >> 5;
    int wm = wid >> 2, wn = wid & 3;
    float acc[4][4][4];
#pragma unroll
    for (int i = 0; i < 4; i++)
#pragma unroll
        for (int j = 0; j < 4; j++)
#pragma unroll
            for (int q = 0; q < 4; q++) acc[i][j][q] = 0.f;

    atb_fill(sb, 0, 0, Ah, Al, Bh, Bl);
    for (int c = 0; c < 8; c++) {
        int s = c & 1;
        if (c + 1 < 8) {
            atb_fill(sb, (c + 1) & 1, c + 1, Ah, Al, Bh, Bl);
            asm volatile("cp.async.wait_group 1;\n");
        } else {
            asm volatile("cp.async.wait_group 0;\n");
        }
        __syncthreads();
        atb_compute(sb, s, acc, wm, wn, lane);
        __syncthreads();
    }
#pragma unroll
    for (int mi = 0; mi < 4; mi++) {
        int d0 = wm * 64 + mi * 16 + (lane >> 2);
#pragma unroll
        for (int ni = 0; ni < 4; ni++) {
            int e = wn * 32 + ni * 8 + (lane & 3) * 2;
            if (SPLIT_OUT) {
                uint32_t hh, ll;
                split2(acc[mi][ni][0], acc[mi][ni][1], hh, ll);
                *(uint32_t*)(Oh + d0 * DD + e) = hh;
                *(uint32_t*)(Ol + d0 * DD + e) = ll;
                split2(acc[mi][ni][2], acc[mi][ni][3], hh, ll);
                *(uint32_t*)(Oh + (d0 + 8) * DD + e) = hh;
                *(uint32_t*)(Ol + (d0 + 8) * DD + e) = ll;
            } else {
                *(float2*)(Cf + d0 * DD + e) = make_float2(acc[mi][ni][0], acc[mi][ni][1]);
                *(float2*)(Cf + (d0 + 8) * DD + e) = make_float2(acc[mi][ni][2], acc[mi][ni][3]);
            }
        }
    }
}

__global__ void __launch_bounds__(256, 1) gram_tc_kernel() {
    int ch = blockIdx.x, h = blockIdx.y;
    const __nv_bfloat16* Ah = d_qch + (size_t)(ch * 512) * DIMM + h * DD;
    const __nv_bfloat16* Al = d_qcl + (size_t)(ch * 512) * DIMM + h * DD;
    atb_body<false>(Ah, Al, Ah, Al, d_Cpart[h * GCH + ch], nullptr, nullptr);
}

__global__ void __launch_bounds__(256, 1) kvm_tc_kernel() {
    int blk = blockIdx.x;
    int h = blk >> 4, qi = blk & 15;
    size_t off = (size_t)(qi * NN) * DIMM + h * DD;
    atb_body<true>(d_fkh + off, d_fkl + off, d_vth + off, d_vtl + off,
                   nullptr, d_Mh + (size_t)blk * DD * DD, d_Ml + (size_t)blk * DD * DD);
}

// =====================================================================
//  attout: att[128x128] = f_q(128x128) @ M(128x128), + rank-1 term
// =====================================================================
static constexpr int AO_MAT = 128 * 272;       // 34816
static constexpr int AO_SMEM = 4 * AO_MAT;     // 139264

__global__ void __launch_bounds__(256, 1) attout_tc_kernel() {
    int blk = blockIdx.y, mt = blockIdx.x;
    int h = blk >> 4, qi = blk & 15;
    int r0g = qi * NN + mt * 128;
    int co = h * DD;
    extern __shared__ char smem[];
    uint32_t sb = smem_u32(smem);
    int tid = threadIdx.x, lane = tid & 31, wid = tid >> 5;
    int wm = wid >> 2, wn = wid & 3;
    int la7 = lane & 7;

    // fill: A (f_q split, stride DIMM), B (M split, stride 128)
    {
        const __nv_bfloat16* Asrc[2] = {d_fqh, d_fql};
#pragma unroll
        for (int p = 0; p < 2; p++) {
            uint32_t base = sb + p * AO_MAT;
            const __nv_bfloat16* src = Asrc[p] + (size_t)r0g * DIMM + co;
#pragma unroll
            for (int i = 0; i < 8; i++) {
                int id = tid + i * 256;
                int row = id >> 4, c16 = id & 15;
                cp16(base + row * 272 + c16 * 16, src + (size_t)row * DIMM + c16 * 8);
            }
        }
        const __nv_bfloat16* Bsrc[2] = {d_Mh + (size_t)blk * DD * DD,
                                        d_Ml + (size_t)blk * DD * DD};
#pragma unroll
        for (int p = 0; p < 2; p++) {
            uint32_t base = sb + (2 + p) * AO_MAT;
            const __nv_bfloat16* src = Bsrc[p];
#pragma unroll
            for (int i = 0; i < 8; i++) {
                int id = tid + i * 256;
                int row = id >> 4, c16 = id & 15;
                cp16(base + row * 272 + c16 * 16, src + row * DD + c16 * 8);
            }
        }
        asm volatile("cp.async.commit_group;\ncp.async.wait_group 0;\n");
        __syncthreads();
    }

    float acc[4][4][4];
#pragma unroll
    for (int i = 0; i < 4; i++)
#pragma unroll
        for (int j = 0; j < 4; j++)
#pragma unroll
            for (int q = 0; q < 4; q++) acc[i][j][q] = 0.f;

    uint32_t bA  = sb;
    uint32_t bAl = sb + AO_MAT;
    uint32_t bB  = sb + 2 * AO_MAT;
    uint32_t bBl = sb + 3 * AO_MAT;
    int brow = (((lane >> 3) & 1) << 3) + la7;
    int bcol = ((lane >> 4) << 3);
#pragma unroll
    for (int kc = 0; kc < 8; kc++) {
        uint32_t ah[4][4], al[4][4];
#pragma unroll
        for (int mi = 0; mi < 4; mi++) {
            uint32_t off = (uint32_t)(wm * 64 + mi * 16 + (lane & 15)) * 272 +
                           (uint32_t)(kc * 16 + ((lane >> 4) << 3)) * 2;
            ldsm_x4(ah[mi], bA + off);
            ldsm_x4(al[mi], bAl + off);
        }
        uint32_t bh[4][2], bl[4][2];
#pragma unroll
        for (int nh = 0; nh < 2; nh++) {
            uint32_t off = (uint32_t)(kc * 16 + brow) * 272 +
                           (uint32_t)(wn * 32 + nh * 16 + bcol) * 2;
            uint32_t r[4];
            ldsm_x4_t(r, bB + off);
            bh[2 * nh][0] = r[0]; bh[2 * nh][1] = r[1];
            bh[2 * nh + 1][0] = r[2]; bh[2 * nh + 1][1] = r[3];
            ldsm_x4_t(r, bBl + off);
            bl[2 * nh][0] = r[0]; bl[2 * nh][1] = r[1];
            bl[2 * nh + 1][0] = r[2]; bl[2 * nh + 1][1] = r[3];
        }
#pragma unroll
        for (int mi = 0; mi < 4; mi++)
#pragma unroll
            for (int ni = 0; ni < 4; ni++) {
                mma_bf16(acc[mi][ni], ah[mi], bh[ni]);
                mma_bf16(acc[mi][ni], al[mi], bh[ni]);
                mma_bf16(acc[mi][ni], ah[mi], bl[ni]);
            }
    }

    float s1 = d_s1[h], ww = d_wws[h];
#pragma unroll
    for (int mi = 0; mi < 4; mi++) {
        int rA = r0g + wm * 64 + mi * 16 + (lane >> 2);
        int rB = rA + 8;
        float f1a = s1 * d_iqn[h][rA], f2a = ww * d_qr[h][rA];
        float f1b = s1 * d_iqn[h][rB], f2b = ww * d_qr[h][rB];
#pragma unroll
        for (int ni = 0; ni < 4; ni++) {
            int c = wn * 32 + ni * 8 + (lane & 3) * 2;
            float g0 = d_gv[blk][c], g1 = d_gv[blk][c + 1];
            float o0 = f1a * acc[mi][ni][0] + f2a * g0;
            float o1 = f1a * acc[mi][ni][1] + f2a * g1;
            float o2 = f1b * acc[mi][ni][2] + f2b * g0;
            float o3 = f1b * acc[mi][ni][3] + f2b * g1;
            uint32_t hh, ll;
            split2(o0, o1, hh, ll);
            *(uint32_t*)(d_oh + (size_t)rA * DIMM + co + c) = hh;
            *(uint32_t*)(d_ol + (size_t)rA * DIMM + co + c) = ll;
            split2(o2, o3, hh, ll);
            *(uint32_t*)(d_oh + (size_t)rB * DIMM + co + c) = hh;
            *(uint32_t*)(d_ol + (size_t)rB * DIMM + co + c) = ll;
        }
    }
}

// ---------------- per-(head,row) stats ----------------
__global__ void headstats_kernel() {
    int r = blockIdx.x;
    int w = threadIdx.x >> 5, lane = threadIdx.x & 31;
    {
        float4 x = *(const float4*)(d_fq + (size_t)r * DIMM + w * DD + lane * 4);
        float s = x.x + x.y + x.z + x.w;
        float sq = x.x * x.x + x.y * x.y + x.z * x.z + x.w * x.w;
        s = warpsum(s); sq = warpsum(sq);
        if (lane == 0) {
            float mean = s * (1.f / DD);
            float var = (sq - s * s * (1.f / DD)) * (1.f / (DD - 1));
            d_iqn[w][r] = rsqrtf(sq);
            d_qmean[w][r] = mean;
            d_qr[w][r] = 2.f * fminf(var, 1.f) / (var + 1.f);
        }
    }
    {
        float4 x = *(const float4*)(d_fk + (size_t)r * DIMM + w * DD + lane * 4);
        float s = x.x + x.y + x.z + x.w;
        float sq = x.x * x.x + x.y * x.y + x.z * x.z + x.w * x.w;
        s = warpsum(s); sq = warpsum(sq);
        if (lane == 0) {
            float var = (sq - s * s * (1.f / DD)) * (1.f / (DD - 1));
            d_ikn[w][r] = rsqrtf(sq);
            d_kr[w][r] = 2.f * fminf(var, 1.f) / (var + 1.f);
        }
    }
}

// ---------------- prep: q-centered split + ikn-scaled v split ----------------
__global__ void prep_kernel() {
    int r = blockIdx.x;
    int tid = threadIdx.x;
    int h = tid >> 5;
    float qm = d_qmean[h][r];
    float ik = d_ikn[h][r];
    float4 x = ((const float4*)(d_fq + (size_t)r * DIMM))[tid];
    uint2 hv, lv;
    split4(x.x - qm, x.y - qm, x.z - qm, x.w - qm, hv, lv);
    ((uint2*)(d_qch + (size_t)r * DIMM))[tid] = hv;
    ((uint2*)(d_qcl + (size_t)r * DIMM))[tid] = lv;
    float4 vv = ((const float4*)(d_fv + (size_t)r * DIMM))[tid];
    split4(vv.x * ik, vv.y * ik, vv.z * ik, vv.w * ik, hv, lv);
    ((uint2*)(d_vth + (size_t)r * DIMM))[tid] = hv;
    ((uint2*)(d_vtl + (size_t)r * DIMM))[tid] = lv;
}

// ---------------- gv: g[e] = sum_n kr[n] * f_v[n,e] ----------------
__global__ void gv_kernel() {
    int blk = blockIdx.x;
    int h = blk >> 4, qi = blk & 15;
    int r0 = qi * NN;
    int e = threadIdx.x;
    __shared__ float kr[NN];
    for (int i = threadIdx.x; i < NN; i += 128) kr[i] = d_kr[h][r0 + i];
    __syncthreads();
    float a0 = 0.f, a1 = 0.f, a2 = 0.f, a3 = 0.f;
    const float* vp = d_fv + (size_t)r0 * DIMM + h * DD + e;
#pragma unroll 4
    for (int n = 0; n < NN; n += 4) {
        a0 += kr[n] * vp[(size_t)n * DIMM];
        a1 += kr[n + 1] * vp[(size_t)(n + 1) * DIMM];
        a2 += kr[n + 2] * vp[(size_t)(n + 2) * DIMM];
        a3 += kr[n + 3] * vp[(size_t)(n + 3) * DIMM];
    }
    d_gv[blk][e] = (a0 + a1) + (a2 + a3);
}

// ---------------- reduce gram partials ----------------
__global__ void creduce_kernel() {
    int h = blockIdx.x;
    float ssum = 0.f;
    for (int i = threadIdx.x; i < DD * DD; i += 256) {
        float c = 0.f;
#pragma unroll
        for (int p = 0; p < GCH; p++) c += d_Cpart[h * GCH + p][i];
        if ((i / DD) != (i % DD)) ssum += c * c;
    }
    __shared__ float sh[8];
    ssum = warpsum(ssum);
    int w = threadIdx.x >> 5, lane = threadIdx.x & 31;
    if (lane == 0) sh[w] = ssum;
    __syncthreads();
    if (threadIdx.x == 0) {
        float S = 0.f;
#pragma unroll
        for (int i = 0; i < 8; i++) S += sh[i];
        float fro = sqrtf(S) * (1.f / RTOT);
        float score = fro * (1.f / (128.f * 128.f));
        d_dscale[h] = expf(-5.f * score);
    }
}

// ---------------- global column-sum partials ----------------
__global__ void gpart_kernel() {
    int b = blockIdx.x;
    int r0 = b * 128;
    int t = threadIdx.x;
    float sq[4] = {}, sk[4] = {};
    for (int row = 0; row < 128; row++) {
        const float* fq = d_fq + (size_t)(r0 + row) * DIMM;
        const float* fk = d_fk + (size_t)(r0 + row) * DIMM;
#pragma unroll
        for (int c = 0; c < 4; c++) {
            sq[c] += fq[t + c * 256];
            sk[c] += fk[t + c * 256];
        }
    }
#pragma unroll
    for (int c = 0; c < 4; c++) {
        d_gpart[b][t + c * 256] = sq[c];
        d_gpart[b][DIMM + t + c * 256] = sk[c];
    }
}

// ---------------- weight-predictor MLP ----------------
__global__ void wp_kernel(const float* __restrict__ w1, const float* __restrict__ b1,
                          const float* __restrict__ lng, const float* __restrict__ lnb,
                          const float* __restrict__ w2, const float* __restrict__ b2) {
    __shared__ float qg[DIMM], kg[DIMM];
    __shared__ float h1[HH][DD];
    __shared__ float logits[HH][3];
    int tid = threadIdx.x;
    for (int i = tid; i < DIMM; i += 256) {
        float s = 0.f, s2 = 0.f;
        for (int b = 0; b < 64; b++) { s += d_gpart[b][i]; s2 += d_gpart[b][DIMM + i]; }
        qg[i] = s * (1.f / RTOT);
        kg[i] = s2 * (1.f / RTOT);
    }
    __syncthreads();
    for (int idx = tid; idx < HH * DD; idx += 256) {
        int h = idx / DD, i = idx % DD;
        float s = b1[i];
        const float* wr = w1 + i * 256;
#pragma unroll 4
        for (int j = 0; j < 128; j++) s += qg[h * 128 + j] * wr[j];
#pragma unroll 4
        for (int j = 0; j < 128; j++) s += kg[h * 128 + j] * wr[128 + j];
        h1[h][i] = s;
    }
    __syncthreads();
    int w = tid >> 5, lane = tid & 31;
    if (w < 8) {
        float s = 0.f, sq = 0.f;
        for (int i = lane; i < DD; i += 32) { float v = h1[w][i]; s += v; sq += v * v; }
        s = warpsum(s); sq = warpsum(sq);
        float mean = s * (1.f / DD);
        float var = sq * (1.f / DD) - mean * mean;
        float rs = rsqrtf(var + 1e-5f);
        for (int i = lane; i < DD; i += 32) {
            float vv = (h1[w][i] - mean) * rs * lng[i] + lnb[i];
            h1[w][i] = fmaxf(vv, 0.f);
        }
    }
    __syncthreads();
    if (tid < 24) {
        int h = tid / 3, c = tid % 3;
        float s = b2[c];
        const float* wr = w2 + c * DD;
        for (int i = 0; i < DD; i++) s += h1[h][i] * wr[i];
        logits[h][c] = s;
    }
    __syncthreads();
    if (tid < 8) {
        float a = logits[tid][0], b = logits[tid][1], c = logits[tid][2];
        float m = fmaxf(a, fmaxf(b, c));
        float ea = expf(a - m), eb = expf(b - m), ec = expf(c - m);
        float inv = 1.f / (ea + eb + ec);
        d_s1[tid] = ea * inv + eb * inv * d_dscale[tid];
        d_wws[tid] = ec * inv;
    }
}

// ---------------- launch ----------------
extern "C" void kernel_launch(void* const* d_in, const int* in_sizes, int n_in,
                              void* d_out, int out_size) {
    const float* q      = (const float*)d_in[0];
    const float* k      = (const float*)d_in[1];
    const float* v      = (const float*)d_in[2];
    const float* ln_g   = (const float*)d_in[3];
    const float* ln_b   = (const float*)d_in[4];
    const float* w_in   = (const float*)d_in[5];
    const float* wp_w1  = (const float*)d_in[6];
    const float* wp_b1  = (const float*)d_in[7];
    const float* wp_lng = (const float*)d_in[8];
    const float* wp_lnb = (const float*)d_in[9];
    const float* wp_w2  = (const float*)d_in[10];
    const float* wp_b2  = (const float*)d_in[11];
    const float* w_out  = (const float*)d_in[12];
    const float* b_out  = (const float*)d_in[13];
    float* out = (float*)d_out;

    cudaFuncSetAttribute(mm_proj_kernel, cudaFuncAttributeMaxDynamicSharedMemorySize, MM_SMEM);
    cudaFuncSetAttribute(mm_out_kernel, cudaFuncAttributeMaxDynamicSharedMemorySize, MM_SMEM);
    cudaFuncSetAttribute(gram_tc_kernel, cudaFuncAttributeMaxDynamicSharedMemorySize, ATB_SMEM);
    cudaFuncSetAttribute(kvm_tc_kernel, cudaFuncAttributeMaxDynamicSharedMemorySize, ATB_SMEM);
    cudaFuncSetAttribute(attout_tc_kernel, cudaFuncAttributeMaxDynamicSharedMemorySize, AO_SMEM);

    lnconv_kernel<<<3 * RTOT, 256>>>(q, k, v, ln_g, ln_b);
    wconv_kernel<<<2 * DIMM, 256>>>(w_in, w_out);

    dim3 gproj(DIMM / 128, RTOT / 128, 3);
    mm_proj_kernel<<<gproj, 256, MM_SMEM>>>();

    headstats_kernel<<<RTOT, 256>>>();
    prep_kernel<<<RTOT, 256>>>();

    dim3 ggram(GCH, HH);
    gram_tc_kernel<<<ggram, 256, ATB_SMEM>>>();
    creduce_kernel<<<HH, 256>>>();

    gpart_kernel<<<64, 256>>>();
    wp_kernel<<<1, 256>>>(wp_w1, wp_b1, wp_lng, wp_lnb, wp_w2, wp_b2);

    kvm_tc_kernel<<<HH * QBB, 256, ATB_SMEM>>>();
    gv_kernel<<<HH * QBB, 128>>>();

    dim3 gatt(4, HH * QBB);
    attout_tc_kernel<<<gatt, 256, AO_SMEM>>>();

    dim3 gout(DIMM / 128, RTOT / 128);
    mm_out_kernel<<<gout, 256, MM_SMEM>>>(b_out, out);
}

// round 9
// speedup vs baseline: 2.6846x; 1.0530x over previous
#include <cuda_runtime.h>
#include <cuda_bf16.h>
#include <math.h>
#include <stdint.h>

// Problem constants
#define RTOT 8192     // QB*N tokens
#define DIMM 1024
#define HH 8
#define DD 128
#define NN 512
#define QBB 16
#define GCH 16        // gram split-K chunks (512 rows each)

// ---------------- static device scratch (no runtime allocation) ----------------
__device__ __nv_bfloat16 d_xh[3][RTOT * DIMM];   // LN(x) hi bf16 (q,k,v)
__device__ __nv_bfloat16 d_xl[3][RTOT * DIMM];   // LN(x) lo residual
__device__ __nv_bfloat16 d_oh[RTOT * DIMM];      // att output hi
__device__ __nv_bfloat16 d_ol[RTOT * DIMM];      // att output lo
__device__ __nv_bfloat16 d_wih[DIMM * DIMM], d_wil[DIMM * DIMM];  // w_in split
__device__ __nv_bfloat16 d_woh[DIMM * DIMM], d_wol[DIMM * DIMM];  // w_out split
__device__ __nv_bfloat16 d_fqh[RTOT * DIMM], d_fql[RTOT * DIMM];  // f_q split
__device__ __nv_bfloat16 d_fkh[RTOT * DIMM], d_fkl[RTOT * DIMM];  // f_k split
__device__ __nv_bfloat16 d_qch[RTOT * DIMM], d_qcl[RTOT * DIMM];  // q centered split
__device__ __nv_bfloat16 d_vth[RTOT * DIMM], d_vtl[RTOT * DIMM];  // ikn-scaled v split
__device__ __nv_bfloat16 d_Mh[HH * QBB * DD * DD], d_Ml[HH * QBB * DD * DD];
__device__ float d_fq[RTOT * DIMM];
__device__ float d_fk[RTOT * DIMM];
__device__ float d_fv[RTOT * DIMM];
__device__ float d_iqn[HH][RTOT];
__device__ float d_ikn[HH][RTOT];
__device__ float d_qr[HH][RTOT];
__device__ float d_kr[HH][RTOT];
__device__ float d_qmean[HH][RTOT];
__device__ float d_Cpart[HH * GCH][DD * DD];
__device__ float d_cred[HH][16];
__device__ float d_dscale[HH];
__device__ float d_gpart[256][2 * DIMM];
__device__ float d_s1[HH];
__device__ float d_wws[HH];
__device__ float d_gv[HH * QBB][DD];

__device__ __forceinline__ float warpsum(float v) {
#pragma unroll
    for (int o = 16; o; o >>= 1) v += __shfl_xor_sync(0xffffffffu, v, o);
    return v;
}

__device__ __forceinline__ uint32_t smem_u32(const void* p) {
    uint32_t a;
    asm("{ .reg .u64 t; cvta.to.shared.u64 t, %1; cvt.u32.u64 %0, t; }" : "=r"(a) : "l"(p));
    return a;
}

// split fp32 -> bf16 hi (truncate) + bf16 lo (rn residual)
__device__ __forceinline__ void split4(float x0, float x1, float x2, float x3,
                                       uint2& h, uint2& l) {
    uint32_t u0 = __float_as_uint(x0), u1 = __float_as_uint(x1);
    uint32_t u2 = __float_as_uint(x2), u3 = __float_as_uint(x3);
    h.x = (u0 >> 16) | (u1 & 0xFFFF0000u);
    h.y = (u2 >> 16) | (u3 & 0xFFFF0000u);
    float l0 = x0 - __uint_as_float(u0 & 0xFFFF0000u);
    float l1 = x1 - __uint_as_float(u1 & 0xFFFF0000u);
    float l2 = x2 - __uint_as_float(u2 & 0xFFFF0000u);
    float l3 = x3 - __uint_as_float(u3 & 0xFFFF0000u);
    asm("cvt.rn.bf16x2.f32 %0, %1, %2;" : "=r"(l.x) : "f"(l1), "f"(l0));
    asm("cvt.rn.bf16x2.f32 %0, %1, %2;" : "=r"(l.y) : "f"(l3), "f"(l2));
}
__device__ __forceinline__ void split2(float x0, float x1, uint32_t& h, uint32_t& l) {
    uint32_t u0 = __float_as_uint(x0), u1 = __float_as_uint(x1);
    h = (u0 >> 16) | (u1 & 0xFFFF0000u);
    float l0 = x0 - __uint_as_float(u0 & 0xFFFF0000u);
    float l1 = x1 - __uint_as_float(u1 & 0xFFFF0000u);
    asm("cvt.rn.bf16x2.f32 %0, %1, %2;" : "=r"(l) : "f"(l1), "f"(l0));
}

__device__ __forceinline__ void cp16(uint32_t dst, const void* src) {
    asm volatile("cp.async.cg.shared.global [%0], [%1], 16;\n" :: "r"(dst), "l"(src));
}
__device__ __forceinline__ void ldsm_x4(uint32_t* r, uint32_t a) {
    asm volatile("ldmatrix.sync.aligned.m8n8.x4.shared.b16 {%0,%1,%2,%3}, [%4];\n"
                 : "=r"(r[0]), "=r"(r[1]), "=r"(r[2]), "=r"(r[3]) : "r"(a));
}
__device__ __forceinline__ void ldsm_x4_t(uint32_t* r, uint32_t a) {
    asm volatile("ldmatrix.sync.aligned.m8n8.x4.trans.shared.b16 {%0,%1,%2,%3}, [%4];\n"
                 : "=r"(r[0]), "=r"(r[1]), "=r"(r[2]), "=r"(r[3]) : "r"(a));
}
__device__ __forceinline__ void mma_bf16(float* d, const uint32_t* a, const uint32_t* b) {
    asm volatile(
        "mma.sync.aligned.m16n8k16.row.col.f32.bf16.bf16.f32 "
        "{%0,%1,%2,%3}, {%4,%5,%6,%7}, {%8,%9}, {%0,%1,%2,%3};\n"
        : "+f"(d[0]), "+f"(d[1]), "+f"(d[2]), "+f"(d[3])
        : "r"(a[0]), "r"(a[1]), "r"(a[2]), "r"(a[3]), "r"(b[0]), "r"(b[1]));
}

// ---------------- fused rowstats + LayerNorm + bf16 split ----------------
__global__ void lnconv_kernel(const float* __restrict__ q, const float* __restrict__ k,
                              const float* __restrict__ v,
                              const float* __restrict__ lng, const float* __restrict__ lnb) {
    int idx = blockIdx.x;
    int t = idx >> 13;
    int r = idx & (RTOT - 1);
    const float* A = (t == 0) ? q : (t == 1) ? k : v;
    int tid = threadIdx.x;
    float4 x = ((const float4*)(A + (size_t)r * DIMM))[tid];
    float s = x.x + x.y + x.z + x.w;
    float sq = x.x * x.x + x.y * x.y + x.z * x.z + x.w * x.w;
    __shared__ float sh[16];
    __shared__ float smu, srs;
    s = warpsum(s); sq = warpsum(sq);
    int w = tid >> 5, lane = tid & 31;
    if (lane == 0) { sh[w] = s; sh[8 + w] = sq; }
    __syncthreads();
    if (tid == 0) {
        float S = 0.f, SQ = 0.f;
#pragma unroll
        for (int i = 0; i < 8; i++) { S += sh[i]; SQ += sh[8 + i]; }
        float mu = S * (1.f / DIMM);
        float var = SQ * (1.f / DIMM) - mu * mu;
        smu = mu;
        srs = rsqrtf(var + 1e-5f);
    }
    __syncthreads();
    float mu = smu, rs = srs;
    float4 g = ((const float4*)lng)[tid];
    float4 b = ((const float4*)lnb)[tid];
    float y0 = (x.x - mu) * rs * g.x + b.x;
    float y1 = (x.y - mu) * rs * g.y + b.y;
    float y2 = (x.z - mu) * rs * g.z + b.z;
    float y3 = (x.w - mu) * rs * g.w + b.w;
    uint2 hv, lv;
    split4(y0, y1, y2, y3, hv, lv);
    ((uint2*)(d_xh[t] + (size_t)r * DIMM))[tid] = hv;
    ((uint2*)(d_xl[t] + (size_t)r * DIMM))[tid] = lv;
}

// ---------------- weight convert ----------------
__global__ void wconv_kernel(const float* __restrict__ w_in, const float* __restrict__ w_out) {
    int row = blockIdx.x;
    int tid = threadIdx.x;
    const float* src;
    __nv_bfloat16 *H, *L;
    if (row < DIMM) {
        src = w_in + (size_t)row * DIMM;
        H = d_wih + (size_t)row * DIMM;
        L = d_wil + (size_t)row * DIMM;
    } else {
        src = w_out + (size_t)(row - DIMM) * DIMM;
        H = d_woh + (size_t)(row - DIMM) * DIMM;
        L = d_wol + (size_t)(row - DIMM) * DIMM;
    }
    float4 x = ((const float4*)src)[tid];
    uint2 hv, lv;
    split4(x.x, x.y, x.z, x.w, hv, lv);
    ((uint2*)H)[tid] = hv;
    ((uint2*)L)[tid] = lv;
}

// =====================================================================
//  big GEMM: C[8192x1024] = A @ B^T, bf16x3.  CTA tile 128x256,
//  K-blocks of 64, 2-stage cp.async pipeline, 1 sync per K-iter.
//  Stage layout: Ah 16KB | Al 16KB | Bh 32KB | Bl 32KB = 96KB
// =====================================================================
static constexpr int MM_STAGE = 98304;
static constexpr int MM_SMEM = 2 * MM_STAGE;    // 192 KB

__device__ __forceinline__ void mm_fill(uint32_t sb, int s, int kb,
                                        const char* const* gsrc, int tid) {
    uint32_t st = sb + s * MM_STAGE;
    // A: 128 rows x 128B per part
#pragma unroll
    for (int p = 0; p < 2; p++) {
        uint32_t base = st + p * 16384;
        const char* src = gsrc[p] + kb * 128;
#pragma unroll
        for (int i = 0; i < 4; i++) {
            int id = tid + i * 256;
            int row = id >> 3, c = id & 7;
            uint32_t sw = (uint32_t)((c ^ (row & 7)) << 4);
            cp16(base + row * 128 + sw, src + (size_t)row * 2048 + c * 16);
        }
    }
    // B: 256 rows x 128B per part
#pragma unroll
    for (int p = 0; p < 2; p++) {
        uint32_t base = st + 32768 + p * 32768;
        const char* src = gsrc[2 + p] + kb * 128;
#pragma unroll
        for (int i = 0; i < 8; i++) {
            int id = tid + i * 256;
            int row = id >> 3, c = id & 7;
            uint32_t sw = (uint32_t)((c ^ (row & 7)) << 4);
            cp16(base + row * 128 + sw, src + (size_t)row * 2048 + c * 16);
        }
    }
    asm volatile("cp.async.commit_group;\n");
}

__device__ __forceinline__ void mm_compute(uint32_t st, float acc[4][8][4],
                                           int wm, int wn, int lane) {
    uint32_t bAh = st, bAl = st + 16384, bBh = st + 32768, bBl = st + 65536;
    int la7 = lane & 7;
#pragma unroll
    for (int kc = 0; kc < 4; kc++) {
        uint32_t ah[4][4], al[4][4];
        int chA = kc * 2 + (lane >> 4);
#pragma unroll
        for (int mi = 0; mi < 4; mi++) {
            int row = wm * 64 + mi * 16 + la7 + ((lane >> 3) & 1) * 8;
            uint32_t off = (uint32_t)row * 128 + (uint32_t)((chA ^ (row & 7)) << 4);
            ldsm_x4(ah[mi], bAh + off);
            ldsm_x4(al[mi], bAl + off);
        }
        int chB = kc * 2 + ((lane >> 3) & 1);
#pragma unroll
        for (int nh = 0; nh < 4; nh++) {
            int row = wn * 64 + nh * 16 + la7 + (lane >> 4) * 8;
            uint32_t off = (uint32_t)row * 128 + (uint32_t)((chB ^ (row & 7)) << 4);
            uint32_t bh[4], bl[4];
            ldsm_x4(bh, bBh + off);
            ldsm_x4(bl, bBl + off);
#pragma unroll
            for (int mi = 0; mi < 4; mi++) {
                mma_bf16(acc[mi][2 * nh],     ah[mi], bh);
                mma_bf16(acc[mi][2 * nh],     al[mi], bh);
                mma_bf16(acc[mi][2 * nh],     ah[mi], bl);
                mma_bf16(acc[mi][2 * nh + 1], ah[mi], bh + 2);
                mma_bf16(acc[mi][2 * nh + 1], al[mi], bh + 2);
                mma_bf16(acc[mi][2 * nh + 1], ah[mi], bl + 2);
            }
        }
    }
}

template <bool DO_BIAS, bool WSPLIT>
__device__ __forceinline__ void mm_body(
    const __nv_bfloat16* __restrict__ Ah, const __nv_bfloat16* __restrict__ Al,
    const __nv_bfloat16* __restrict__ Bh, const __nv_bfloat16* __restrict__ Bl,
    float* __restrict__ C, const float* __restrict__ bias,
    __nv_bfloat16* __restrict__ SH, __nv_bfloat16* __restrict__ SL) {
    extern __shared__ char smem[];
    int tid = threadIdx.x, lane = tid & 31, wid = tid >> 5;
    int wm = wid >> 2, wn = wid & 3;
    int m0 = blockIdx.y * 128, n0 = blockIdx.x * 256;
    uint32_t sb = smem_u32(smem);

    const char* gsrc[4];
    gsrc[0] = (const char*)(Ah + (size_t)m0 * DIMM);
    gsrc[1] = (const char*)(Al + (size_t)m0 * DIMM);
    gsrc[2] = (const char*)(Bh + (size_t)n0 * DIMM);
    gsrc[3] = (const char*)(Bl + (size_t)n0 * DIMM);

    float acc[4][8][4];
#pragma unroll
    for (int i = 0; i < 4; i++)
#pragma unroll
        for (int j = 0; j < 8; j++)
#pragma unroll
            for (int q = 0; q < 4; q++) acc[i][j][q] = 0.f;

    mm_fill(sb, 0, 0, gsrc, tid);

    for (int kb = 0; kb < 16; kb++) {
        asm volatile("cp.async.wait_group 0;\n");
        __syncthreads();
        if (kb + 1 < 16) mm_fill(sb, (kb + 1) & 1, kb + 1, gsrc, tid);
        mm_compute(sb + (kb & 1) * MM_STAGE, acc, wm, wn, lane);
    }

#pragma unroll
    for (int mi = 0; mi < 4; mi++) {
        int r0 = m0 + wm * 64 + mi * 16 + (lane >> 2);
#pragma unroll
        for (int ni = 0; ni < 8; ni++) {
            int c = n0 + wn * 64 + ni * 8 + (lane & 3) * 2;
            float2 v0 = make_float2(acc[mi][ni][0], acc[mi][ni][1]);
            float2 v1 = make_float2(acc[mi][ni][2], acc[mi][ni][3]);
            if (DO_BIAS) {
                float b0 = bias[c], b1 = bias[c + 1];
                v0.x += b0; v0.y += b1;
                v1.x += b0; v1.y += b1;
            }
            *(float2*)(C + (size_t)r0 * DIMM + c) = v0;
            *(float2*)(C + (size_t)(r0 + 8) * DIMM + c) = v1;
            if (WSPLIT) {
                uint32_t hh, ll;
                split2(v0.x, v0.y, hh, ll);
                *(uint32_t*)(SH + (size_t)r0 * DIMM + c) = hh;
                *(uint32_t*)(SL + (size_t)r0 * DIMM + c) = ll;
                split2(v1.x, v1.y, hh, ll);
                *(uint32_t*)(SH + (size_t)(r0 + 8) * DIMM + c) = hh;
                *(uint32_t*)(SL + (size_t)(r0 + 8) * DIMM + c) = ll;
            }
        }
    }
}

__global__ void __launch_bounds__(256, 1) mm_proj_kernel() {
    int which = blockIdx.z;
    if (which == 0)
        mm_body<false, true>(d_xh[0], d_xl[0], d_wih, d_wil, d_fq, nullptr, d_fqh, d_fql);
    else if (which == 1)
        mm_body<false, true>(d_xh[1], d_xl[1], d_wih, d_wil, d_fk, nullptr, d_fkh, d_fkl);
    else
        mm_body<false, false>(d_xh[2], d_xl[2], d_wih, d_wil, d_fv, nullptr, nullptr, nullptr);
}

__global__ void __launch_bounds__(256, 1) mm_out_kernel(const float* __restrict__ bias,
                                                        float* __restrict__ out) {
    mm_body<true, false>(d_oh, d_ol, d_woh, d_wol, out, bias, nullptr, nullptr);
}

// =====================================================================
//  A^T B tensor-core kernel: C[128x128] = sum_{n<512} A[n][d] * B[n][e]
// =====================================================================
static constexpr int ATB_MAT = 64 * 272;       // 17408
static constexpr int ATB_STG = 4 * ATB_MAT;    // 69632
static constexpr int ATB_SMEM = 2 * ATB_STG;   // 139264

__device__ __forceinline__ void atb_fill(uint32_t sb, int s, int c,
        const __nv_bfloat16* Ah, const __nv_bfloat16* Al,
        const __nv_bfloat16* Bh, const __nv_bfloat16* Bl) {
    int tid = threadIdx.x;
    const __nv_bfloat16* srcs[4] = {Ah, Al, Bh, Bl};
#pragma unroll
    for (int p = 0; p < 4; p++) {
        uint32_t base = sb + s * ATB_STG + p * ATB_MAT;
        const __nv_bfloat16* src = srcs[p];
#pragma unroll
        for (int i = 0; i < 4; i++) {
            int id = tid + i * 256;
            int row = id >> 4, c16 = id & 15;
            cp16(base + row * 272 + c16 * 16,
                 src + (size_t)(c * 64 + row) * DIMM + c16 * 8);
        }
    }
    asm volatile("cp.async.commit_group;\n");
}

__device__ __forceinline__ void atb_compute(uint32_t sb, int s, float acc[4][4][4],
                                            int wm, int wn, int lane) {
    uint32_t bA  = sb + s * ATB_STG;
    uint32_t bAl = bA + ATB_MAT;
    uint32_t bB  = bA + 2 * ATB_MAT;
    uint32_t bBl = bA + 3 * ATB_MAT;
    int la7 = lane & 7;
    int arow = ((lane >> 4) << 3) + la7;
    int acol = (((lane >> 3) & 1) << 3);
    int brow = (((lane >> 3) & 1) << 3) + la7;
    int bcol = ((lane >> 4) << 3);
#pragma unroll
    for (int kc = 0; kc < 4; kc++) {
        uint32_t ah[4][4], al[4][4];
#pragma unroll
        for (int mi = 0; mi < 4; mi++) {
            uint32_t off = (uint32_t)(kc * 16 + arow) * 272 +
                           (uint32_t)(wm * 64 + mi * 16 + acol) * 2;
            ldsm_x4_t(ah[mi], bA + off);
            ldsm_x4_t(al[mi], bAl + off);
        }
        uint32_t bh[4][2], bl[4][2];
#pragma unroll
        for (int nh = 0; nh < 2; nh++) {
            uint32_t off = (uint32_t)(kc * 16 + brow) * 272 +
                           (uint32_t)(wn * 32 + nh * 16 + bcol) * 2;
            uint32_t r[4];
            ldsm_x4_t(r, bB + off);
            bh[2 * nh][0] = r[0]; bh[2 * nh][1] = r[1];
            bh[2 * nh + 1][0] = r[2]; bh[2 * nh + 1][1] = r[3];
            ldsm_x4_t(r, bBl + off);
            bl[2 * nh][0] = r[0]; bl[2 * nh][1] = r[1];
            bl[2 * nh + 1][0] = r[2]; bl[2 * nh + 1][1] = r[3];
        }
#pragma unroll
        for (int mi = 0; mi < 4; mi++)
#pragma unroll
            for (int ni = 0; ni < 4; ni++) {
                mma_bf16(acc[mi][ni], ah[mi], bh[ni]);
                mma_bf16(acc[mi][ni], al[mi], bh[ni]);
                mma_bf16(acc[mi][ni], ah[mi], bl[ni]);
            }
    }
}

template <bool SPLIT_OUT>
__device__ __forceinline__ void atb_body(
        const __nv_bfloat16* Ah, const __nv_bfloat16* Al,
        const __nv_bfloat16* Bh, const __nv_bfloat16* Bl,
        float* Cf, __nv_bfloat16* Oh, __nv_bfloat16* Ol) {
    extern __shared__ char smem[];
    uint32_t sb = smem_u32(smem);
    int tid = threadIdx.x, lane = tid & 31, wid = tid >> 5;
    int wm = wid >> 2, wn = wid & 3;
    float acc[4][4][4];
#pragma unroll
    for (int i = 0; i < 4; i++)
#pragma unroll
        for (int j = 0; j < 4; j++)
#pragma unroll
            for (int q = 0; q < 4; q++) acc[i][j][q] = 0.f;

    atb_fill(sb, 0, 0, Ah, Al, Bh, Bl);
    for (int c = 0; c < 8; c++) {
        int s = c & 1;
        asm volatile("cp.async.wait_group 0;\n");
        __syncthreads();
        if (c + 1 < 8) atb_fill(sb, (c + 1) & 1, c + 1, Ah, Al, Bh, Bl);
        atb_compute(sb, s, acc, wm, wn, lane);
    }
#pragma unroll
    for (int mi = 0; mi < 4; mi++) {
        int d0 = wm * 64 + mi * 16 + (lane >> 2);
#pragma unroll
        for (int ni = 0; ni < 4; ni++) {
            int e = wn * 32 + ni * 8 + (lane & 3) * 2;
            if (SPLIT_OUT) {
                uint32_t hh, ll;
                split2(acc[mi][ni][0], acc[mi][ni][1], hh, ll);
                *(uint32_t*)(Oh + d0 * DD + e) = hh;
                *(uint32_t*)(Ol + d0 * DD + e) = ll;
                split2(acc[mi][ni][2], acc[mi][ni][3], hh, ll);
                *(uint32_t*)(Oh + (d0 + 8) * DD + e) = hh;
                *(uint32_t*)(Ol + (d0 + 8) * DD + e) = ll;
            } else {
                *(float2*)(Cf + d0 * DD + e) = make_float2(acc[mi][ni][0], acc[mi][ni][1]);
                *(float2*)(Cf + (d0 + 8) * DD + e) = make_float2(acc[mi][ni][2], acc[mi][ni][3]);
            }
        }
    }
}

__global__ void __launch_bounds__(256, 1) gram_tc_kernel() {
    int ch = blockIdx.x, h = blockIdx.y;
    const __nv_bfloat16* Ah = d_qch + (size_t)(ch * 512) * DIMM + h * DD;
    const __nv_bfloat16* Al = d_qcl + (size_t)(ch * 512) * DIMM + h * DD;
    atb_body<false>(Ah, Al, Ah, Al, d_Cpart[h * GCH + ch], nullptr, nullptr);
}

__global__ void __launch_bounds__(256, 1) kvm_tc_kernel() {
    int blk = blockIdx.x;
    int h = blk >> 4, qi = blk & 15;
    size_t off = (size_t)(qi * NN) * DIMM + h * DD;
    atb_body<true>(d_fkh + off, d_fkl + off, d_vth + off, d_vtl + off,
                   nullptr, d_Mh + (size_t)blk * DD * DD, d_Ml + (size_t)blk * DD * DD);
}

// =====================================================================
//  attout: att[128x128] = f_q(128x128) @ M(128x128), + rank-1 term
// =====================================================================
static constexpr int AO_MAT = 128 * 272;       // 34816
static constexpr int AO_SMEM = 4 * AO_MAT;     // 139264

__global__ void __launch_bounds__(256, 1) attout_tc_kernel() {
    int blk = blockIdx.y, mt = blockIdx.x;
    int h = blk >> 4, qi = blk & 15;
    int r0g = qi * NN + mt * 128;
    int co = h * DD;
    extern __shared__ char smem[];
    uint32_t sb = smem_u32(smem);
    int tid = threadIdx.x, lane = tid & 31, wid = tid >> 5;
    int wm = wid >> 2, wn = wid & 3;
    int la7 = lane & 7;

    {
        const __nv_bfloat16* Asrc[2] = {d_fqh, d_fql};
#pragma unroll
        for (int p = 0; p < 2; p++) {
            uint32_t base = sb + p * AO_MAT;
            const __nv_bfloat16* src = Asrc[p] + (size_t)r0g * DIMM + co;
#pragma unroll
            for (int i = 0; i < 8; i++) {
                int id = tid + i * 256;
                int row = id >> 4, c16 = id & 15;
                cp16(base + row * 272 + c16 * 16, src + (size_t)row * DIMM + c16 * 8);
            }
        }
        const __nv_bfloat16* Bsrc[2] = {d_Mh + (size_t)blk * DD * DD,
                                        d_Ml + (size_t)blk * DD * DD};
#pragma unroll
        for (int p = 0; p < 2; p++) {
            uint32_t base = sb + (2 + p) * AO_MAT;
            const __nv_bfloat16* src = Bsrc[p];
#pragma unroll
            for (int i = 0; i < 8; i++) {
                int id = tid + i * 256;
                int row = id >> 4, c16 = id & 15;
                cp16(base + row * 272 + c16 * 16, src + row * DD + c16 * 8);
            }
        }
        asm volatile("cp.async.commit_group;\ncp.async.wait_group 0;\n");
        __syncthreads();
    }

    float acc[4][4][4];
#pragma unroll
    for (int i = 0; i < 4; i++)
#pragma unroll
        for (int j = 0; j < 4; j++)
#pragma unroll
            for (int q = 0; q < 4; q++) acc[i][j][q] = 0.f;

    uint32_t bA  = sb;
    uint32_t bAl = sb + AO_MAT;
    uint32_t bB  = sb + 2 * AO_MAT;
    uint32_t bBl = sb + 3 * AO_MAT;
    int brow = (((lane >> 3) & 1) << 3) + la7;
    int bcol = ((lane >> 4) << 3);
#pragma unroll
    for (int kc = 0; kc < 8; kc++) {
        uint32_t ah[4][4], al[4][4];
#pragma unroll
        for (int mi = 0; mi < 4; mi++) {
            uint32_t off = (uint32_t)(wm * 64 + mi * 16 + (lane & 15)) * 272 +
                           (uint32_t)(kc * 16 + ((lane >> 4) << 3)) * 2;
            ldsm_x4(ah[mi], bA + off);
            ldsm_x4(al[mi], bAl + off);
        }
        uint32_t bh[4][2], bl[4][2];
#pragma unroll
        for (int nh = 0; nh < 2; nh++) {
            uint32_t off = (uint32_t)(kc * 16 + brow) * 272 +
                           (uint32_t)(wn * 32 + nh * 16 + bcol) * 2;
            uint32_t r[4];
            ldsm_x4_t(r, bB + off);
            bh[2 * nh][0] = r[0]; bh[2 * nh][1] = r[1];
            bh[2 * nh + 1][0] = r[2]; bh[2 * nh + 1][1] = r[3];
            ldsm_x4_t(r, bBl + off);
            bl[2 * nh][0] = r[0]; bl[2 * nh][1] = r[1];
            bl[2 * nh + 1][0] = r[2]; bl[2 * nh + 1][1] = r[3];
        }
#pragma unroll
        for (int mi = 0; mi < 4; mi++)
#pragma unroll
            for (int ni = 0; ni < 4; ni++) {
                mma_bf16(acc[mi][ni], ah[mi], bh[ni]);
                mma_bf16(acc[mi][ni], al[mi], bh[ni]);
                mma_bf16(acc[mi][ni], ah[mi], bl[ni]);
            }
    }

    float s1 = d_s1[h], ww = d_wws[h];
#pragma unroll
    for (int mi = 0; mi < 4; mi++) {
        int rA = r0g + wm * 64 + mi * 16 + (lane >> 2);
        int rB = rA + 8;
        float f1a = s1 * d_iqn[h][rA], f2a = ww * d_qr[h][rA];
        float f1b = s1 * d_iqn[h][rB], f2b = ww * d_qr[h][rB];
#pragma unroll
        for (int ni = 0; ni < 4; ni++) {
            int c = wn * 32 + ni * 8 + (lane & 3) * 2;
            float g0 = d_gv[blk][c], g1 = d_gv[blk][c + 1];
            float o0 = f1a * acc[mi][ni][0] + f2a * g0;
            float o1 = f1a * acc[mi][ni][1] + f2a * g1;
            float o2 = f1b * acc[mi][ni][2] + f2b * g0;
            float o3 = f1b * acc[mi][ni][3] + f2b * g1;
            uint32_t hh, ll;
            split2(o0, o1, hh, ll);
            *(uint32_t*)(d_oh + (size_t)rA * DIMM + co + c) = hh;
            *(uint32_t*)(d_ol + (size_t)rA * DIMM + co + c) = ll;
            split2(o2, o3, hh, ll);
            *(uint32_t*)(d_oh + (size_t)rB * DIMM + co + c) = hh;
            *(uint32_t*)(d_ol + (size_t)rB * DIMM + co + c) = ll;
        }
    }
}

// ---------------- per-(head,row) stats ----------------
__global__ void headstats_kernel() {
    int r = blockIdx.x;
    int w = threadIdx.x >> 5, lane = threadIdx.x & 31;
    {
        float4 x = *(const float4*)(d_fq + (size_t)r * DIMM + w * DD + lane * 4);
        float s = x.x + x.y + x.z + x.w;
        float sq = x.x * x.x + x.y * x.y + x.z * x.z + x.w * x.w;
        s = warpsum(s); sq = warpsum(sq);
        if (lane == 0) {
            float mean = s * (1.f / DD);
            float var = (sq - s * s * (1.f / DD)) * (1.f / (DD - 1));
            d_iqn[w][r] = rsqrtf(sq);
            d_qmean[w][r] = mean;
            d_qr[w][r] = 2.f * fminf(var, 1.f) / (var + 1.f);
        }
    }
    {
        float4 x = *(const float4*)(d_fk + (size_t)r * DIMM + w * DD + lane * 4);
        float s = x.x + x.y + x.z + x.w;
        float sq = x.x * x.x + x.y * x.y + x.z * x.z + x.w * x.w;
        s = warpsum(s); sq = warpsum(sq);
        if (lane == 0) {
            float var = (sq - s * s * (1.f / DD)) * (1.f / (DD - 1));
            d_ikn[w][r] = rsqrtf(sq);
            d_kr[w][r] = 2.f * fminf(var, 1.f) / (var + 1.f);
        }
    }
}

// ---------------- prep: q-centered split + ikn-scaled v split ----------------
__global__ void prep_kernel() {
    int r = blockIdx.x;
    int tid = threadIdx.x;
    int h = tid >> 5;
    float qm = d_qmean[h][r];
    float ik = d_ikn[h][r];
    float4 x = ((const float4*)(d_fq + (size_t)r * DIMM))[tid];
    uint2 hv, lv;
    split4(x.x - qm, x.y - qm, x.z - qm, x.w - qm, hv, lv);
    ((uint2*)(d_qch + (size_t)r * DIMM))[tid] = hv;
    ((uint2*)(d_qcl + (size_t)r * DIMM))[tid] = lv;
    float4 vv = ((const float4*)(d_fv + (size_t)r * DIMM))[tid];
    split4(vv.x * ik, vv.y * ik, vv.z * ik, vv.w * ik, hv, lv);
    ((uint2*)(d_vth + (size_t)r * DIMM))[tid] = hv;
    ((uint2*)(d_vtl + (size_t)r * DIMM))[tid] = lv;
}

// ---------------- gv: g[e] = sum_n kr[n] * f_v[n,e], 2 n-halves ----------------
__global__ void gv_kernel() {
    int blk = blockIdx.x;
    int h = blk >> 4, qi = blk & 15;
    int r0 = qi * NN;
    int tid = threadIdx.x;
    int e = tid & 127, half = tid >> 7;
    __shared__ float kr[NN];
    __shared__ float part[2][DD];
    for (int i = tid; i < NN; i += 256) kr[i] = d_kr[h][r0 + i];
    __syncthreads();
    float a0 = 0.f, a1 = 0.f, a2 = 0.f, a3 = 0.f;
    int nb = half * 256;
    const float* vp = d_fv + (size_t)(r0 + nb) * DIMM + h * DD + e;
#pragma unroll 4
    for (int n = 0; n < 256; n += 4) {
        a0 += kr[nb + n] * vp[(size_t)n * DIMM];
        a1 += kr[nb + n + 1] * vp[(size_t)(n + 1) * DIMM];
        a2 += kr[nb + n + 2] * vp[(size_t)(n + 2) * DIMM];
        a3 += kr[nb + n + 3] * vp[(size_t)(n + 3) * DIMM];
    }
    part[half][e] = (a0 + a1) + (a2 + a3);
    __syncthreads();
    if (half == 0) d_gv[blk][e] = part[0][e] + part[1][e];
}

// ---------------- reduce gram partials: two stage ----------------
__global__ void creduce1_kernel() {
    int ch = blockIdx.x;   // 16 i-chunks of 1024
    int h = blockIdx.y;
    int tid = threadIdx.x;
    float ssum = 0.f;
#pragma unroll
    for (int u = 0; u < 4; u++) {
        int i = ch * 1024 + tid + u * 256;
        float c = 0.f;
#pragma unroll
        for (int p = 0; p < GCH; p++) c += d_Cpart[h * GCH + p][i];
        if ((i / DD) != (i % DD)) ssum += c * c;
    }
    __shared__ float sh[8];
    ssum = warpsum(ssum);
    int w = tid >> 5, lane = tid & 31;
    if (lane == 0) sh[w] = ssum;
    __syncthreads();
    if (tid == 0) {
        float S = 0.f;
#pragma unroll
        for (int i = 0; i < 8; i++) S += sh[i];
        d_cred[h][ch] = S;
    }
}
__global__ void creduce2_kernel() {
    int h = blockIdx.x;
    int lane = threadIdx.x;
    float s = (lane < 16) ? d_cred[h][lane] : 0.f;
    s = warpsum(s);
    if (lane == 0) {
        float fro = sqrtf(s) * (1.f / RTOT);
        float score = fro * (1.f / (128.f * 128.f));
        d_dscale[h] = expf(-5.f * score);
    }
}

// ---------------- global column-sum partials (256 blocks x 32 rows) ----------------
__global__ void gpart_kernel() {
    int b = blockIdx.x;
    int r0 = b * 32;
    int t = threadIdx.x;
    float sq[4] = {}, sk[4] = {};
    for (int row = 0; row < 32; row++) {
        const float* fq = d_fq + (size_t)(r0 + row) * DIMM;
        const float* fk = d_fk + (size_t)(r0 + row) * DIMM;
#pragma unroll
        for (int c = 0; c < 4; c++) {
            sq[c] += fq[t + c * 256];
            sk[c] += fk[t + c * 256];
        }
    }
#pragma unroll
    for (int c = 0; c < 4; c++) {
        d_gpart[b][t + c * 256] = sq[c];
        d_gpart[b][DIMM + t + c * 256] = sk[c];
    }
}

// ---------------- weight-predictor MLP ----------------
__global__ void wp_kernel(const float* __restrict__ w1, const float* __restrict__ b1,
                          const float* __restrict__ lng, const float* __restrict__ lnb,
                          const float* __restrict__ w2, const float* __restrict__ b2) {
    __shared__ float qg[DIMM], kg[DIMM];
    __shared__ float h1[HH][DD];
    __shared__ float logits[HH][3];
    int tid = threadIdx.x;
    for (int i = tid; i < DIMM; i += 256) {
        float s = 0.f, s2 = 0.f;
        for (int b = 0; b < 256; b++) { s += d_gpart[b][i]; s2 += d_gpart[b][DIMM + i]; }
        qg[i] = s * (1.f / RTOT);
        kg[i] = s2 * (1.f / RTOT);
    }
    __syncthreads();
    for (int idx = tid; idx < HH * DD; idx += 256) {
        int h = idx / DD, i = idx % DD;
        float s = b1[i];
        const float* wr = w1 + i * 256;
#pragma unroll 4
        for (int j = 0; j < 128; j++) s += qg[h * 128 + j] * wr[j];
#pragma unroll 4
        for (int j = 0; j < 128; j++) s += kg[h * 128 + j] * wr[128 + j];
        h1[h][i] = s;
    }
    __syncthreads();
    int w = tid >> 5, lane = tid & 31;
    if (w < 8) {
        float s = 0.f, sq = 0.f;
        for (int i = lane; i < DD; i += 32) { float v = h1[w][i]; s += v; sq += v * v; }
        s = warpsum(s); sq = warpsum(sq);
        float mean = s * (1.f / DD);
        float var = sq * (1.f / DD) - mean * mean;
        float rs = rsqrtf(var + 1e-5f);
        for (int i = lane; i < DD; i += 32) {
            float vv = (h1[w][i] - mean) * rs * lng[i] + lnb[i];
            h1[w][i] = fmaxf(vv, 0.f);
        }
    }
    __syncthreads();
    if (tid < 24) {
        int h = tid / 3, c = tid % 3;
        float s = b2[c];
        const float* wr = w2 + c * DD;
        for (int i = 0; i < DD; i++) s += h1[h][i] * wr[i];
        logits[h][c] = s;
    }
    __syncthreads();
    if (tid < 8) {
        float a = logits[tid][0], b = logits[tid][1], c = logits[tid][2];
        float m = fmaxf(a, fmaxf(b, c));
        float ea = expf(a - m), eb = expf(b - m), ec = expf(c - m);
        float inv = 1.f / (ea + eb + ec);
        d_s1[tid] = ea * inv + eb * inv * d_dscale[tid];
        d_wws[tid] = ec * inv;
    }
}

// ---------------- launch ----------------
extern "C" void kernel_launch(void* const* d_in, const int* in_sizes, int n_in,
                              void* d_out, int out_size) {
    const float* q      = (const float*)d_in[0];
    const float* k      = (const float*)d_in[1];
    const float* v      = (const float*)d_in[2];
    const float* ln_g   = (const float*)d_in[3];
    const float* ln_b   = (const float*)d_in[4];
    const float* w_in   = (const float*)d_in[5];
    const float* wp_w1  = (const float*)d_in[6];
    const float* wp_b1  = (const float*)d_in[7];
    const float* wp_lng = (const float*)d_in[8];
    const float* wp_lnb = (const float*)d_in[9];
    const float* wp_w2  = (const float*)d_in[10];
    const float* wp_b2  = (const float*)d_in[11];
    const float* w_out  = (const float*)d_in[12];
    const float* b_out  = (const float*)d_in[13];
    float* out = (float*)d_out;

    cudaFuncSetAttribute(mm_proj_kernel, cudaFuncAttributeMaxDynamicSharedMemorySize, MM_SMEM);
    cudaFuncSetAttribute(mm_out_kernel, cudaFuncAttributeMaxDynamicSharedMemorySize, MM_SMEM);
    cudaFuncSetAttribute(gram_tc_kernel, cudaFuncAttributeMaxDynamicSharedMemorySize, ATB_SMEM);
    cudaFuncSetAttribute(kvm_tc_kernel, cudaFuncAttributeMaxDynamicSharedMemorySize, ATB_SMEM);
    cudaFuncSetAttribute(attout_tc_kernel, cudaFuncAttributeMaxDynamicSharedMemorySize, AO_SMEM);

    lnconv_kernel<<<3 * RTOT, 256>>>(q, k, v, ln_g, ln_b);
    wconv_kernel<<<2 * DIMM, 256>>>(w_in, w_out);

    dim3 gproj(DIMM / 256, RTOT / 128, 3);   // (4, 64, 3)
    mm_proj_kernel<<<gproj, 256, MM_SMEM>>>();

    headstats_kernel<<<RTOT, 256>>>();
    prep_kernel<<<RTOT, 256>>>();

    dim3 ggram(GCH, HH);
    gram_tc_kernel<<<ggram, 256, ATB_SMEM>>>();
    dim3 gcr1(16, HH);
    creduce1_kernel<<<gcr1, 256>>>();
    creduce2_kernel<<<HH, 32>>>();

    gpart_kernel<<<256, 256>>>();
    wp_kernel<<<1, 256>>>(wp_w1, wp_b1, wp_lng, wp_lnb, wp_w2, wp_b2);

    kvm_tc_kernel<<<HH * QBB, 256, ATB_SMEM>>>();
    gv_kernel<<<HH * QBB, 256>>>();

    dim3 gatt(4, HH * QBB);
    attout_tc_kernel<<<gatt, 256, AO_SMEM>>>();

    dim3 gout(DIMM / 256, RTOT / 128);       // (4, 64)
    mm_out_kernel<<<gout, 256, MM_SMEM>>>(b_out, out);
}

// round 13
// speedup vs baseline: 2.8289x; 1.0537x over previous
#include <cuda_runtime.h>
#include <cuda_fp16.h>
#include <math.h>
#include <stdint.h>

// Problem constants
#define RTOT 8192     // QB*N tokens
#define DIMM 1024
#define HH 8
#define DD 128
#define NN 512
#define QBB 16
#define GCH 16        // gram split-K chunks (512 rows each)

// ---------------- static device scratch (no runtime allocation) ----------------
__device__ __half d_xh[3][RTOT * DIMM];   // LN(x) hi fp16 (q,k,v)
__device__ __half d_xl[3][RTOT * DIMM];   // LN(x) lo residual
__device__ __half d_oh[RTOT * DIMM];      // att output hi
__device__ __half d_ol[RTOT * DIMM];      // att output lo
__device__ __half d_wih[DIMM * DIMM], d_wil[DIMM * DIMM];  // w_in split hi/lo
__device__ __half d_woh[DIMM * DIMM];                      // w_out hi only (2-term)
__device__ __half d_fqh[RTOT * DIMM], d_fql[RTOT * DIMM];  // f_q split
__device__ __half d_fkh[RTOT * DIMM], d_fkl[RTOT * DIMM];  // f_k split
__device__ __half d_fvh[RTOT * DIMM], d_fvl[RTOT * DIMM];  // f_v split
__device__ __half d_qch[RTOT * DIMM];                      // q centered, hi only
__device__ __half d_vth[RTOT * DIMM], d_vtl[RTOT * DIMM];  // ikn-scaled v split
__device__ __half d_Mh[HH * QBB * DD * DD], d_Ml[HH * QBB * DD * DD];
__device__ float d_iqn[HH][RTOT];
__device__ float d_ikn[HH][RTOT];
__device__ float d_qr[HH][RTOT];
__device__ float d_kr[HH][RTOT];
__device__ float d_qmean[HH][RTOT];
__device__ float d_Cpart[HH * GCH][DD * DD];
__device__ float d_cred[HH][16];
__device__ float d_dscale[HH];
__device__ float d_gpart[256][2 * DIMM];
__device__ float d_s1[HH];
__device__ float d_wws[HH];
__device__ float d_gv[HH * QBB][DD];

__device__ __forceinline__ float warpsum(float v) {
#pragma unroll
    for (int o = 16; o; o >>= 1) v += __shfl_xor_sync(0xffffffffu, v, o);
    return v;
}

__device__ __forceinline__ uint32_t smem_u32(const void* p) {
    uint32_t a;
    asm("{ .reg .u64 t; cvta.to.shared.u64 t, %1; cvt.u32.u64 %0, t; }" : "=r"(a) : "l"(p));
    return a;
}
__device__ __forceinline__ uint32_t h2u(__half2 v) { return *reinterpret_cast<uint32_t*>(&v); }

// split fp32 -> fp16 hi (rn) + fp16 lo (rn residual): 22-bit pair
__device__ __forceinline__ void hsplit2(float x0, float x1, uint32_t& h, uint32_t& l) {
    __half2 hh = __floats2half2_rn(x0, x1);
    float2 f = __half22float2(hh);
    __half2 ll = __floats2half2_rn(x0 - f.x, x1 - f.y);
    h = h2u(hh); l = h2u(ll);
}
__device__ __forceinline__ void hsplit4(float x0, float x1, float x2, float x3,
                                        uint2& h, uint2& l) {
    hsplit2(x0, x1, h.x, l.x);
    hsplit2(x2, x3, h.y, l.y);
}

__device__ __forceinline__ void cp16(uint32_t dst, const void* src) {
    asm volatile("cp.async.cg.shared.global [%0], [%1], 16;\n" :: "r"(dst), "l"(src));
}
__device__ __forceinline__ void ldsm_x4(uint32_t* r, uint32_t a) {
    asm volatile("ldmatrix.sync.aligned.m8n8.x4.shared.b16 {%0,%1,%2,%3}, [%4];\n"
                 : "=r"(r[0]), "=r"(r[1]), "=r"(r[2]), "=r"(r[3]) : "r"(a));
}
__device__ __forceinline__ void ldsm_x4_t(uint32_t* r, uint32_t a) {
    asm volatile("ldmatrix.sync.aligned.m8n8.x4.trans.shared.b16 {%0,%1,%2,%3}, [%4];\n"
                 : "=r"(r[0]), "=r"(r[1]), "=r"(r[2]), "=r"(r[3]) : "r"(a));
}
__device__ __forceinline__ void mma_f16(float* d, const uint32_t* a, const uint32_t* b) {
    asm volatile(
        "mma.sync.aligned.m16n8k16.row.col.f32.f16.f16.f32 "
        "{%0,%1,%2,%3}, {%4,%5,%6,%7}, {%8,%9}, {%0,%1,%2,%3};\n"
        : "+f"(d[0]), "+f"(d[1]), "+f"(d[2]), "+f"(d[3])
        : "r"(a[0]), "r"(a[1]), "r"(a[2]), "r"(a[3]), "r"(b[0]), "r"(b[1]));
}

// ---------------- fused rowstats + LayerNorm + fp16 split ----------------
__global__ void lnconv_kernel(const float* __restrict__ q, const float* __restrict__ k,
                              const float* __restrict__ v,
                              const float* __restrict__ lng, const float* __restrict__ lnb) {
    int idx = blockIdx.x;
    int t = idx >> 13;
    int r = idx & (RTOT - 1);
    const float* A = (t == 0) ? q : (t == 1) ? k : v;
    int tid = threadIdx.x;
    float4 x = ((const float4*)(A + (size_t)r * DIMM))[tid];
    float s = x.x + x.y + x.z + x.w;
    float sq = x.x * x.x + x.y * x.y + x.z * x.z + x.w * x.w;
    __shared__ float sh[16];
    __shared__ float smu, srs;
    s = warpsum(s); sq = warpsum(sq);
    int w = tid >> 5, lane = tid & 31;
    if (lane == 0) { sh[w] = s; sh[8 + w] = sq; }
    __syncthreads();
    if (tid == 0) {
        float S = 0.f, SQ = 0.f;
#pragma unroll
        for (int i = 0; i < 8; i++) { S += sh[i]; SQ += sh[8 + i]; }
        float mu = S * (1.f / DIMM);
        float var = SQ * (1.f / DIMM) - mu * mu;
        smu = mu;
        srs = rsqrtf(var + 1e-5f);
    }
    __syncthreads();
    float mu = smu, rs = srs;
    float4 g = ((const float4*)lng)[tid];
    float4 b = ((const float4*)lnb)[tid];
    float y0 = (x.x - mu) * rs * g.x + b.x;
    float y1 = (x.y - mu) * rs * g.y + b.y;
    float y2 = (x.z - mu) * rs * g.z + b.z;
    float y3 = (x.w - mu) * rs * g.w + b.w;
    uint2 hv, lv;
    hsplit4(y0, y1, y2, y3, hv, lv);
    ((uint2*)(d_xh[t] + (size_t)r * DIMM))[tid] = hv;
    ((uint2*)(d_xl[t] + (size_t)r * DIMM))[tid] = lv;
}

// ---------------- weight convert: w_in hi/lo, w_out hi only ----------------
__global__ void wconv_kernel(const float* __restrict__ w_in, const float* __restrict__ w_out) {
    int row = blockIdx.x;
    int tid = threadIdx.x;
    if (row < DIMM) {
        float4 x = ((const float4*)(w_in + (size_t)row * DIMM))[tid];
        uint2 hv, lv;
        hsplit4(x.x, x.y, x.z, x.w, hv, lv);
        ((uint2*)(d_wih + (size_t)row * DIMM))[tid] = hv;
        ((uint2*)(d_wil + (size_t)row * DIMM))[tid] = lv;
    } else {
        int r = row - DIMM;
        float4 x = ((const float4*)(w_out + (size_t)r * DIMM))[tid];
        uint2 hv;
        hv.x = h2u(__floats2half2_rn(x.x, x.y));
        hv.y = h2u(__floats2half2_rn(x.z, x.w));
        ((uint2*)(d_woh + (size_t)r * DIMM))[tid] = hv;
    }
}

// =====================================================================
//  big GEMM: C[8192x1024] = A @ B^T.  CTA tile 128x256, K-blocks of 64.
//  THREE=true: fp16x3 (Ah,Al,Bh,Bl).  THREE=false: fp16x2 (Ah,Al,Bh).
//  Pass-per-term MMA ordering to break accumulator RAW chains.
// =====================================================================
template <bool THREE>
__device__ __forceinline__ void mm_fill(uint32_t sb, int s, int kb,
                                        const char* const* gsrc, int tid) {
    constexpr int STAGE = THREE ? 98304 : 65536;
    uint32_t st = sb + s * STAGE;
#pragma unroll
    for (int p = 0; p < 2; p++) {       // A hi/lo: 128 rows x 128B
        uint32_t base = st + p * 16384;
        const char* src = gsrc[p] + kb * 128;
#pragma unroll
        for (int i = 0; i < 4; i++) {
            int id = tid + i * 256;
            int row = id >> 3, c = id & 7;
            uint32_t sw = (uint32_t)((c ^ (row & 7)) << 4);
            cp16(base + row * 128 + sw, src + (size_t)row * 2048 + c * 16);
        }
    }
    {                                    // B hi: 256 rows x 128B
        uint32_t base = st + 32768;
        const char* src = gsrc[2] + kb * 128;
#pragma unroll
        for (int i = 0; i < 8; i++) {
            int id = tid + i * 256;
            int row = id >> 3, c = id & 7;
            uint32_t sw = (uint32_t)((c ^ (row & 7)) << 4);
            cp16(base + row * 128 + sw, src + (size_t)row * 2048 + c * 16);
        }
    }
    if (THREE) {                         // B lo
        uint32_t base = st + 65536;
        const char* src = gsrc[3] + kb * 128;
#pragma unroll
        for (int i = 0; i < 8; i++) {
            int id = tid + i * 256;
            int row = id >> 3, c = id & 7;
            uint32_t sw = (uint32_t)((c ^ (row & 7)) << 4);
            cp16(base + row * 128 + sw, src + (size_t)row * 2048 + c * 16);
        }
    }
    asm volatile("cp.async.commit_group;\n");
}

template <bool THREE>
__device__ __forceinline__ void mm_compute(uint32_t st, float acc[4][8][4],
                                           int wm, int wn, int lane) {
    uint32_t bAh = st, bAl = st + 16384, bBh = st + 32768, bBl = st + 65536;
    int la7 = lane & 7;
#pragma unroll
    for (int kc = 0; kc < 4; kc++) {
        uint32_t ah[4][4], al[4][4];
        int chA = kc * 2 + (lane >> 4);
#pragma unroll
        for (int mi = 0; mi < 4; mi++) {
            int row = wm * 64 + mi * 16 + la7 + ((lane >> 3) & 1) * 8;
            uint32_t off = (uint32_t)row * 128 + (uint32_t)((chA ^ (row & 7)) << 4);
            ldsm_x4(ah[mi], bAh + off);
            ldsm_x4(al[mi], bAl + off);
        }
        int chB = kc * 2 + ((lane >> 3) & 1);
#pragma unroll
        for (int nhf = 0; nhf < 2; nhf++) {
            uint32_t bh[2][4], bl[2][4];
#pragma unroll
            for (int nh = 0; nh < 2; nh++) {
                int row = wn * 64 + (nhf * 2 + nh) * 16 + la7 + (lane >> 4) * 8;
                uint32_t off = (uint32_t)row * 128 + (uint32_t)((chB ^ (row & 7)) << 4);
                ldsm_x4(bh[nh], bBh + off);
                if (THREE) ldsm_x4(bl[nh], bBl + off);
            }
            // pass 1: Ah*Bh  (16 independent accumulators)
#pragma unroll
            for (int mi = 0; mi < 4; mi++)
#pragma unroll
                for (int nj = 0; nj < 4; nj++)
                    mma_f16(acc[mi][nhf * 4 + nj], ah[mi], &bh[nj >> 1][2 * (nj & 1)]);
            // pass 2: Al*Bh
#pragma unroll
            for (int mi = 0; mi < 4; mi++)
#pragma unroll
                for (int nj = 0; nj < 4; nj++)
                    mma_f16(acc[mi][nhf * 4 + nj], al[mi], &bh[nj >> 1][2 * (nj & 1)]);
            // pass 3: Ah*Bl (3-term only)
            if (THREE) {
#pragma unroll
                for (int mi = 0; mi < 4; mi++)
#pragma unroll
                    for (int nj = 0; nj < 4; nj++)
                        mma_f16(acc[mi][nhf * 4 + nj], ah[mi], &bl[nj >> 1][2 * (nj & 1)]);
            }
        }
    }
}

template <bool THREE, bool OUTF32>
__device__ __forceinline__ void mm_body(
    const __half* __restrict__ Ah, const __half* __restrict__ Al,
    const __half* __restrict__ Bh, const __half* __restrict__ Bl,
    float* __restrict__ C, const float* __restrict__ bias,
    __half* __restrict__ SH, __half* __restrict__ SL) {
    constexpr int STAGE = THREE ? 98304 : 65536;
    extern __shared__ char smem[];
    int tid = threadIdx.x, lane = tid & 31, wid = tid >> 5;
    int wm = wid >> 2, wn = wid & 3;
    int m0 = blockIdx.y * 128, n0 = blockIdx.x * 256;
    uint32_t sb = smem_u32(smem);

    const char* gsrc[4];
    gsrc[0] = (const char*)(Ah + (size_t)m0 * DIMM);
    gsrc[1] = (const char*)(Al + (size_t)m0 * DIMM);
    gsrc[2] = (const char*)(Bh + (size_t)n0 * DIMM);
    gsrc[3] = THREE ? (const char*)(Bl + (size_t)n0 * DIMM) : nullptr;

    float acc[4][8][4];
#pragma unroll
    for (int i = 0; i < 4; i++)
#pragma unroll
        for (int j = 0; j < 8; j++)
#pragma unroll
            for (int q = 0; q < 4; q++) acc[i][j][q] = 0.f;

    mm_fill<THREE>(sb, 0, 0, gsrc, tid);

    for (int kb = 0; kb < 16; kb++) {
        asm volatile("cp.async.wait_group 0;\n");
        __syncthreads();
        if (kb + 1 < 16) mm_fill<THREE>(sb, (kb + 1) & 1, kb + 1, gsrc, tid);
        mm_compute<THREE>(sb + (kb & 1) * STAGE, acc, wm, wn, lane);
    }

#pragma unroll
    for (int mi = 0; mi < 4; mi++) {
        int r0 = m0 + wm * 64 + mi * 16 + (lane >> 2);
#pragma unroll
        for (int ni = 0; ni < 8; ni++) {
            int c = n0 + wn * 64 + ni * 8 + (lane & 3) * 2;
            float2 v0 = make_float2(acc[mi][ni][0], acc[mi][ni][1]);
            float2 v1 = make_float2(acc[mi][ni][2], acc[mi][ni][3]);
            if (OUTF32) {
                float b0 = bias[c], b1 = bias[c + 1];
                v0.x += b0; v0.y += b1;
                v1.x += b0; v1.y += b1;
                *(float2*)(C + (size_t)r0 * DIMM + c) = v0;
                *(float2*)(C + (size_t)(r0 + 8) * DIMM + c) = v1;
            } else {
                uint32_t hh, ll;
                hsplit2(v0.x, v0.y, hh, ll);
                *(uint32_t*)(SH + (size_t)r0 * DIMM + c) = hh;
                *(uint32_t*)(SL + (size_t)r0 * DIMM + c) = ll;
                hsplit2(v1.x, v1.y, hh, ll);
                *(uint32_t*)(SH + (size_t)(r0 + 8) * DIMM + c) = hh;
                *(uint32_t*)(SL + (size_t)(r0 + 8) * DIMM + c) = ll;
            }
        }
    }
}

__global__ void __launch_bounds__(256, 1) mm_proj_kernel() {
    int which = blockIdx.z;
    if (which == 0)
        mm_body<true, false>(d_xh[0], d_xl[0], d_wih, d_wil, nullptr, nullptr, d_fqh, d_fql);
    else if (which == 1)
        mm_body<true, false>(d_xh[1], d_xl[1], d_wih, d_wil, nullptr, nullptr, d_fkh, d_fkl);
    else
        mm_body<true, false>(d_xh[2], d_xl[2], d_wih, d_wil, nullptr, nullptr, d_fvh, d_fvl);
}

__global__ void __launch_bounds__(256, 1) mm_out_kernel(const float* __restrict__ bias,
                                                        float* __restrict__ out) {
    mm_body<false, true>(d_oh, d_ol, d_woh, nullptr, out, bias, nullptr, nullptr);
}

// =====================================================================
//  merged per-(head,row) stats + centered-q hi + ikn-scaled v split
// =====================================================================
__global__ void statsprep_kernel() {
    int r = blockIdx.x;
    int tid = threadIdx.x;
    int w = tid >> 5, lane = tid & 31;
    size_t base = (size_t)r * DIMM + w * DD + lane * 4;

    // f_q: stats + centered hi
    float x0, x1, x2, x3;
    {
        uint2 uh = *(const uint2*)(d_fqh + base);
        uint2 ul = *(const uint2*)(d_fql + base);
        float2 a0 = __half22float2(*(__half2*)&uh.x), a1 = __half22float2(*(__half2*)&uh.y);
        float2 b0 = __half22float2(*(__half2*)&ul.x), b1 = __half22float2(*(__half2*)&ul.y);
        x0 = a0.x + b0.x; x1 = a0.y + b0.y; x2 = a1.x + b1.x; x3 = a1.y + b1.y;
        float s = warpsum(x0 + x1 + x2 + x3);
        float sq = warpsum(x0 * x0 + x1 * x1 + x2 * x2 + x3 * x3);
        float mean = s * (1.f / DD);
        float var = (sq - s * s * (1.f / DD)) * (1.f / (DD - 1));
        if (lane == 0) {
            d_iqn[w][r] = rsqrtf(sq);
            d_qmean[w][r] = mean;
            d_qr[w][r] = 2.f * fminf(var, 1.f) / (var + 1.f);
        }
        uint2 hv;
        hv.x = h2u(__floats2half2_rn(x0 - mean, x1 - mean));
        hv.y = h2u(__floats2half2_rn(x2 - mean, x3 - mean));
        *(uint2*)(d_qch + base) = hv;
    }
    // f_k: stats (ikn needed by all lanes for vt)
    float ikn;
    {
        uint2 uh = *(const uint2*)(d_fkh + base);
        uint2 ul = *(const uint2*)(d_fkl + base);
        float2 a0 = __half22float2(*(__half2*)&uh.x), a1 = __half22float2(*(__half2*)&uh.y);
        float2 b0 = __half22float2(*(__half2*)&ul.x), b1 = __half22float2(*(__half2*)&ul.y);
        float k0 = a0.x + b0.x, k1 = a0.y + b0.y, k2 = a1.x + b1.x, k3 = a1.y + b1.y;
        float s = warpsum(k0 + k1 + k2 + k3);
        float sq = warpsum(k0 * k0 + k1 * k1 + k2 * k2 + k3 * k3);
        ikn = rsqrtf(sq);
        float var = (sq - s * s * (1.f / DD)) * (1.f / (DD - 1));
        if (lane == 0) {
            d_ikn[w][r] = ikn;
            d_kr[w][r] = 2.f * fminf(var, 1.f) / (var + 1.f);
        }
    }
    // f_v -> vt = fv * ikn, split hi/lo
    {
        uint2 uh = *(const uint2*)(d_fvh + base);
        uint2 ul = *(const uint2*)(d_fvl + base);
        float2 a0 = __half22float2(*(__half2*)&uh.x), a1 = __half22float2(*(__half2*)&uh.y);
        float2 b0 = __half22float2(*(__half2*)&ul.x), b1 = __half22float2(*(__half2*)&ul.y);
        float v0 = (a0.x + b0.x) * ikn, v1 = (a0.y + b0.y) * ikn;
        float v2 = (a1.x + b1.x) * ikn, v3 = (a1.y + b1.y) * ikn;
        uint2 hv, lv;
        hsplit4(v0, v1, v2, v3, hv, lv);
        *(uint2*)(d_vth + base) = hv;
        *(uint2*)(d_vtl + base) = lv;
    }
}

// =====================================================================
//  A^T B kernel (3-term fp16): C[128x128] = sum_n A[n][d]*B[n][e]
//  pass-per-term ordering.
// =====================================================================
static constexpr int ATB_MAT = 64 * 272;       // 17408
static constexpr int ATB_STG = 4 * ATB_MAT;    // 69632
static constexpr int ATB_SMEM = 2 * ATB_STG;   // 139264

__device__ __forceinline__ void atb_fill(uint32_t sb, int s, int c,
        const __half* Ah, const __half* Al,
        const __half* Bh, const __half* Bl) {
    int tid = threadIdx.x;
    const __half* srcs[4] = {Ah, Al, Bh, Bl};
#pragma unroll
    for (int p = 0; p < 4; p++) {
        uint32_t base = sb + s * ATB_STG + p * ATB_MAT;
        const __half* src = srcs[p];
#pragma unroll
        for (int i = 0; i < 4; i++) {
            int id = tid + i * 256;
            int row = id >> 4, c16 = id & 15;
            cp16(base + row * 272 + c16 * 16,
                 src + (size_t)(c * 64 + row) * DIMM + c16 * 8);
        }
    }
    asm volatile("cp.async.commit_group;\n");
}

__device__ __forceinline__ void atb_compute(uint32_t sb, int s, float acc[4][4][4],
                                            int wm, int wn, int lane) {
    uint32_t bA  = sb + s * ATB_STG;
    uint32_t bAl = bA + ATB_MAT;
    uint32_t bB  = bA + 2 * ATB_MAT;
    uint32_t bBl = bA + 3 * ATB_MAT;
    int la7 = lane & 7;
    int arow = ((lane >> 4) << 3) + la7;
    int acol = (((lane >> 3) & 1) << 3);
    int brow = (((lane >> 3) & 1) << 3) + la7;
    int bcol = ((lane >> 4) << 3);
#pragma unroll
    for (int kc = 0; kc < 4; kc++) {
        uint32_t ah[4][4], al[4][4];
#pragma unroll
        for (int mi = 0; mi < 4; mi++) {
            uint32_t off = (uint32_t)(kc * 16 + arow) * 272 +
                           (uint32_t)(wm * 64 + mi * 16 + acol) * 2;
            ldsm_x4_t(ah[mi], bA + off);
            ldsm_x4_t(al[mi], bAl + off);
        }
        uint32_t bh[4][2], bl[4][2];
#pragma unroll
        for (int nh = 0; nh < 2; nh++) {
            uint32_t off = (uint32_t)(kc * 16 + brow) * 272 +
                           (uint32_t)(wn * 32 + nh * 16 + bcol) * 2;
            uint32_t r[4];
            ldsm_x4_t(r, bB + off);
            bh[2 * nh][0] = r[0]; bh[2 * nh][1] = r[1];
            bh[2 * nh + 1][0] = r[2]; bh[2 * nh + 1][1] = r[3];
            ldsm_x4_t(r, bBl + off);
            bl[2 * nh][0] = r[0]; bl[2 * nh][1] = r[1];
            bl[2 * nh + 1][0] = r[2]; bl[2 * nh + 1][1] = r[3];
        }
#pragma unroll
        for (int mi = 0; mi < 4; mi++)
#pragma unroll
            for (int ni = 0; ni < 4; ni++) mma_f16(acc[mi][ni], ah[mi], bh[ni]);
#pragma unroll
        for (int mi = 0; mi < 4; mi++)
#pragma unroll
            for (int ni = 0; ni < 4; ni++) mma_f16(acc[mi][ni], al[mi], bh[ni]);
#pragma unroll
        for (int mi = 0; mi < 4; mi++)
#pragma unroll
            for (int ni = 0; ni < 4; ni++) mma_f16(acc[mi][ni], ah[mi], bl[ni]);
    }
}

// kvm: M = f_k^T diag(ikn) f_v, writes fp16 hi/lo
__global__ void __launch_bounds__(256, 1) kvm_tc_kernel() {
    int blk = blockIdx.x;
    int h = blk >> 4, qi = blk & 15;
    size_t off = (size_t)(qi * NN) * DIMM + h * DD;
    extern __shared__ char smem[];
    uint32_t sb = smem_u32(smem);
    int tid = threadIdx.x, lane = tid & 31, wid = tid >> 5;
    int wm = wid >> 2, wn = wid & 3;
    float acc[4][4][4];
#pragma unroll
    for (int i = 0; i < 4; i++)
#pragma unroll
        for (int j = 0; j < 4; j++)
#pragma unroll
            for (int q = 0; q < 4; q++) acc[i][j][q] = 0.f;

    atb_fill(sb, 0, 0, d_fkh + off, d_fkl + off, d_vth + off, d_vtl + off);
    for (int c = 0; c < 8; c++) {
        asm volatile("cp.async.wait_group 0;\n");
        __syncthreads();
        if (c + 1 < 8)
            atb_fill(sb, (c + 1) & 1, c + 1, d_fkh + off, d_fkl + off, d_vth + off, d_vtl + off);
        atb_compute(sb, c & 1, acc, wm, wn, lane);
    }
    __half* Oh = d_Mh + (size_t)blk * DD * DD;
    __half* Ol = d_Ml + (size_t)blk * DD * DD;
#pragma unroll
    for (int mi = 0; mi < 4; mi++) {
        int d0 = wm * 64 + mi * 16 + (lane >> 2);
#pragma unroll
        for (int ni = 0; ni < 4; ni++) {
            int e = wn * 32 + ni * 8 + (lane & 3) * 2;
            uint32_t hh, ll;
            hsplit2(acc[mi][ni][0], acc[mi][ni][1], hh, ll);
            *(uint32_t*)(Oh + d0 * DD + e) = hh;
            *(uint32_t*)(Ol + d0 * DD + e) = ll;
            hsplit2(acc[mi][ni][2], acc[mi][ni][3], hh, ll);
            *(uint32_t*)(Oh + (d0 + 8) * DD + e) = hh;
            *(uint32_t*)(Ol + (d0 + 8) * DD + e) = ll;
        }
    }
}

// =====================================================================
//  gram (1-term, hi only): C = qc^T qc over 512-row chunk
// =====================================================================
static constexpr int G1_MAT = 64 * 272;        // 17408
static constexpr int G1_SMEM = 2 * G1_MAT;     // 34816

__global__ void __launch_bounds__(256, 1) gram1_kernel() {
    int ch = blockIdx.x, h = blockIdx.y;
    const __half* A = d_qch + (size_t)(ch * 512) * DIMM + h * DD;
    extern __shared__ char smem[];
    uint32_t sb = smem_u32(smem);
    int tid = threadIdx.x, lane = tid & 31, wid = tid >> 5;
    int wm = wid >> 2, wn = wid & 3;
    int la7 = lane & 7;
    float acc[4][4][4];
#pragma unroll
    for (int i = 0; i < 4; i++)
#pragma unroll
        for (int j = 0; j < 4; j++)
#pragma unroll
            for (int q = 0; q < 4; q++) acc[i][j][q] = 0.f;

    auto fill = [&](int s, int c) {
#pragma unroll
        for (int i = 0; i < 4; i++) {
            int id = tid + i * 256;
            int row = id >> 4, c16 = id & 15;
            cp16(sb + s * G1_MAT + row * 272 + c16 * 16,
                 A + (size_t)(c * 64 + row) * DIMM + c16 * 8);
        }
        asm volatile("cp.async.commit_group;\n");
    };

    fill(0, 0);
    int arow = ((lane >> 4) << 3) + la7;
    int acol = (((lane >> 3) & 1) << 3);
    int brow = (((lane >> 3) & 1) << 3) + la7;
    int bcol = ((lane >> 4) << 3);
    for (int c = 0; c < 8; c++) {
        asm volatile("cp.async.wait_group 0;\n");
        __syncthreads();
        if (c + 1 < 8) fill((c + 1) & 1, c + 1);
        uint32_t bA = sb + (c & 1) * G1_MAT;
#pragma unroll
        for (int kc = 0; kc < 4; kc++) {
            uint32_t ah[4][4];
#pragma unroll
            for (int mi = 0; mi < 4; mi++) {
                uint32_t off = (uint32_t)(kc * 16 + arow) * 272 +
                               (uint32_t)(wm * 64 + mi * 16 + acol) * 2;
                ldsm_x4_t(ah[mi], bA + off);
            }
            uint32_t bh[4][2];
#pragma unroll
            for (int nh = 0; nh < 2; nh++) {
                uint32_t off = (uint32_t)(kc * 16 + brow) * 272 +
                               (uint32_t)(wn * 32 + nh * 16 + bcol) * 2;
                uint32_t r[4];
                ldsm_x4_t(r, bA + off);
                bh[2 * nh][0] = r[0]; bh[2 * nh][1] = r[1];
                bh[2 * nh + 1][0] = r[2]; bh[2 * nh + 1][1] = r[3];
            }
#pragma unroll
            for (int mi = 0; mi < 4; mi++)
#pragma unroll
                for (int ni = 0; ni < 4; ni++) mma_f16(acc[mi][ni], ah[mi], bh[ni]);
        }
    }
    float* Cf = d_Cpart[h * GCH + ch];
#pragma unroll
    for (int mi = 0; mi < 4; mi++) {
        int d0 = wm * 64 + mi * 16 + (lane >> 2);
#pragma unroll
        for (int ni = 0; ni < 4; ni++) {
            int e = wn * 32 + ni * 8 + (lane & 3) * 2;
            *(float2*)(Cf + d0 * DD + e) = make_float2(acc[mi][ni][0], acc[mi][ni][1]);
            *(float2*)(Cf + (d0 + 8) * DD + e) = make_float2(acc[mi][ni][2], acc[mi][ni][3]);
        }
    }
}

// =====================================================================
//  attout: att[128x128] = f_q @ M (3-term), + rank-1 term -> oh/ol
// =====================================================================
static constexpr int AO_MAT = 128 * 272;       // 34816
static constexpr int AO_SMEM = 4 * AO_MAT;     // 139264

__global__ void __launch_bounds__(256, 1) attout_tc_kernel() {
    int blk = blockIdx.y, mt = blockIdx.x;
    int h = blk >> 4, qi = blk & 15;
    int r0g = qi * NN + mt * 128;
    int co = h * DD;
    extern __shared__ char smem[];
    uint32_t sb = smem_u32(smem);
    int tid = threadIdx.x, lane = tid & 31, wid = tid >> 5;
    int wm = wid >> 2, wn = wid & 3;
    int la7 = lane & 7;

    {
        const __half* Asrc[2] = {d_fqh, d_fql};
#pragma unroll
        for (int p = 0; p < 2; p++) {
            uint32_t base = sb + p * AO_MAT;
            const __half* src = Asrc[p] + (size_t)r0g * DIMM + co;
#pragma unroll
            for (int i = 0; i < 8; i++) {
                int id = tid + i * 256;
                int row = id >> 4, c16 = id & 15;
                cp16(base + row * 272 + c16 * 16, src + (size_t)row * DIMM + c16 * 8);
            }
        }
        const __half* Bsrc[2] = {d_Mh + (size_t)blk * DD * DD,
                                 d_Ml + (size_t)blk * DD * DD};
#pragma unroll
        for (int p = 0; p < 2; p++) {
            uint32_t base = sb + (2 + p) * AO_MAT;
            const __half* src = Bsrc[p];
#pragma unroll
            for (int i = 0; i < 8; i++) {
                int id = tid + i * 256;
                int row = id >> 4, c16 = id & 15;
                cp16(base + row * 272 + c16 * 16, src + row * DD + c16 * 8);
            }
        }
        asm volatile("cp.async.commit_group;\ncp.async.wait_group 0;\n");
        __syncthreads();
    }

    float acc[4][4][4];
#pragma unroll
    for (int i = 0; i < 4; i++)
#pragma unroll
        for (int j = 0; j < 4; j++)
#pragma unroll
            for (int q = 0; q < 4; q++) acc[i][j][q] = 0.f;

    uint32_t bA  = sb;
    uint32_t bAl = sb + AO_MAT;
    uint32_t bB  = sb + 2 * AO_MAT;
    uint32_t bBl = sb + 3 * AO_MAT;
    int brow = (((lane >> 3) & 1) << 3) + la7;
    int bcol = ((lane >> 4) << 3);
#pragma unroll
    for (int kc = 0; kc < 8; kc++) {
        uint32_t ah[4][4], al[4][4];
#pragma unroll
        for (int mi = 0; mi < 4; mi++) {
            uint32_t off = (uint32_t)(wm * 64 + mi * 16 + (lane & 15)) * 272 +
                           (uint32_t)(kc * 16 + ((lane >> 4) << 3)) * 2;
            ldsm_x4(ah[mi], bA + off);
            ldsm_x4(al[mi], bAl + off);
        }
        uint32_t bh[4][2], bl[4][2];
#pragma unroll
        for (int nh = 0; nh < 2; nh++) {
            uint32_t off = (uint32_t)(kc * 16 + brow) * 272 +
                           (uint32_t)(wn * 32 + nh * 16 + bcol) * 2;
            uint32_t r[4];
            ldsm_x4_t(r, bB + off);
            bh[2 * nh][0] = r[0]; bh[2 * nh][1] = r[1];
            bh[2 * nh + 1][0] = r[2]; bh[2 * nh + 1][1] = r[3];
            ldsm_x4_t(r, bBl + off);
            bl[2 * nh][0] = r[0]; bl[2 * nh][1] = r[1];
            bl[2 * nh + 1][0] = r[2]; bl[2 * nh + 1][1] = r[3];
        }
#pragma unroll
        for (int mi = 0; mi < 4; mi++)
#pragma unroll
            for (int ni = 0; ni < 4; ni++) mma_f16(acc[mi][ni], ah[mi], bh[ni]);
#pragma unroll
        for (int mi = 0; mi < 4; mi++)
#pragma unroll
            for (int ni = 0; ni < 4; ni++) mma_f16(acc[mi][ni], al[mi], bh[ni]);
#pragma unroll
        for (int mi = 0; mi < 4; mi++)
#pragma unroll
            for (int ni = 0; ni < 4; ni++) mma_f16(acc[mi][ni], ah[mi], bl[ni]);
    }

    float s1 = d_s1[h], ww = d_wws[h];
#pragma unroll
    for (int mi = 0; mi < 4; mi++) {
        int rA = r0g + wm * 64 + mi * 16 + (lane >> 2);
        int rB = rA + 8;
        float f1a = s1 * d_iqn[h][rA], f2a = ww * d_qr[h][rA];
        float f1b = s1 * d_iqn[h][rB], f2b = ww * d_qr[h][rB];
#pragma unroll
        for (int ni = 0; ni < 4; ni++) {
            int c = wn * 32 + ni * 8 + (lane & 3) * 2;
            float g0 = d_gv[blk][c], g1 = d_gv[blk][c + 1];
            float o0 = f1a * acc[mi][ni][0] + f2a * g0;
            float o1 = f1a * acc[mi][ni][1] + f2a * g1;
            float o2 = f1b * acc[mi][ni][2] + f2b * g0;
            float o3 = f1b * acc[mi][ni][3] + f2b * g1;
            uint32_t hh, ll;
            hsplit2(o0, o1, hh, ll);
            *(uint32_t*)(d_oh + (size_t)rA * DIMM + co + c) = hh;
            *(uint32_t*)(d_ol + (size_t)rA * DIMM + co + c) = ll;
            hsplit2(o2, o3, hh, ll);
            *(uint32_t*)(d_oh + (size_t)rB * DIMM + co + c) = hh;
            *(uint32_t*)(d_ol + (size_t)rB * DIMM + co + c) = ll;
        }
    }
}

// ---------------- gv: g[e] = sum_n kr[n] * f_v[n,e] ----------------
__global__ void gv_kernel() {
    int blk = blockIdx.x;
    int h = blk >> 4, qi = blk & 15;
    int r0 = qi * NN;
    int tid = threadIdx.x;
    int e = tid & 127, half = tid >> 7;
    __shared__ float kr[NN];
    __shared__ float part[2][DD];
    for (int i = tid; i < NN; i += 256) kr[i] = d_kr[h][r0 + i];
    __syncthreads();
    float a0 = 0.f, a1 = 0.f;
    int nb = half * 256;
    const __half* vh = d_fvh + (size_t)(r0 + nb) * DIMM + h * DD + e;
    const __half* vl = d_fvl + (size_t)(r0 + nb) * DIMM + h * DD + e;
#pragma unroll 2
    for (int n = 0; n < 256; n += 2) {
        a0 += kr[nb + n] * (__half2float(vh[(size_t)n * DIMM]) + __half2float(vl[(size_t)n * DIMM]));
        a1 += kr[nb + n + 1] * (__half2float(vh[(size_t)(n + 1) * DIMM]) + __half2float(vl[(size_t)(n + 1) * DIMM]));
    }
    part[half][e] = a0 + a1;
    __syncthreads();
    if (half == 0) d_gv[blk][e] = part[0][e] + part[1][e];
}

// ---------------- reduce gram partials: two stage ----------------
__global__ void creduce1_kernel() {
    int ch = blockIdx.x;
    int h = blockIdx.y;
    int tid = threadIdx.x;
    float ssum = 0.f;
#pragma unroll
    for (int u = 0; u < 4; u++) {
        int i = ch * 1024 + tid + u * 256;
        float c = 0.f;
#pragma unroll
        for (int p = 0; p < GCH; p++) c += d_Cpart[h * GCH + p][i];
        if ((i / DD) != (i % DD)) ssum += c * c;
    }
    __shared__ float sh[8];
    ssum = warpsum(ssum);
    int w = tid >> 5, lane = tid & 31;
    if (lane == 0) sh[w] = ssum;
    __syncthreads();
    if (tid == 0) {
        float S = 0.f;
#pragma unroll
        for (int i = 0; i < 8; i++) S += sh[i];
        d_cred[h][ch] = S;
    }
}
__global__ void creduce2_kernel() {
    int h = blockIdx.x;
    int lane = threadIdx.x;
    float s = (lane < 16) ? d_cred[h][lane] : 0.f;
    s = warpsum(s);
    if (lane == 0) {
        float fro = sqrtf(s) * (1.f / RTOT);
        float score = fro * (1.f / (128.f * 128.f));
        d_dscale[h] = expf(-5.f * score);
    }
}

// ---------------- global column-sum partials (hi only) ----------------
__global__ void gpart_kernel() {
    int b = blockIdx.x;
    int r0 = b * 32;
    int t = threadIdx.x;
    float2 sq0 = {0.f, 0.f}, sq1 = {0.f, 0.f};
    float2 sk0 = {0.f, 0.f}, sk1 = {0.f, 0.f};
    for (int row = 0; row < 32; row++) {
        const __half2* fq = (const __half2*)(d_fqh + (size_t)(r0 + row) * DIMM);
        const __half2* fk = (const __half2*)(d_fkh + (size_t)(r0 + row) * DIMM);
        float2 a = __half22float2(fq[t]);       sq0.x += a.x; sq0.y += a.y;
        float2 c = __half22float2(fq[t + 256]); sq1.x += c.x; sq1.y += c.y;
        float2 e = __half22float2(fk[t]);       sk0.x += e.x; sk0.y += e.y;
        float2 f = __half22float2(fk[t + 256]); sk1.x += f.x; sk1.y += f.y;
    }
    d_gpart[b][2 * t] = sq0.x;       d_gpart[b][2 * t + 1] = sq0.y;
    d_gpart[b][512 + 2 * t] = sq1.x; d_gpart[b][512 + 2 * t + 1] = sq1.y;
    d_gpart[b][DIMM + 2 * t] = sk0.x;       d_gpart[b][DIMM + 2 * t + 1] = sk0.y;
    d_gpart[b][DIMM + 512 + 2 * t] = sk1.x; d_gpart[b][DIMM + 512 + 2 * t + 1] = sk1.y;
}

// ---------------- weight-predictor MLP ----------------
__global__ void wp_kernel(const float* __restrict__ w1, const float* __restrict__ b1,
                          const float* __restrict__ lng, const float* __restrict__ lnb,
                          const float* __restrict__ w2, const float* __restrict__ b2) {
    __shared__ float qg[DIMM], kg[DIMM];
    __shared__ float h1[HH][DD];
    __shared__ float logits[HH][3];
    int tid = threadIdx.x;
    for (int i = tid; i < DIMM; i += 256) {
        float s = 0.f, s2 = 0.f;
        for (int b = 0; b < 256; b++) { s += d_gpart[b][i]; s2 += d_gpart[b][DIMM + i]; }
        qg[i] = s * (1.f / RTOT);
        kg[i] = s2 * (1.f / RTOT);
    }
    __syncthreads();
    for (int idx = tid; idx < HH * DD; idx += 256) {
        int h = idx / DD, i = idx % DD;
        float s = b1[i];
        const float* wr = w1 + i * 256;
#pragma unroll 4
        for (int j = 0; j < 128; j++) s += qg[h * 128 + j] * wr[j];
#pragma unroll 4
        for (int j = 0; j < 128; j++) s += kg[h * 128 + j] * wr[128 + j];
        h1[h][i] = s;
    }
    __syncthreads();
    int w = tid >> 5, lane = tid & 31;
    if (w < 8) {
        float s = 0.f, sq = 0.f;
        for (int i = lane; i < DD; i += 32) { float v = h1[w][i]; s += v; sq += v * v; }
        s = warpsum(s); sq = warpsum(sq);
        float mean = s * (1.f / DD);
        float var = sq * (1.f / DD) - mean * mean;
        float rs = rsqrtf(var + 1e-5f);
        for (int i = lane; i < DD; i += 32) {
            float vv = (h1[w][i] - mean) * rs * lng[i] + lnb[i];
            h1[w][i] = fmaxf(vv, 0.f);
        }
    }
    __syncthreads();
    if (tid < 24) {
        int h = tid / 3, c = tid % 3;
        float s = b2[c];
        const float* wr = w2 + c * DD;
        for (int i = 0; i < DD; i++) s += h1[h][i] * wr[i];
        logits[h][c] = s;
    }
    __syncthreads();
    if (tid < 8) {
        float a = logits[tid][0], b = logits[tid][1], c = logits[tid][2];
        float m = fmaxf(a, fmaxf(b, c));
        float ea = expf(a - m), eb = expf(b - m), ec = expf(c - m);
        float inv = 1.f / (ea + eb + ec);
        d_s1[tid] = ea * inv + eb * inv * d_dscale[tid];
        d_wws[tid] = ec * inv;
    }
}

// ---------------- launch ----------------
extern "C" void kernel_launch(void* const* d_in, const int* in_sizes, int n_in,
                              void* d_out, int out_size) {
    const float* q      = (const float*)d_in[0];
    const float* k      = (const float*)d_in[1];
    const float* v      = (const float*)d_in[2];
    const float* ln_g   = (const float*)d_in[3];
    const float* ln_b   = (const float*)d_in[4];
    const float* w_in   = (const float*)d_in[5];
    const float* wp_w1  = (const float*)d_in[6];
    const float* wp_b1  = (const float*)d_in[7];
    const float* wp_lng = (const float*)d_in[8];
    const float* wp_lnb = (const float*)d_in[9];
    const float* wp_w2  = (const float*)d_in[10];
    const float* wp_b2  = (const float*)d_in[11];
    const float* w_out  = (const float*)d_in[12];
    const float* b_out  = (const float*)d_in[13];
    float* out = (float*)d_out;

    cudaFuncSetAttribute(mm_proj_kernel, cudaFuncAttributeMaxDynamicSharedMemorySize, 2 * 98304);
    cudaFuncSetAttribute(mm_out_kernel, cudaFuncAttributeMaxDynamicSharedMemorySize, 2 * 65536);
    cudaFuncSetAttribute(kvm_tc_kernel, cudaFuncAttributeMaxDynamicSharedMemorySize, ATB_SMEM);
    cudaFuncSetAttribute(gram1_kernel, cudaFuncAttributeMaxDynamicSharedMemorySize, G1_SMEM);
    cudaFuncSetAttribute(attout_tc_kernel, cudaFuncAttributeMaxDynamicSharedMemorySize, AO_SMEM);

    lnconv_kernel<<<3 * RTOT, 256>>>(q, k, v, ln_g, ln_b);
    wconv_kernel<<<2 * DIMM, 256>>>(w_in, w_out);

    dim3 gproj(DIMM / 256, RTOT / 128, 3);   // (4, 64, 3)
    mm_proj_kernel<<<gproj, 256, 2 * 98304>>>();

    statsprep_kernel<<<RTOT, 256>>>();

    dim3 ggram(GCH, HH);
    gram1_kernel<<<ggram, 256, G1_SMEM>>>();
    dim3 gcr1(16, HH);
    creduce1_kernel<<<gcr1, 256>>>();
    creduce2_kernel<<<HH, 32>>>();

    gpart_kernel<<<256, 256>>>();
    wp_kernel<<<1, 256>>>(wp_w1, wp_b1, wp_lng, wp_lnb, wp_w2, wp_b2);

    kvm_tc_kernel<<<HH * QBB, 256, ATB_SMEM>>>();
    gv_kernel<<<HH * QBB, 256>>>();

    dim3 gatt(4, HH * QBB);
    attout_tc_kernel<<<gatt, 256, AO_SMEM>>>();

    dim3 gout(DIMM / 256, RTOT / 128);       // (4, 64)
    mm_out_kernel<<<gout, 256, 2 * 65536>>>(b_out, out);
}

// round 14
// speedup vs baseline: 3.1886x; 1.1272x over previous
#include <cuda_runtime.h>
#include <cuda_fp16.h>
#include <math.h>
#include <stdint.h>

// Problem constants
#define RTOT 8192     // QB*N tokens
#define DIMM 1024
#define HH 8
#define DD 128
#define NN 512
#define QBB 16
#define GCH 16        // gram split-K chunks (512 rows each)

// ---------------- static device scratch (no runtime allocation) ----------------
__device__ __half d_xh[3][RTOT * DIMM];   // LN(x) hi fp16 (q,k,v)
__device__ __half d_xl[3][RTOT * DIMM];   // LN(x) lo residual
__device__ __half d_oh[RTOT * DIMM];      // att output hi
__device__ __half d_ol[RTOT * DIMM];      // att output lo
__device__ __half d_wih[DIMM * DIMM];     // w_in hi (2-term GEMM)
__device__ __half d_woh[DIMM * DIMM];     // w_out hi (2-term GEMM)
__device__ __half d_fqh[RTOT * DIMM], d_fql[RTOT * DIMM];  // f_q split
__device__ __half d_fkh[RTOT * DIMM], d_fkl[RTOT * DIMM];  // f_k split
__device__ __half d_fvh[RTOT * DIMM], d_fvl[RTOT * DIMM];  // f_v split
__device__ __half d_qch[RTOT * DIMM];                      // q centered, hi only
__device__ __half d_vth[RTOT * DIMM], d_vtl[RTOT * DIMM];  // ikn-scaled v split
__device__ __half d_Mh[HH * QBB * DD * DD], d_Ml[HH * QBB * DD * DD];
__device__ float d_iqn[HH][RTOT];
__device__ float d_ikn[HH][RTOT];
__device__ float d_qr[HH][RTOT];
__device__ float d_kr[HH][RTOT];
__device__ float d_qmean[HH][RTOT];
__device__ float d_Cpart[HH * GCH][DD * DD];
__device__ float d_cred[HH][16];
__device__ float d_dscale[HH];
__device__ float d_gpart[256][2 * DIMM];
__device__ float d_s1[HH];
__device__ float d_wws[HH];
__device__ float d_gv[HH * QBB][DD];

__device__ __forceinline__ float warpsum(float v) {
#pragma unroll
    for (int o = 16; o; o >>= 1) v += __shfl_xor_sync(0xffffffffu, v, o);
    return v;
}

__device__ __forceinline__ uint32_t smem_u32(const void* p) {
    uint32_t a;
    asm("{ .reg .u64 t; cvta.to.shared.u64 t, %1; cvt.u32.u64 %0, t; }" : "=r"(a) : "l"(p));
    return a;
}
__device__ __forceinline__ uint32_t h2u(__half2 v) { return *reinterpret_cast<uint32_t*>(&v); }

// split fp32 -> fp16 hi (rn) + fp16 lo (rn residual): 22-bit pair
__device__ __forceinline__ void hsplit2(float x0, float x1, uint32_t& h, uint32_t& l) {
    __half2 hh = __floats2half2_rn(x0, x1);
    float2 f = __half22float2(hh);
    __half2 ll = __floats2half2_rn(x0 - f.x, x1 - f.y);
    h = h2u(hh); l = h2u(ll);
}
__device__ __forceinline__ void hsplit4(float x0, float x1, float x2, float x3,
                                        uint2& h, uint2& l) {
    hsplit2(x0, x1, h.x, l.x);
    hsplit2(x2, x3, h.y, l.y);
}

__device__ __forceinline__ void cp16(uint32_t dst, const void* src) {
    asm volatile("cp.async.cg.shared.global [%0], [%1], 16;\n" :: "r"(dst), "l"(src));
}
__device__ __forceinline__ void ldsm_x4(uint32_t* r, uint32_t a) {
    asm volatile("ldmatrix.sync.aligned.m8n8.x4.shared.b16 {%0,%1,%2,%3}, [%4];\n"
                 : "=r"(r[0]), "=r"(r[1]), "=r"(r[2]), "=r"(r[3]) : "r"(a));
}
__device__ __forceinline__ void ldsm_x4_t(uint32_t* r, uint32_t a) {
    asm volatile("ldmatrix.sync.aligned.m8n8.x4.trans.shared.b16 {%0,%1,%2,%3}, [%4];\n"
                 : "=r"(r[0]), "=r"(r[1]), "=r"(r[2]), "=r"(r[3]) : "r"(a));
}
__device__ __forceinline__ void mma_f16(float* d, const uint32_t* a, const uint32_t* b) {
    asm volatile(
        "mma.sync.aligned.m16n8k16.row.col.f32.f16.f16.f32 "
        "{%0,%1,%2,%3}, {%4,%5,%6,%7}, {%8,%9}, {%0,%1,%2,%3};\n"
        : "+f"(d[0]), "+f"(d[1]), "+f"(d[2]), "+f"(d[3])
        : "r"(a[0]), "r"(a[1]), "r"(a[2]), "r"(a[3]), "r"(b[0]), "r"(b[1]));
}

// ---------------- fused rowstats + LayerNorm + fp16 split ----------------
__global__ void lnconv_kernel(const float* __restrict__ q, const float* __restrict__ k,
                              const float* __restrict__ v,
                              const float* __restrict__ lng, const float* __restrict__ lnb) {
    int idx = blockIdx.x;
    int t = idx >> 13;
    int r = idx & (RTOT - 1);
    const float* A = (t == 0) ? q : (t == 1) ? k : v;
    int tid = threadIdx.x;
    float4 x = ((const float4*)(A + (size_t)r * DIMM))[tid];
    float s = x.x + x.y + x.z + x.w;
    float sq = x.x * x.x + x.y * x.y + x.z * x.z + x.w * x.w;
    __shared__ float sh[16];
    __shared__ float smu, srs;
    s = warpsum(s); sq = warpsum(sq);
    int w = tid >> 5, lane = tid & 31;
    if (lane == 0) { sh[w] = s; sh[8 + w] = sq; }
    __syncthreads();
    if (tid == 0) {
        float S = 0.f, SQ = 0.f;
#pragma unroll
        for (int i = 0; i < 8; i++) { S += sh[i]; SQ += sh[8 + i]; }
        float mu = S * (1.f / DIMM);
        float var = SQ * (1.f / DIMM) - mu * mu;
        smu = mu;
        srs = rsqrtf(var + 1e-5f);
    }
    __syncthreads();
    float mu = smu, rs = srs;
    float4 g = ((const float4*)lng)[tid];
    float4 b = ((const float4*)lnb)[tid];
    float y0 = (x.x - mu) * rs * g.x + b.x;
    float y1 = (x.y - mu) * rs * g.y + b.y;
    float y2 = (x.z - mu) * rs * g.z + b.z;
    float y3 = (x.w - mu) * rs * g.w + b.w;
    uint2 hv, lv;
    hsplit4(y0, y1, y2, y3, hv, lv);
    ((uint2*)(d_xh[t] + (size_t)r * DIMM))[tid] = hv;
    ((uint2*)(d_xl[t] + (size_t)r * DIMM))[tid] = lv;
}

// ---------------- weight convert: hi only for w_in and w_out ----------------
__global__ void wconv_kernel(const float* __restrict__ w_in, const float* __restrict__ w_out) {
    int row = blockIdx.x;
    int tid = threadIdx.x;
    const float* src = (row < DIMM) ? w_in + (size_t)row * DIMM
                                    : w_out + (size_t)(row - DIMM) * DIMM;
    __half* H = (row < DIMM) ? d_wih + (size_t)row * DIMM
                             : d_woh + (size_t)(row - DIMM) * DIMM;
    float4 x = ((const float4*)src)[tid];
    uint2 hv;
    hv.x = h2u(__floats2half2_rn(x.x, x.y));
    hv.y = h2u(__floats2half2_rn(x.z, x.w));
    ((uint2*)H)[tid] = hv;
}

// =====================================================================
//  big GEMM: C[8192x1024] = A @ B^T, fp16x2 (Ah,Al vs Bh).
//  CTA tile 128x256, K-blocks of 64, 3-stage cp.async pipeline.
//  Stage: Ah 16KB | Al 16KB | Bh 32KB = 64KB, 3 stages = 192KB.
//  Pass-per-term MMA ordering (16-acc reuse distance).
// =====================================================================
static constexpr int MM_STAGE = 65536;
static constexpr int MM_SMEM = 3 * MM_STAGE;   // 196608

__device__ __forceinline__ void mm_fill(uint32_t sb, int s, int kb,
                                        const char* const* gsrc, int tid) {
    uint32_t st = sb + s * MM_STAGE;
#pragma unroll
    for (int p = 0; p < 2; p++) {       // A hi/lo: 128 rows x 128B
        uint32_t base = st + p * 16384;
        const char* src = gsrc[p] + kb * 128;
#pragma unroll
        for (int i = 0; i < 4; i++) {
            int id = tid + i * 256;
            int row = id >> 3, c = id & 7;
            uint32_t sw = (uint32_t)((c ^ (row & 7)) << 4);
            cp16(base + row * 128 + sw, src + (size_t)row * 2048 + c * 16);
        }
    }
    {                                    // B hi: 256 rows x 128B
        uint32_t base = st + 32768;
        const char* src = gsrc[2] + kb * 128;
#pragma unroll
        for (int i = 0; i < 8; i++) {
            int id = tid + i * 256;
            int row = id >> 3, c = id & 7;
            uint32_t sw = (uint32_t)((c ^ (row & 7)) << 4);
            cp16(base + row * 128 + sw, src + (size_t)row * 2048 + c * 16);
        }
    }
    asm volatile("cp.async.commit_group;\n");
}

__device__ __forceinline__ void mm_compute(uint32_t st, float acc[4][8][4],
                                           int wm, int wn, int lane) {
    uint32_t bAh = st, bAl = st + 16384, bBh = st + 32768;
    int la7 = lane & 7;
#pragma unroll
    for (int kc = 0; kc < 4; kc++) {
        uint32_t ah[4][4], al[4][4];
        int chA = kc * 2 + (lane >> 4);
#pragma unroll
        for (int mi = 0; mi < 4; mi++) {
            int row = wm * 64 + mi * 16 + la7 + ((lane >> 3) & 1) * 8;
            uint32_t off = (uint32_t)row * 128 + (uint32_t)((chA ^ (row & 7)) << 4);
            ldsm_x4(ah[mi], bAh + off);
            ldsm_x4(al[mi], bAl + off);
        }
        int chB = kc * 2 + ((lane >> 3) & 1);
#pragma unroll
        for (int nhf = 0; nhf < 2; nhf++) {
            uint32_t bh[2][4];
#pragma unroll
            for (int nh = 0; nh < 2; nh++) {
                int row = wn * 64 + (nhf * 2 + nh) * 16 + la7 + (lane >> 4) * 8;
                uint32_t off = (uint32_t)row * 128 + (uint32_t)((chB ^ (row & 7)) << 4);
                ldsm_x4(bh[nh], bBh + off);
            }
            // pass 1: Ah*Bh  (16 independent accumulators)
#pragma unroll
            for (int mi = 0; mi < 4; mi++)
#pragma unroll
                for (int nj = 0; nj < 4; nj++)
                    mma_f16(acc[mi][nhf * 4 + nj], ah[mi], &bh[nj >> 1][2 * (nj & 1)]);
            // pass 2: Al*Bh
#pragma unroll
            for (int mi = 0; mi < 4; mi++)
#pragma unroll
                for (int nj = 0; nj < 4; nj++)
                    mma_f16(acc[mi][nhf * 4 + nj], al[mi], &bh[nj >> 1][2 * (nj & 1)]);
        }
    }
}

template <bool OUTF32>
__device__ __forceinline__ void mm_body(
    const __half* __restrict__ Ah, const __half* __restrict__ Al,
    const __half* __restrict__ Bh,
    float* __restrict__ C, const float* __restrict__ bias,
    __half* __restrict__ SH, __half* __restrict__ SL) {
    extern __shared__ char smem[];
    int tid = threadIdx.x, lane = tid & 31, wid = tid >> 5;
    int wm = wid >> 2, wn = wid & 3;
    int m0 = blockIdx.y * 128, n0 = blockIdx.x * 256;
    uint32_t sb = smem_u32(smem);

    const char* gsrc[3];
    gsrc[0] = (const char*)(Ah + (size_t)m0 * DIMM);
    gsrc[1] = (const char*)(Al + (size_t)m0 * DIMM);
    gsrc[2] = (const char*)(Bh + (size_t)n0 * DIMM);

    float acc[4][8][4];
#pragma unroll
    for (int i = 0; i < 4; i++)
#pragma unroll
        for (int j = 0; j < 8; j++)
#pragma unroll
            for (int q = 0; q < 4; q++) acc[i][j][q] = 0.f;

    mm_fill(sb, 0, 0, gsrc, tid);
    mm_fill(sb, 1, 1, gsrc, tid);

    for (int kb = 0; kb < 16; kb++) {
        if (kb < 15) asm volatile("cp.async.wait_group 1;\n");
        else         asm volatile("cp.async.wait_group 0;\n");
        __syncthreads();
        if (kb + 2 < 16) mm_fill(sb, (kb + 2) % 3, kb + 2, gsrc, tid);
        mm_compute(sb + (kb % 3) * MM_STAGE, acc, wm, wn, lane);
    }

#pragma unroll
    for (int mi = 0; mi < 4; mi++) {
        int r0 = m0 + wm * 64 + mi * 16 + (lane >> 2);
#pragma unroll
        for (int ni = 0; ni < 8; ni++) {
            int c = n0 + wn * 64 + ni * 8 + (lane & 3) * 2;
            float2 v0 = make_float2(acc[mi][ni][0], acc[mi][ni][1]);
            float2 v1 = make_float2(acc[mi][ni][2], acc[mi][ni][3]);
            if (OUTF32) {
                float b0 = bias[c], b1 = bias[c + 1];
                v0.x += b0; v0.y += b1;
                v1.x += b0; v1.y += b1;
                *(float2*)(C + (size_t)r0 * DIMM + c) = v0;
                *(float2*)(C + (size_t)(r0 + 8) * DIMM + c) = v1;
            } else {
                uint32_t hh, ll;
                hsplit2(v0.x, v0.y, hh, ll);
                *(uint32_t*)(SH + (size_t)r0 * DIMM + c) = hh;
                *(uint32_t*)(SL + (size_t)r0 * DIMM + c) = ll;
                hsplit2(v1.x, v1.y, hh, ll);
                *(uint32_t*)(SH + (size_t)(r0 + 8) * DIMM + c) = hh;
                *(uint32_t*)(SL + (size_t)(r0 + 8) * DIMM + c) = ll;
            }
        }
    }
}

__global__ void __launch_bounds__(256, 1) mm_proj_kernel() {
    int which = blockIdx.z;
    if (which == 0)
        mm_body<false>(d_xh[0], d_xl[0], d_wih, nullptr, nullptr, d_fqh, d_fql);
    else if (which == 1)
        mm_body<false>(d_xh[1], d_xl[1], d_wih, nullptr, nullptr, d_fkh, d_fkl);
    else
        mm_body<false>(d_xh[2], d_xl[2], d_wih, nullptr, nullptr, d_fvh, d_fvl);
}

__global__ void __launch_bounds__(256, 1) mm_out_kernel(const float* __restrict__ bias,
                                                        float* __restrict__ out) {
    mm_body<true>(d_oh, d_ol, d_woh, out, bias, nullptr, nullptr);
}

// =====================================================================
//  merged per-(head,row) stats + centered-q hi + ikn-scaled v split
// =====================================================================
__global__ void statsprep_kernel() {
    int r = blockIdx.x;
    int tid = threadIdx.x;
    int w = tid >> 5, lane = tid & 31;
    size_t base = (size_t)r * DIMM + w * DD + lane * 4;

    // f_q: stats + centered hi
    float x0, x1, x2, x3;
    {
        uint2 uh = *(const uint2*)(d_fqh + base);
        uint2 ul = *(const uint2*)(d_fql + base);
        float2 a0 = __half22float2(*(__half2*)&uh.x), a1 = __half22float2(*(__half2*)&uh.y);
        float2 b0 = __half22float2(*(__half2*)&ul.x), b1 = __half22float2(*(__half2*)&ul.y);
        x0 = a0.x + b0.x; x1 = a0.y + b0.y; x2 = a1.x + b1.x; x3 = a1.y + b1.y;
        float s = warpsum(x0 + x1 + x2 + x3);
        float sq = warpsum(x0 * x0 + x1 * x1 + x2 * x2 + x3 * x3);
        float mean = s * (1.f / DD);
        float var = (sq - s * s * (1.f / DD)) * (1.f / (DD - 1));
        if (lane == 0) {
            d_iqn[w][r] = rsqrtf(sq);
            d_qmean[w][r] = mean;
            d_qr[w][r] = 2.f * fminf(var, 1.f) / (var + 1.f);
        }
        uint2 hv;
        hv.x = h2u(__floats2half2_rn(x0 - mean, x1 - mean));
        hv.y = h2u(__floats2half2_rn(x2 - mean, x3 - mean));
        *(uint2*)(d_qch + base) = hv;
    }
    // f_k: stats (ikn needed by all lanes for vt)
    float ikn;
    {
        uint2 uh = *(const uint2*)(d_fkh + base);
        uint2 ul = *(const uint2*)(d_fkl + base);
        float2 a0 = __half22float2(*(__half2*)&uh.x), a1 = __half22float2(*(__half2*)&uh.y);
        float2 b0 = __half22float2(*(__half2*)&ul.x), b1 = __half22float2(*(__half2*)&ul.y);
        float k0 = a0.x + b0.x, k1 = a0.y + b0.y, k2 = a1.x + b1.x, k3 = a1.y + b1.y;
        float s = warpsum(k0 + k1 + k2 + k3);
        float sq = warpsum(k0 * k0 + k1 * k1 + k2 * k2 + k3 * k3);
        ikn = rsqrtf(sq);
        float var = (sq - s * s * (1.f / DD)) * (1.f / (DD - 1));
        if (lane == 0) {
            d_ikn[w][r] = ikn;
            d_kr[w][r] = 2.f * fminf(var, 1.f) / (var + 1.f);
        }
    }
    // f_v -> vt = fv * ikn, split hi/lo
    {
        uint2 uh = *(const uint2*)(d_fvh + base);
        uint2 ul = *(const uint2*)(d_fvl + base);
        float2 a0 = __half22float2(*(__half2*)&uh.x), a1 = __half22float2(*(__half2*)&uh.y);
        float2 b0 = __half22float2(*(__half2*)&ul.x), b1 = __half22float2(*(__half2*)&ul.y);
        float v0 = (a0.x + b0.x) * ikn, v1 = (a0.y + b0.y) * ikn;
        float v2 = (a1.x + b1.x) * ikn, v3 = (a1.y + b1.y) * ikn;
        uint2 hv, lv;
        hsplit4(v0, v1, v2, v3, hv, lv);
        *(uint2*)(d_vth + base) = hv;
        *(uint2*)(d_vtl + base) = lv;
    }
}

// =====================================================================
//  A^T B kernel (3-term fp16): C[128x128] = sum_n A[n][d]*B[n][e]
// =====================================================================
static constexpr int ATB_MAT = 64 * 272;       // 17408
static constexpr int ATB_STG = 4 * ATB_MAT;    // 69632
static constexpr int ATB_SMEM = 2 * ATB_STG;   // 139264

__device__ __forceinline__ void atb_fill(uint32_t sb, int s, int c,
        const __half* Ah, const __half* Al,
        const __half* Bh, const __half* Bl) {
    int tid = threadIdx.x;
    const __half* srcs[4] = {Ah, Al, Bh, Bl};
#pragma unroll
    for (int p = 0; p < 4; p++) {
        uint32_t base = sb + s * ATB_STG + p * ATB_MAT;
        const __half* src = srcs[p];
#pragma unroll
        for (int i = 0; i < 4; i++) {
            int id = tid + i * 256;
            int row = id >> 4, c16 = id & 15;
            cp16(base + row * 272 + c16 * 16,
                 src + (size_t)(c * 64 + row) * DIMM + c16 * 8);
        }
    }
    asm volatile("cp.async.commit_group;\n");
}

__device__ __forceinline__ void atb_compute(uint32_t sb, int s, float acc[4][4][4],
                                            int wm, int wn, int lane) {
    uint32_t bA  = sb + s * ATB_STG;
    uint32_t bAl = bA + ATB_MAT;
    uint32_t bB  = bA + 2 * ATB_MAT;
    uint32_t bBl = bA + 3 * ATB_MAT;
    int la7 = lane & 7;
    int arow = ((lane >> 4) << 3) + la7;
    int acol = (((lane >> 3) & 1) << 3);
    int brow = (((lane >> 3) & 1) << 3) + la7;
    int bcol = ((lane >> 4) << 3);
#pragma unroll
    for (int kc = 0; kc < 4; kc++) {
        uint32_t ah[4][4], al[4][4];
#pragma unroll
        for (int mi = 0; mi < 4; mi++) {
            uint32_t off = (uint32_t)(kc * 16 + arow) * 272 +
                           (uint32_t)(wm * 64 + mi * 16 + acol) * 2;
            ldsm_x4_t(ah[mi], bA + off);
            ldsm_x4_t(al[mi], bAl + off);
        }
        uint32_t bh[4][2], bl[4][2];
#pragma unroll
        for (int nh = 0; nh < 2; nh++) {
            uint32_t off = (uint32_t)(kc * 16 + brow) * 272 +
                           (uint32_t)(wn * 32 + nh * 16 + bcol) * 2;
            uint32_t r[4];
            ldsm_x4_t(r, bB + off);
            bh[2 * nh][0] = r[0]; bh[2 * nh][1] = r[1];
            bh[2 * nh + 1][0] = r[2]; bh[2 * nh + 1][1] = r[3];
            ldsm_x4_t(r, bBl + off);
            bl[2 * nh][0] = r[0]; bl[2 * nh][1] = r[1];
            bl[2 * nh + 1][0] = r[2]; bl[2 * nh + 1][1] = r[3];
        }
#pragma unroll
        for (int mi = 0; mi < 4; mi++)
#pragma unroll
            for (int ni = 0; ni < 4; ni++) mma_f16(acc[mi][ni], ah[mi], bh[ni]);
#pragma unroll
        for (int mi = 0; mi < 4; mi++)
#pragma unroll
            for (int ni = 0; ni < 4; ni++) mma_f16(acc[mi][ni], al[mi], bh[ni]);
#pragma unroll
        for (int mi = 0; mi < 4; mi++)
#pragma unroll
            for (int ni = 0; ni < 4; ni++) mma_f16(acc[mi][ni], ah[mi], bl[ni]);
    }
}

// kvm: M = f_k^T diag(ikn) f_v, writes fp16 hi/lo
__global__ void __launch_bounds__(256, 1) kvm_tc_kernel() {
    int blk = blockIdx.x;
    int h = blk >> 4, qi = blk & 15;
    size_t off = (size_t)(qi * NN) * DIMM + h * DD;
    extern __shared__ char smem[];
    uint32_t sb = smem_u32(smem);
    int tid = threadIdx.x, lane = tid & 31, wid = tid >> 5;
    int wm = wid >> 2, wn = wid & 3;
    float acc[4][4][4];
#pragma unroll
    for (int i = 0; i < 4; i++)
#pragma unroll
        for (int j = 0; j < 4; j++)
#pragma unroll
            for (int q = 0; q < 4; q++) acc[i][j][q] = 0.f;

    atb_fill(sb, 0, 0, d_fkh + off, d_fkl + off, d_vth + off, d_vtl + off);
    for (int c = 0; c < 8; c++) {
        asm volatile("cp.async.wait_group 0;\n");
        __syncthreads();
        if (c + 1 < 8)
            atb_fill(sb, (c + 1) & 1, c + 1, d_fkh + off, d_fkl + off, d_vth + off, d_vtl + off);
        atb_compute(sb, c & 1, acc, wm, wn, lane);
    }
    __half* Oh = d_Mh + (size_t)blk * DD * DD;
    __half* Ol = d_Ml + (size_t)blk * DD * DD;
#pragma unroll
    for (int mi = 0; mi < 4; mi++) {
        int d0 = wm * 64 + mi * 16 + (lane >> 2);
#pragma unroll
        for (int ni = 0; ni < 4; ni++) {
            int e = wn * 32 + ni * 8 + (lane & 3) * 2;
            uint32_t hh, ll;
            hsplit2(acc[mi][ni][0], acc[mi][ni][1], hh, ll);
            *(uint32_t*)(Oh + d0 * DD + e) = hh;
            *(uint32_t*)(Ol + d0 * DD + e) = ll;
            hsplit2(acc[mi][ni][2], acc[mi][ni][3], hh, ll);
            *(uint32_t*)(Oh + (d0 + 8) * DD + e) = hh;
            *(uint32_t*)(Ol + (d0 + 8) * DD + e) = ll;
        }
    }
}

// =====================================================================
//  gram (1-term, hi only): C = qc^T qc over 512-row chunk
// =====================================================================
static constexpr int G1_MAT = 64 * 272;        // 17408
static constexpr int G1_SMEM = 2 * G1_MAT;     // 34816

__global__ void __launch_bounds__(256, 1) gram1_kernel() {
    int ch = blockIdx.x, h = blockIdx.y;
    const __half* A = d_qch + (size_t)(ch * 512) * DIMM + h * DD;
    extern __shared__ char smem[];
    uint32_t sb = smem_u32(smem);
    int tid = threadIdx.x, lane = tid & 31, wid = tid >> 5;
    int wm = wid >> 2, wn = wid & 3;
    int la7 = lane & 7;
    float acc[4][4][4];
#pragma unroll
    for (int i = 0; i < 4; i++)
#pragma unroll
        for (int j = 0; j < 4; j++)
#pragma unroll
            for (int q = 0; q < 4; q++) acc[i][j][q] = 0.f;

    auto fill = [&](int s, int c) {
#pragma unroll
        for (int i = 0; i < 4; i++) {
            int id = tid + i * 256;
            int row = id >> 4, c16 = id & 15;
            cp16(sb + s * G1_MAT + row * 272 + c16 * 16,
                 A + (size_t)(c * 64 + row) * DIMM + c16 * 8);
        }
        asm volatile("cp.async.commit_group;\n");
    };

    fill(0, 0);
    int arow = ((lane >> 4) << 3) + la7;
    int acol = (((lane >> 3) & 1) << 3);
    int brow = (((lane >> 3) & 1) << 3) + la7;
    int bcol = ((lane >> 4) << 3);
    for (int c = 0; c < 8; c++) {
        asm volatile("cp.async.wait_group 0;\n");
        __syncthreads();
        if (c + 1 < 8) fill((c + 1) & 1, c + 1);
        uint32_t bA = sb + (c & 1) * G1_MAT;
#pragma unroll
        for (int kc = 0; kc < 4; kc++) {
            uint32_t ah[4][4];
#pragma unroll
            for (int mi = 0; mi < 4; mi++) {
                uint32_t off = (uint32_t)(kc * 16 + arow) * 272 +
                               (uint32_t)(wm * 64 + mi * 16 + acol) * 2;
                ldsm_x4_t(ah[mi], bA + off);
            }
            uint32_t bh[4][2];
#pragma unroll
            for (int nh = 0; nh < 2; nh++) {
                uint32_t off = (uint32_t)(kc * 16 + brow) * 272 +
                               (uint32_t)(wn * 32 + nh * 16 + bcol) * 2;
                uint32_t r[4];
                ldsm_x4_t(r, bA + off);
                bh[2 * nh][0] = r[0]; bh[2 * nh][1] = r[1];
                bh[2 * nh + 1][0] = r[2]; bh[2 * nh + 1][1] = r[3];
            }
#pragma unroll
            for (int mi = 0; mi < 4; mi++)
#pragma unroll
                for (int ni = 0; ni < 4; ni++) mma_f16(acc[mi][ni], ah[mi], bh[ni]);
        }
    }
    float* Cf = d_Cpart[h * GCH + ch];
#pragma unroll
    for (int mi = 0; mi < 4; mi++) {
        int d0 = wm * 64 + mi * 16 + (lane >> 2);
#pragma unroll
        for (int ni = 0; ni < 4; ni++) {
            int e = wn * 32 + ni * 8 + (lane & 3) * 2;
            *(float2*)(Cf + d0 * DD + e) = make_float2(acc[mi][ni][0], acc[mi][ni][1]);
            *(float2*)(Cf + (d0 + 8) * DD + e) = make_float2(acc[mi][ni][2], acc[mi][ni][3]);
        }
    }
}

// =====================================================================
//  attout: att[128x128] = f_q @ M (3-term), + rank-1 term -> oh/ol
// =====================================================================
static constexpr int AO_MAT = 128 * 272;       // 34816
static constexpr int AO_SMEM = 4 * AO_MAT;     // 139264

__global__ void __launch_bounds__(256, 1) attout_tc_kernel() {
    int blk = blockIdx.y, mt = blockIdx.x;
    int h = blk >> 4, qi = blk & 15;
    int r0g = qi * NN + mt * 128;
    int co = h * DD;
    extern __shared__ char smem[];
    uint32_t sb = smem_u32(smem);
    int tid = threadIdx.x, lane = tid & 31, wid = tid >> 5;
    int wm = wid >> 2, wn = wid & 3;
    int la7 = lane & 7;

    {
        const __half* Asrc[2] = {d_fqh, d_fql};
#pragma unroll
        for (int p = 0; p < 2; p++) {
            uint32_t base = sb + p * AO_MAT;
            const __half* src = Asrc[p] + (size_t)r0g * DIMM + co;
#pragma unroll
            for (int i = 0; i < 8; i++) {
                int id = tid + i * 256;
                int row = id >> 4, c16 = id & 15;
                cp16(base + row * 272 + c16 * 16, src + (size_t)row * DIMM + c16 * 8);
            }
        }
        const __half* Bsrc[2] = {d_Mh + (size_t)blk * DD * DD,
                                 d_Ml + (size_t)blk * DD * DD};
#pragma unroll
        for (int p = 0; p < 2; p++) {
            uint32_t base = sb + (2 + p) * AO_MAT;
            const __half* src = Bsrc[p];
#pragma unroll
            for (int i = 0; i < 8; i++) {
                int id = tid + i * 256;
                int row = id >> 4, c16 = id & 15;
                cp16(base + row * 272 + c16 * 16, src + row * DD + c16 * 8);
            }
        }
        asm volatile("cp.async.commit_group;\ncp.async.wait_group 0;\n");
        __syncthreads();
    }

    float acc[4][4][4];
#pragma unroll
    for (int i = 0; i < 4; i++)
#pragma unroll
        for (int j = 0; j < 4; j++)
#pragma unroll
            for (int q = 0; q < 4; q++) acc[i][j][q] = 0.f;

    uint32_t bA  = sb;
    uint32_t bAl = sb + AO_MAT;
    uint32_t bB  = sb + 2 * AO_MAT;
    uint32_t bBl = sb + 3 * AO_MAT;
    int brow = (((lane >> 3) & 1) << 3) + la7;
    int bcol = ((lane >> 4) << 3);
#pragma unroll
    for (int kc = 0; kc < 8; kc++) {
        uint32_t ah[4][4], al[4][4];
#pragma unroll
        for (int mi = 0; mi < 4; mi++) {
            uint32_t off = (uint32_t)(wm * 64 + mi * 16 + (lane & 15)) * 272 +
                           (uint32_t)(kc * 16 + ((lane >> 4) << 3)) * 2;
            ldsm_x4(ah[mi], bA + off);
            ldsm_x4(al[mi], bAl + off);
        }
        uint32_t bh[4][2], bl[4][2];
#pragma unroll
        for (int nh = 0; nh < 2; nh++) {
            uint32_t off = (uint32_t)(kc * 16 + brow) * 272 +
                           (uint32_t)(wn * 32 + nh * 16 + bcol) * 2;
            uint32_t r[4];
            ldsm_x4_t(r, bB + off);
            bh[2 * nh][0] = r[0]; bh[2 * nh][1] = r[1];
            bh[2 * nh + 1][0] = r[2]; bh[2 * nh + 1][1] = r[3];
            ldsm_x4_t(r, bBl + off);
            bl[2 * nh][0] = r[0]; bl[2 * nh][1] = r[1];
            bl[2 * nh + 1][0] = r[2]; bl[2 * nh + 1][1] = r[3];
        }
#pragma unroll
        for (int mi = 0; mi < 4; mi++)
#pragma unroll
            for (int ni = 0; ni < 4; ni++) mma_f16(acc[mi][ni], ah[mi], bh[ni]);
#pragma unroll
        for (int mi = 0; mi < 4; mi++)
#pragma unroll
            for (int ni = 0; ni < 4; ni++) mma_f16(acc[mi][ni], al[mi], bh[ni]);
#pragma unroll
        for (int mi = 0; mi < 4; mi++)
#pragma unroll
            for (int ni = 0; ni < 4; ni++) mma_f16(acc[mi][ni], ah[mi], bl[ni]);
    }

    float s1 = d_s1[h], ww = d_wws[h];
#pragma unroll
    for (int mi = 0; mi < 4; mi++) {
        int rA = r0g + wm * 64 + mi * 16 + (lane >> 2);
        int rB = rA + 8;
        float f1a = s1 * d_iqn[h][rA], f2a = ww * d_qr[h][rA];
        float f1b = s1 * d_iqn[h][rB], f2b = ww * d_qr[h][rB];
#pragma unroll
        for (int ni = 0; ni < 4; ni++) {
            int c = wn * 32 + ni * 8 + (lane & 3) * 2;
            float g0 = d_gv[blk][c], g1 = d_gv[blk][c + 1];
            float o0 = f1a * acc[mi][ni][0] + f2a * g0;
            float o1 = f1a * acc[mi][ni][1] + f2a * g1;
            float o2 = f1b * acc[mi][ni][2] + f2b * g0;
            float o3 = f1b * acc[mi][ni][3] + f2b * g1;
            uint32_t hh, ll;
            hsplit2(o0, o1, hh, ll);
            *(uint32_t*)(d_oh + (size_t)rA * DIMM + co + c) = hh;
            *(uint32_t*)(d_ol + (size_t)rA * DIMM + co + c) = ll;
            hsplit2(o2, o3, hh, ll);
            *(uint32_t*)(d_oh + (size_t)rB * DIMM + co + c) = hh;
            *(uint32_t*)(d_ol + (size_t)rB * DIMM + co + c) = ll;
        }
    }
}

// ---------------- gv: g[e] = sum_n kr[n] * f_v[n,e] ----------------
__global__ void gv_kernel() {
    int blk = blockIdx.x;
    int h = blk >> 4, qi = blk & 15;
    int r0 = qi * NN;
    int tid = threadIdx.x;
    int e = tid & 127, half = tid >> 7;
    __shared__ float kr[NN];
    __shared__ float part[2][DD];
    for (int i = tid; i < NN; i += 256) kr[i] = d_kr[h][r0 + i];
    __syncthreads();
    float a0 = 0.f, a1 = 0.f;
    int nb = half * 256;
    const __half* vh = d_fvh + (size_t)(r0 + nb) * DIMM + h * DD + e;
    const __half* vl = d_fvl + (size_t)(r0 + nb) * DIMM + h * DD + e;
#pragma unroll 2
    for (int n = 0; n < 256; n += 2) {
        a0 += kr[nb + n] * (__half2float(vh[(size_t)n * DIMM]) + __half2float(vl[(size_t)n * DIMM]));
        a1 += kr[nb + n + 1] * (__half2float(vh[(size_t)(n + 1) * DIMM]) + __half2float(vl[(size_t)(n + 1) * DIMM]));
    }
    part[half][e] = a0 + a1;
    __syncthreads();
    if (half == 0) d_gv[blk][e] = part[0][e] + part[1][e];
}

// ---------------- reduce gram partials: two stage ----------------
__global__ void creduce1_kernel() {
    int ch = blockIdx.x;
    int h = blockIdx.y;
    int tid = threadIdx.x;
    float ssum = 0.f;
#pragma unroll
    for (int u = 0; u < 4; u++) {
        int i = ch * 1024 + tid + u * 256;
        float c = 0.f;
#pragma unroll
        for (int p = 0; p < GCH; p++) c += d_Cpart[h * GCH + p][i];
        if ((i / DD) != (i % DD)) ssum += c * c;
    }
    __shared__ float sh[8];
    ssum = warpsum(ssum);
    int w = tid >> 5, lane = tid & 31;
    if (lane == 0) sh[w] = ssum;
    __syncthreads();
    if (tid == 0) {
        float S = 0.f;
#pragma unroll
        for (int i = 0; i < 8; i++) S += sh[i];
        d_cred[h][ch] = S;
    }
}
__global__ void creduce2_kernel() {
    int h = blockIdx.x;
    int lane = threadIdx.x;
    float s = (lane < 16) ? d_cred[h][lane] : 0.f;
    s = warpsum(s);
    if (lane == 0) {
        float fro = sqrtf(s) * (1.f / RTOT);
        float score = fro * (1.f / (128.f * 128.f));
        d_dscale[h] = expf(-5.f * score);
    }
}

// ---------------- global column-sum partials (hi only) ----------------
__global__ void gpart_kernel() {
    int b = blockIdx.x;
    int r0 = b * 32;
    int t = threadIdx.x;
    float2 sq0 = {0.f, 0.f}, sq1 = {0.f, 0.f};
    float2 sk0 = {0.f, 0.f}, sk1 = {0.f, 0.f};
    for (int row = 0; row < 32; row++) {
        const __half2* fq = (const __half2*)(d_fqh + (size_t)(r0 + row) * DIMM);
        const __half2* fk = (const __half2*)(d_fkh + (size_t)(r0 + row) * DIMM);
        float2 a = __half22float2(fq[t]);       sq0.x += a.x; sq0.y += a.y;
        float2 c = __half22float2(fq[t + 256]); sq1.x += c.x; sq1.y += c.y;
        float2 e = __half22float2(fk[t]);       sk0.x += e.x; sk0.y += e.y;
        float2 f = __half22float2(fk[t + 256]); sk1.x += f.x; sk1.y += f.y;
    }
    d_gpart[b][2 * t] = sq0.x;       d_gpart[b][2 * t + 1] = sq0.y;
    d_gpart[b][512 + 2 * t] = sq1.x; d_gpart[b][512 + 2 * t + 1] = sq1.y;
    d_gpart[b][DIMM + 2 * t] = sk0.x;       d_gpart[b][DIMM + 2 * t + 1] = sk0.y;
    d_gpart[b][DIMM + 512 + 2 * t] = sk1.x; d_gpart[b][DIMM + 512 + 2 * t + 1] = sk1.y;
}

// ---------------- weight-predictor MLP ----------------
__global__ void wp_kernel(const float* __restrict__ w1, const float* __restrict__ b1,
                          const float* __restrict__ lng, const float* __restrict__ lnb,
                          const float* __restrict__ w2, const float* __restrict__ b2) {
    __shared__ float qg[DIMM], kg[DIMM];
    __shared__ float h1[HH][DD];
    __shared__ float logits[HH][3];
    int tid = threadIdx.x;
    for (int i = tid; i < DIMM; i += 256) {
        float s = 0.f, s2 = 0.f;
        for (int b = 0; b < 256; b++) { s += d_gpart[b][i]; s2 += d_gpart[b][DIMM + i]; }
        qg[i] = s * (1.f / RTOT);
        kg[i] = s2 * (1.f / RTOT);
    }
    __syncthreads();
    for (int idx = tid; idx < HH * DD; idx += 256) {
        int h = idx / DD, i = idx % DD;
        float s = b1[i];
        const float* wr = w1 + i * 256;
#pragma unroll 4
        for (int j = 0; j < 128; j++) s += qg[h * 128 + j] * wr[j];
#pragma unroll 4
        for (int j = 0; j < 128; j++) s += kg[h * 128 + j] * wr[128 + j];
        h1[h][i] = s;
    }
    __syncthreads();
    int w = tid >> 5, lane = tid & 31;
    if (w < 8) {
        float s = 0.f, sq = 0.f;
        for (int i = lane; i < DD; i += 32) { float v = h1[w][i]; s += v; sq += v * v; }
        s = warpsum(s); sq = warpsum(sq);
        float mean = s * (1.f / DD);
        float var = sq * (1.f / DD) - mean * mean;
        float rs = rsqrtf(var + 1e-5f);
        for (int i = lane; i < DD; i += 32) {
            float vv = (h1[w][i] - mean) * rs * lng[i] + lnb[i];
            h1[w][i] = fmaxf(vv, 0.f);
        }
    }
    __syncthreads();
    if (tid < 24) {
        int h = tid / 3, c = tid % 3;
        float s = b2[c];
        const float* wr = w2 + c * DD;
        for (int i = 0; i < DD; i++) s += h1[h][i] * wr[i];
        logits[h][c] = s;
    }
    __syncthreads();
    if (tid < 8) {
        float a = logits[tid][0], b = logits[tid][1], c = logits[tid][2];
        float m = fmaxf(a, fmaxf(b, c));
        float ea = expf(a - m), eb = expf(b - m), ec = expf(c - m);
        float inv = 1.f / (ea + eb + ec);
        d_s1[tid] = ea * inv + eb * inv * d_dscale[tid];
        d_wws[tid] = ec * inv;
    }
}

// ---------------- launch ----------------
extern "C" void kernel_launch(void* const* d_in, const int* in_sizes, int n_in,
                              void* d_out, int out_size) {
    const float* q      = (const float*)d_in[0];
    const float* k      = (const float*)d_in[1];
    const float* v      = (const float*)d_in[2];
    const float* ln_g   = (const float*)d_in[3];
    const float* ln_b   = (const float*)d_in[4];
    const float* w_in   = (const float*)d_in[5];
    const float* wp_w1  = (const float*)d_in[6];
    const float* wp_b1  = (const float*)d_in[7];
    const float* wp_lng = (const float*)d_in[8];
    const float* wp_lnb = (const float*)d_in[9];
    const float* wp_w2  = (const float*)d_in[10];
    const float* wp_b2  = (const float*)d_in[11];
    const float* w_out  = (const float*)d_in[12];
    const float* b_out  = (const float*)d_in[13];
    float* out = (float*)d_out;

    cudaFuncSetAttribute(mm_proj_kernel, cudaFuncAttributeMaxDynamicSharedMemorySize, MM_SMEM);
    cudaFuncSetAttribute(mm_out_kernel, cudaFuncAttributeMaxDynamicSharedMemorySize, MM_SMEM);
    cudaFuncSetAttribute(kvm_tc_kernel, cudaFuncAttributeMaxDynamicSharedMemorySize, ATB_SMEM);
    cudaFuncSetAttribute(gram1_kernel, cudaFuncAttributeMaxDynamicSharedMemorySize, G1_SMEM);
    cudaFuncSetAttribute(attout_tc_kernel, cudaFuncAttributeMaxDynamicSharedMemorySize, AO_SMEM);

    lnconv_kernel<<<3 * RTOT, 256>>>(q, k, v, ln_g, ln_b);
    wconv_kernel<<<2 * DIMM, 256>>>(w_in, w_out);

    dim3 gproj(DIMM / 256, RTOT / 128, 3);   // (4, 64, 3)
    mm_proj_kernel<<<gproj, 256, MM_SMEM>>>();

    statsprep_kernel<<<RTOT, 256>>>();

    dim3 ggram(GCH, HH);
    gram1_kernel<<<ggram, 256, G1_SMEM>>>();
    dim3 gcr1(16, HH);
    creduce1_kernel<<<gcr1, 256>>>();
    creduce2_kernel<<<HH, 32>>>();

    gpart_kernel<<<256, 256>>>();
    wp_kernel<<<1, 256>>>(wp_w1, wp_b1, wp_lng, wp_lnb, wp_w2, wp_b2);

    kvm_tc_kernel<<<HH * QBB, 256, ATB_SMEM>>>();
    gv_kernel<<<HH * QBB, 256>>>();

    dim3 gatt(4, HH * QBB);
    attout_tc_kernel<<<gatt, 256, AO_SMEM>>>();

    dim3 gout(DIMM / 256, RTOT / 128);       // (4, 64)
    mm_out_kernel<<<gout, 256, MM_SMEM>>>(b_out, out);
}

// round 15
// speedup vs baseline: 3.2789x; 1.0283x over previous
#include <cuda_runtime.h>
#include <cuda_fp16.h>
#include <math.h>
#include <stdint.h>

// Problem constants
#define RTOT 8192     // QB*N tokens
#define DIMM 1024
#define HH 8
#define DD 128
#define NN 512
#define QBB 16
#define GCH 16        // gram split-K chunks (512 rows each)

// ---------------- static device scratch (no runtime allocation) ----------------
__device__ __half d_xh[3][RTOT * DIMM];   // LN(x) hi fp16 (q,k,v)
__device__ __half d_xl[3][RTOT * DIMM];   // LN(x) lo residual
__device__ __half d_oh[RTOT * DIMM];      // att output hi
__device__ __half d_ol[RTOT * DIMM];      // att output lo
__device__ __half d_wih[DIMM * DIMM];     // w_in hi (2-term GEMM)
__device__ __half d_woh[DIMM * DIMM];     // w_out hi (2-term GEMM)
__device__ __half d_fqh[RTOT * DIMM], d_fql[RTOT * DIMM];  // f_q split
__device__ __half d_fkh[RTOT * DIMM], d_fkl[RTOT * DIMM];  // f_k split
__device__ __half d_fvh[RTOT * DIMM], d_fvl[RTOT * DIMM];  // f_v split
__device__ __half d_qch[RTOT * DIMM];                      // q centered, hi only
__device__ __half d_vth[RTOT * DIMM], d_vtl[RTOT * DIMM];  // ikn-scaled v split
__device__ __half d_Mh[HH * QBB * DD * DD], d_Ml[HH * QBB * DD * DD];
__device__ float d_iqn[HH][RTOT];
__device__ float d_ikn[HH][RTOT];
__device__ float d_qr[HH][RTOT];
__device__ float d_kr[HH][RTOT];
__device__ float d_Cpart[HH * GCH][DD * DD];
__device__ float d_cred[HH][16];
__device__ float d_gpart[256][2 * DIMM];
__device__ float d_s1[HH];
__device__ float d_wws[HH];
__device__ float d_gv[HH * QBB][DD];

__device__ __forceinline__ float warpsum(float v) {
#pragma unroll
    for (int o = 16; o; o >>= 1) v += __shfl_xor_sync(0xffffffffu, v, o);
    return v;
}

__device__ __forceinline__ uint32_t smem_u32(const void* p) {
    uint32_t a;
    asm("{ .reg .u64 t; cvta.to.shared.u64 t, %1; cvt.u32.u64 %0, t; }" : "=r"(a) : "l"(p));
    return a;
}
__device__ __forceinline__ uint32_t h2u(__half2 v) { return *reinterpret_cast<uint32_t*>(&v); }

// split fp32 -> fp16 hi (rn) + fp16 lo (rn residual): 22-bit pair
__device__ __forceinline__ void hsplit2(float x0, float x1, uint32_t& h, uint32_t& l) {
    __half2 hh = __floats2half2_rn(x0, x1);
    float2 f = __half22float2(hh);
    __half2 ll = __floats2half2_rn(x0 - f.x, x1 - f.y);
    h = h2u(hh); l = h2u(ll);
}
__device__ __forceinline__ void hsplit4(float x0, float x1, float x2, float x3,
                                        uint2& h, uint2& l) {
    hsplit2(x0, x1, h.x, l.x);
    hsplit2(x2, x3, h.y, l.y);
}

__device__ __forceinline__ void cp16(uint32_t dst, const void* src) {
    asm volatile("cp.async.cg.shared.global [%0], [%1], 16;\n" :: "r"(dst), "l"(src));
}
__device__ __forceinline__ void ldsm_x4(uint32_t* r, uint32_t a) {
    asm volatile("ldmatrix.sync.aligned.m8n8.x4.shared.b16 {%0,%1,%2,%3}, [%4];\n"
                 : "=r"(r[0]), "=r"(r[1]), "=r"(r[2]), "=r"(r[3]) : "r"(a));
}
__device__ __forceinline__ void ldsm_x4_t(uint32_t* r, uint32_t a) {
    asm volatile("ldmatrix.sync.aligned.m8n8.x4.trans.shared.b16 {%0,%1,%2,%3}, [%4];\n"
                 : "=r"(r[0]), "=r"(r[1]), "=r"(r[2]), "=r"(r[3]) : "r"(a));
}
__device__ __forceinline__ void mma_f16(float* d, const uint32_t* a, const uint32_t* b) {
    asm volatile(
        "mma.sync.aligned.m16n8k16.row.col.f32.f16.f16.f32 "
        "{%0,%1,%2,%3}, {%4,%5,%6,%7}, {%8,%9}, {%0,%1,%2,%3};\n"
        : "+f"(d[0]), "+f"(d[1]), "+f"(d[2]), "+f"(d[3])
        : "r"(a[0]), "r"(a[1]), "r"(a[2]), "r"(a[3]), "r"(b[0]), "r"(b[1]));
}

// ---------------- fused: rowstats+LN+split (blocks 0..24575) | weight conv (24576..26623) ----------------
__global__ void lnwconv_kernel(const float* __restrict__ q, const float* __restrict__ k,
                               const float* __restrict__ v,
                               const float* __restrict__ lng, const float* __restrict__ lnb,
                               const float* __restrict__ w_in, const float* __restrict__ w_out) {
    int idx = blockIdx.x;
    int tid = threadIdx.x;
    if (idx >= 3 * RTOT) {
        int row = idx - 3 * RTOT;   // 0..2047
        const float* src = (row < DIMM) ? w_in + (size_t)row * DIMM
                                        : w_out + (size_t)(row - DIMM) * DIMM;
        __half* H = (row < DIMM) ? d_wih + (size_t)row * DIMM
                                 : d_woh + (size_t)(row - DIMM) * DIMM;
        float4 x = ((const float4*)src)[tid];
        uint2 hv;
        hv.x = h2u(__floats2half2_rn(x.x, x.y));
        hv.y = h2u(__floats2half2_rn(x.z, x.w));
        ((uint2*)H)[tid] = hv;
        return;
    }
    int t = idx >> 13;
    int r = idx & (RTOT - 1);
    const float* A = (t == 0) ? q : (t == 1) ? k : v;
    float4 x = ((const float4*)(A + (size_t)r * DIMM))[tid];
    float s = x.x + x.y + x.z + x.w;
    float sq = x.x * x.x + x.y * x.y + x.z * x.z + x.w * x.w;
    __shared__ float sh[16];
    __shared__ float smu, srs;
    s = warpsum(s); sq = warpsum(sq);
    int w = tid >> 5, lane = tid & 31;
    if (lane == 0) { sh[w] = s; sh[8 + w] = sq; }
    __syncthreads();
    if (tid == 0) {
        float S = 0.f, SQ = 0.f;
#pragma unroll
        for (int i = 0; i < 8; i++) { S += sh[i]; SQ += sh[8 + i]; }
        float mu = S * (1.f / DIMM);
        float var = SQ * (1.f / DIMM) - mu * mu;
        smu = mu;
        srs = rsqrtf(var + 1e-5f);
    }
    __syncthreads();
    float mu = smu, rs = srs;
    float4 g = ((const float4*)lng)[tid];
    float4 b = ((const float4*)lnb)[tid];
    float y0 = (x.x - mu) * rs * g.x + b.x;
    float y1 = (x.y - mu) * rs * g.y + b.y;
    float y2 = (x.z - mu) * rs * g.z + b.z;
    float y3 = (x.w - mu) * rs * g.w + b.w;
    uint2 hv, lv;
    hsplit4(y0, y1, y2, y3, hv, lv);
    ((uint2*)(d_xh[t] + (size_t)r * DIMM))[tid] = hv;
    ((uint2*)(d_xl[t] + (size_t)r * DIMM))[tid] = lv;
}

// =====================================================================
//  big GEMM: C[8192x1024] = A @ B^T, fp16x2 (Ah,Al vs Bh).
//  CTA tile 128x256, K-blocks of 64, 3-stage cp.async pipeline.
// =====================================================================
static constexpr int MM_STAGE = 65536;
static constexpr int MM_SMEM = 3 * MM_STAGE;   // 196608

__device__ __forceinline__ void mm_fill(uint32_t sb, int s, int kb,
                                        const char* const* gsrc, int tid) {
    uint32_t st = sb + s * MM_STAGE;
#pragma unroll
    for (int p = 0; p < 2; p++) {       // A hi/lo: 128 rows x 128B
        uint32_t base = st + p * 16384;
        const char* src = gsrc[p] + kb * 128;
#pragma unroll
        for (int i = 0; i < 4; i++) {
            int id = tid + i * 256;
            int row = id >> 3, c = id & 7;
            uint32_t sw = (uint32_t)((c ^ (row & 7)) << 4);
            cp16(base + row * 128 + sw, src + (size_t)row * 2048 + c * 16);
        }
    }
    {                                    // B hi: 256 rows x 128B
        uint32_t base = st + 32768;
        const char* src = gsrc[2] + kb * 128;
#pragma unroll
        for (int i = 0; i < 8; i++) {
            int id = tid + i * 256;
            int row = id >> 3, c = id & 7;
            uint32_t sw = (uint32_t)((c ^ (row & 7)) << 4);
            cp16(base + row * 128 + sw, src + (size_t)row * 2048 + c * 16);
        }
    }
    asm volatile("cp.async.commit_group;\n");
}

__device__ __forceinline__ void mm_compute(uint32_t st, float acc[4][8][4],
                                           int wm, int wn, int lane) {
    uint32_t bAh = st, bAl = st + 16384, bBh = st + 32768;
    int la7 = lane & 7;
#pragma unroll
    for (int kc = 0; kc < 4; kc++) {
        uint32_t ah[4][4], al[4][4];
        int chA = kc * 2 + (lane >> 4);
#pragma unroll
        for (int mi = 0; mi < 4; mi++) {
            int row = wm * 64 + mi * 16 + la7 + ((lane >> 3) & 1) * 8;
            uint32_t off = (uint32_t)row * 128 + (uint32_t)((chA ^ (row & 7)) << 4);
            ldsm_x4(ah[mi], bAh + off);
            ldsm_x4(al[mi], bAl + off);
        }
        int chB = kc * 2 + ((lane >> 3) & 1);
#pragma unroll
        for (int nhf = 0; nhf < 2; nhf++) {
            uint32_t bh[2][4];
#pragma unroll
            for (int nh = 0; nh < 2; nh++) {
                int row = wn * 64 + (nhf * 2 + nh) * 16 + la7 + (lane >> 4) * 8;
                uint32_t off = (uint32_t)row * 128 + (uint32_t)((chB ^ (row & 7)) << 4);
                ldsm_x4(bh[nh], bBh + off);
            }
#pragma unroll
            for (int mi = 0; mi < 4; mi++)
#pragma unroll
                for (int nj = 0; nj < 4; nj++)
                    mma_f16(acc[mi][nhf * 4 + nj], ah[mi], &bh[nj >> 1][2 * (nj & 1)]);
#pragma unroll
            for (int mi = 0; mi < 4; mi++)
#pragma unroll
                for (int nj = 0; nj < 4; nj++)
                    mma_f16(acc[mi][nhf * 4 + nj], al[mi], &bh[nj >> 1][2 * (nj & 1)]);
        }
    }
}

template <bool OUTF32>
__device__ __forceinline__ void mm_body(
    const __half* __restrict__ Ah, const __half* __restrict__ Al,
    const __half* __restrict__ Bh,
    float* __restrict__ C, const float* __restrict__ bias,
    __half* __restrict__ SH, __half* __restrict__ SL) {
    extern __shared__ char smem[];
    int tid = threadIdx.x, lane = tid & 31, wid = tid >> 5;
    int wm = wid >> 2, wn = wid & 3;
    int m0 = blockIdx.y * 128, n0 = blockIdx.x * 256;
    uint32_t sb = smem_u32(smem);

    const char* gsrc[3];
    gsrc[0] = (const char*)(Ah + (size_t)m0 * DIMM);
    gsrc[1] = (const char*)(Al + (size_t)m0 * DIMM);
    gsrc[2] = (const char*)(Bh + (size_t)n0 * DIMM);

    float acc[4][8][4];
#pragma unroll
    for (int i = 0; i < 4; i++)
#pragma unroll
        for (int j = 0; j < 8; j++)
#pragma unroll
            for (int q = 0; q < 4; q++) acc[i][j][q] = 0.f;

    mm_fill(sb, 0, 0, gsrc, tid);
    mm_fill(sb, 1, 1, gsrc, tid);

    for (int kb = 0; kb < 16; kb++) {
        if (kb < 15) asm volatile("cp.async.wait_group 1;\n");
        else         asm volatile("cp.async.wait_group 0;\n");
        __syncthreads();
        if (kb + 2 < 16) mm_fill(sb, (kb + 2) % 3, kb + 2, gsrc, tid);
        mm_compute(sb + (kb % 3) * MM_STAGE, acc, wm, wn, lane);
    }

#pragma unroll
    for (int mi = 0; mi < 4; mi++) {
        int r0 = m0 + wm * 64 + mi * 16 + (lane >> 2);
#pragma unroll
        for (int ni = 0; ni < 8; ni++) {
            int c = n0 + wn * 64 + ni * 8 + (lane & 3) * 2;
            float2 v0 = make_float2(acc[mi][ni][0], acc[mi][ni][1]);
            float2 v1 = make_float2(acc[mi][ni][2], acc[mi][ni][3]);
            if (OUTF32) {
                float b0 = bias[c], b1 = bias[c + 1];
                v0.x += b0; v0.y += b1;
                v1.x += b0; v1.y += b1;
                *(float2*)(C + (size_t)r0 * DIMM + c) = v0;
                *(float2*)(C + (size_t)(r0 + 8) * DIMM + c) = v1;
            } else {
                uint32_t hh, ll;
                hsplit2(v0.x, v0.y, hh, ll);
                *(uint32_t*)(SH + (size_t)r0 * DIMM + c) = hh;
                *(uint32_t*)(SL + (size_t)r0 * DIMM + c) = ll;
                hsplit2(v1.x, v1.y, hh, ll);
                *(uint32_t*)(SH + (size_t)(r0 + 8) * DIMM + c) = hh;
                *(uint32_t*)(SL + (size_t)(r0 + 8) * DIMM + c) = ll;
            }
        }
    }
}

__global__ void __launch_bounds__(256, 1) mm_proj_kernel() {
    int which = blockIdx.z;
    if (which == 0)
        mm_body<false>(d_xh[0], d_xl[0], d_wih, nullptr, nullptr, d_fqh, d_fql);
    else if (which == 1)
        mm_body<false>(d_xh[1], d_xl[1], d_wih, nullptr, nullptr, d_fkh, d_fkl);
    else
        mm_body<false>(d_xh[2], d_xl[2], d_wih, nullptr, nullptr, d_fvh, d_fvl);
}

__global__ void __launch_bounds__(256, 1) mm_out_kernel(const float* __restrict__ bias,
                                                        float* __restrict__ out) {
    mm_body<true>(d_oh, d_ol, d_woh, out, bias, nullptr, nullptr);
}

// =====================================================================
//  merged per-(head,row) stats (hi-only) + centered-q hi + ikn-scaled v split
// =====================================================================
__global__ void statsprep_kernel() {
    int r = blockIdx.x;
    int tid = threadIdx.x;
    int w = tid >> 5, lane = tid & 31;
    size_t base = (size_t)r * DIMM + w * DD + lane * 4;

    // f_q: stats from hi + centered hi
    {
        uint2 uh = *(const uint2*)(d_fqh + base);
        float2 a0 = __half22float2(*(__half2*)&uh.x), a1 = __half22float2(*(__half2*)&uh.y);
        float x0 = a0.x, x1 = a0.y, x2 = a1.x, x3 = a1.y;
        float s = warpsum(x0 + x1 + x2 + x3);
        float sq = warpsum(x0 * x0 + x1 * x1 + x2 * x2 + x3 * x3);
        float mean = s * (1.f / DD);
        float var = (sq - s * s * (1.f / DD)) * (1.f / (DD - 1));
        if (lane == 0) {
            d_iqn[w][r] = rsqrtf(sq);
            d_qr[w][r] = 2.f * fminf(var, 1.f) / (var + 1.f);
        }
        uint2 hv;
        hv.x = h2u(__floats2half2_rn(x0 - mean, x1 - mean));
        hv.y = h2u(__floats2half2_rn(x2 - mean, x3 - mean));
        *(uint2*)(d_qch + base) = hv;
    }
    // f_k: stats from hi (ikn broadcast to all lanes)
    float ikn;
    {
        uint2 uh = *(const uint2*)(d_fkh + base);
        float2 a0 = __half22float2(*(__half2*)&uh.x), a1 = __half22float2(*(__half2*)&uh.y);
        float k0 = a0.x, k1 = a0.y, k2 = a1.x, k3 = a1.y;
        float s = warpsum(k0 + k1 + k2 + k3);
        float sq = warpsum(k0 * k0 + k1 * k1 + k2 * k2 + k3 * k3);
        ikn = rsqrtf(sq);
        float var = (sq - s * s * (1.f / DD)) * (1.f / (DD - 1));
        if (lane == 0) {
            d_ikn[w][r] = ikn;
            d_kr[w][r] = 2.f * fminf(var, 1.f) / (var + 1.f);
        }
    }
    // f_v -> vt = fv * ikn, split hi/lo (full precision source)
    {
        uint2 uh = *(const uint2*)(d_fvh + base);
        uint2 ul = *(const uint2*)(d_fvl + base);
        float2 a0 = __half22float2(*(__half2*)&uh.x), a1 = __half22float2(*(__half2*)&uh.y);
        float2 b0 = __half22float2(*(__half2*)&ul.x), b1 = __half22float2(*(__half2*)&ul.y);
        float v0 = (a0.x + b0.x) * ikn, v1 = (a0.y + b0.y) * ikn;
        float v2 = (a1.x + b1.x) * ikn, v3 = (a1.y + b1.y) * ikn;
        uint2 hv, lv;
        hsplit4(v0, v1, v2, v3, hv, lv);
        *(uint2*)(d_vth + base) = hv;
        *(uint2*)(d_vtl + base) = lv;
    }
}

// =====================================================================
//  mid_kernel bodies: kvm (tc), gram1 (tc), gpart (mem), gv (mem)
// =====================================================================
static constexpr int ATB_MAT = 64 * 272;       // 17408
static constexpr int ATB_STG = 4 * ATB_MAT;    // 69632
static constexpr int MID_SMEM = 2 * ATB_STG;   // 139264

__device__ __forceinline__ void atb_fill(char* smem, uint32_t sb, int s, int c,
        const __half* Ah, const __half* Al,
        const __half* Bh, const __half* Bl) {
    int tid = threadIdx.x;
    const __half* srcs[4] = {Ah, Al, Bh, Bl};
#pragma unroll
    for (int p = 0; p < 4; p++) {
        uint32_t base = sb + s * ATB_STG + p * ATB_MAT;
        const __half* src = srcs[p];
#pragma unroll
        for (int i = 0; i < 4; i++) {
            int id = tid + i * 256;
            int row = id >> 4, c16 = id & 15;
            cp16(base + row * 272 + c16 * 16,
                 src + (size_t)(c * 64 + row) * DIMM + c16 * 8);
        }
    }
    asm volatile("cp.async.commit_group;\n");
}

__device__ __forceinline__ void atb_compute(uint32_t sb, int s, float acc[4][4][4],
                                            int wm, int wn, int lane) {
    uint32_t bA  = sb + s * ATB_STG;
    uint32_t bAl = bA + ATB_MAT;
    uint32_t bB  = bA + 2 * ATB_MAT;
    uint32_t bBl = bA + 3 * ATB_MAT;
    int la7 = lane & 7;
    int arow = ((lane >> 4) << 3) + la7;
    int acol = (((lane >> 3) & 1) << 3);
    int brow = (((lane >> 3) & 1) << 3) + la7;
    int bcol = ((lane >> 4) << 3);
#pragma unroll
    for (int kc = 0; kc < 4; kc++) {
        uint32_t ah[4][4], al[4][4];
#pragma unroll
        for (int mi = 0; mi < 4; mi++) {
            uint32_t off = (uint32_t)(kc * 16 + arow) * 272 +
                           (uint32_t)(wm * 64 + mi * 16 + acol) * 2;
            ldsm_x4_t(ah[mi], bA + off);
            ldsm_x4_t(al[mi], bAl + off);
        }
        uint32_t bh[4][2], bl[4][2];
#pragma unroll
        for (int nh = 0; nh < 2; nh++) {
            uint32_t off = (uint32_t)(kc * 16 + brow) * 272 +
                           (uint32_t)(wn * 32 + nh * 16 + bcol) * 2;
            uint32_t r[4];
            ldsm_x4_t(r, bB + off);
            bh[2 * nh][0] = r[0]; bh[2 * nh][1] = r[1];
            bh[2 * nh + 1][0] = r[2]; bh[2 * nh + 1][1] = r[3];
            ldsm_x4_t(r, bBl + off);
            bl[2 * nh][0] = r[0]; bl[2 * nh][1] = r[1];
            bl[2 * nh + 1][0] = r[2]; bl[2 * nh + 1][1] = r[3];
        }
#pragma unroll
        for (int mi = 0; mi < 4; mi++)
#pragma unroll
            for (int ni = 0; ni < 4; ni++) mma_f16(acc[mi][ni], ah[mi], bh[ni]);
#pragma unroll
        for (int mi = 0; mi < 4; mi++)
#pragma unroll
            for (int ni = 0; ni < 4; ni++) mma_f16(acc[mi][ni], al[mi], bh[ni]);
#pragma unroll
        for (int mi = 0; mi < 4; mi++)
#pragma unroll
            for (int ni = 0; ni < 4; ni++) mma_f16(acc[mi][ni], ah[mi], bl[ni]);
    }
}

__device__ void kvm_body(char* smem, int blk) {
    int h = blk >> 4, qi = blk & 15;
    size_t off = (size_t)(qi * NN) * DIMM + h * DD;
    uint32_t sb = smem_u32(smem);
    int tid = threadIdx.x, lane = tid & 31, wid = tid >> 5;
    int wm = wid >> 2, wn = wid & 3;
    float acc[4][4][4];
#pragma unroll
    for (int i = 0; i < 4; i++)
#pragma unroll
        for (int j = 0; j < 4; j++)
#pragma unroll
            for (int q = 0; q < 4; q++) acc[i][j][q] = 0.f;

    atb_fill(smem, sb, 0, 0, d_fkh + off, d_fkl + off, d_vth + off, d_vtl + off);
    for (int c = 0; c < 8; c++) {
        asm volatile("cp.async.wait_group 0;\n");
        __syncthreads();
        if (c + 1 < 8)
            atb_fill(smem, sb, (c + 1) & 1, c + 1, d_fkh + off, d_fkl + off, d_vth + off, d_vtl + off);
        atb_compute(sb, c & 1, acc, wm, wn, lane);
    }
    __half* Oh = d_Mh + (size_t)blk * DD * DD;
    __half* Ol = d_Ml + (size_t)blk * DD * DD;
#pragma unroll
    for (int mi = 0; mi < 4; mi++) {
        int d0 = wm * 64 + mi * 16 + (lane >> 2);
#pragma unroll
        for (int ni = 0; ni < 4; ni++) {
            int e = wn * 32 + ni * 8 + (lane & 3) * 2;
            uint32_t hh, ll;
            hsplit2(acc[mi][ni][0], acc[mi][ni][1], hh, ll);
            *(uint32_t*)(Oh + d0 * DD + e) = hh;
            *(uint32_t*)(Ol + d0 * DD + e) = ll;
            hsplit2(acc[mi][ni][2], acc[mi][ni][3], hh, ll);
            *(uint32_t*)(Oh + (d0 + 8) * DD + e) = hh;
            *(uint32_t*)(Ol + (d0 + 8) * DD + e) = ll;
        }
    }
}

__device__ void gram1_body(char* smem, int ch, int h) {
    const __half* A = d_qch + (size_t)(ch * 512) * DIMM + h * DD;
    uint32_t sb = smem_u32(smem);
    int tid = threadIdx.x, lane = tid & 31, wid = tid >> 5;
    int wm = wid >> 2, wn = wid & 3;
    int la7 = lane & 7;
    float acc[4][4][4];
#pragma unroll
    for (int i = 0; i < 4; i++)
#pragma unroll
        for (int j = 0; j < 4; j++)
#pragma unroll
            for (int q = 0; q < 4; q++) acc[i][j][q] = 0.f;

    auto fill = [&](int s, int c) {
#pragma unroll
        for (int i = 0; i < 4; i++) {
            int id = tid + i * 256;
            int row = id >> 4, c16 = id & 15;
            cp16(sb + s * ATB_MAT + row * 272 + c16 * 16,
                 A + (size_t)(c * 64 + row) * DIMM + c16 * 8);
        }
        asm volatile("cp.async.commit_group;\n");
    };

    fill(0, 0);
    int arow = ((lane >> 4) << 3) + la7;
    int acol = (((lane >> 3) & 1) << 3);
    int brow = (((lane >> 3) & 1) << 3) + la7;
    int bcol = ((lane >> 4) << 3);
    for (int c = 0; c < 8; c++) {
        asm volatile("cp.async.wait_group 0;\n");
        __syncthreads();
        if (c + 1 < 8) fill((c + 1) & 1, c + 1);
        uint32_t bA = sb + (c & 1) * ATB_MAT;
#pragma unroll
        for (int kc = 0; kc < 4; kc++) {
            uint32_t ah[4][4];
#pragma unroll
            for (int mi = 0; mi < 4; mi++) {
                uint32_t off = (uint32_t)(kc * 16 + arow) * 272 +
                               (uint32_t)(wm * 64 + mi * 16 + acol) * 2;
                ldsm_x4_t(ah[mi], bA + off);
            }
            uint32_t bh[4][2];
#pragma unroll
            for (int nh = 0; nh < 2; nh++) {
                uint32_t off = (uint32_t)(kc * 16 + brow) * 272 +
                               (uint32_t)(wn * 32 + nh * 16 + bcol) * 2;
                uint32_t r[4];
                ldsm_x4_t(r, bA + off);
                bh[2 * nh][0] = r[0]; bh[2 * nh][1] = r[1];
                bh[2 * nh + 1][0] = r[2]; bh[2 * nh + 1][1] = r[3];
            }
#pragma unroll
            for (int mi = 0; mi < 4; mi++)
#pragma unroll
                for (int ni = 0; ni < 4; ni++) mma_f16(acc[mi][ni], ah[mi], bh[ni]);
        }
    }
    float* Cf = d_Cpart[h * GCH + ch];
#pragma unroll
    for (int mi = 0; mi < 4; mi++) {
        int d0 = wm * 64 + mi * 16 + (lane >> 2);
#pragma unroll
        for (int ni = 0; ni < 4; ni++) {
            int e = wn * 32 + ni * 8 + (lane & 3) * 2;
            *(float2*)(Cf + d0 * DD + e) = make_float2(acc[mi][ni][0], acc[mi][ni][1]);
            *(float2*)(Cf + (d0 + 8) * DD + e) = make_float2(acc[mi][ni][2], acc[mi][ni][3]);
        }
    }
}

__device__ void gpart_body(int b) {
    int r0 = b * 32;
    int t = threadIdx.x;
    float2 sq0 = {0.f, 0.f}, sq1 = {0.f, 0.f};
    float2 sk0 = {0.f, 0.f}, sk1 = {0.f, 0.f};
    for (int row = 0; row < 32; row++) {
        const __half2* fq = (const __half2*)(d_fqh + (size_t)(r0 + row) * DIMM);
        const __half2* fk = (const __half2*)(d_fkh + (size_t)(r0 + row) * DIMM);
        float2 a = __half22float2(fq[t]);       sq0.x += a.x; sq0.y += a.y;
        float2 c = __half22float2(fq[t + 256]); sq1.x += c.x; sq1.y += c.y;
        float2 e = __half22float2(fk[t]);       sk0.x += e.x; sk0.y += e.y;
        float2 f = __half22float2(fk[t + 256]); sk1.x += f.x; sk1.y += f.y;
    }
    d_gpart[b][2 * t] = sq0.x;       d_gpart[b][2 * t + 1] = sq0.y;
    d_gpart[b][512 + 2 * t] = sq1.x; d_gpart[b][512 + 2 * t + 1] = sq1.y;
    d_gpart[b][DIMM + 2 * t] = sk0.x;       d_gpart[b][DIMM + 2 * t + 1] = sk0.y;
    d_gpart[b][DIMM + 512 + 2 * t] = sk1.x; d_gpart[b][DIMM + 512 + 2 * t + 1] = sk1.y;
}

__device__ void gv_body(int blk) {
    int h = blk >> 4, qi = blk & 15;
    int r0 = qi * NN;
    int tid = threadIdx.x;
    int e = tid & 127, half = tid >> 7;
    __shared__ float kr[NN];
    __shared__ float part[2][DD];
    for (int i = tid; i < NN; i += 256) kr[i] = d_kr[h][r0 + i];
    __syncthreads();
    float a0 = 0.f, a1 = 0.f;
    int nb = half * 256;
    const __half* vh = d_fvh + (size_t)(r0 + nb) * DIMM + h * DD + e;
    const __half* vl = d_fvl + (size_t)(r0 + nb) * DIMM + h * DD + e;
#pragma unroll 2
    for (int n = 0; n < 256; n += 2) {
        a0 += kr[nb + n] * (__half2float(vh[(size_t)n * DIMM]) + __half2float(vl[(size_t)n * DIMM]));
        a1 += kr[nb + n + 1] * (__half2float(vh[(size_t)(n + 1) * DIMM]) + __half2float(vl[(size_t)(n + 1) * DIMM]));
    }
    part[half][e] = a0 + a1;
    __syncthreads();
    if (half == 0) d_gv[blk][e] = part[0][e] + part[1][e];
}

// mid_kernel: 0..127 kvm | 128..255 gram1 | 256..511 gpart | 512..639 gv
__global__ void __launch_bounds__(256, 1) mid_kernel() {
    extern __shared__ char smem[];
    int b = blockIdx.x;
    if (b < 128) kvm_body(smem, b);
    else if (b < 256) { int i = b - 128; gram1_body(smem, i & 15, i >> 4); }
    else if (b < 512) gpart_body(b - 256);
    else gv_body(b - 512);
}

// ---------------- creduce1: gram partial reduce ----------------
__global__ void creduce1_kernel() {
    int ch = blockIdx.x;
    int h = blockIdx.y;
    int tid = threadIdx.x;
    float ssum = 0.f;
#pragma unroll
    for (int u = 0; u < 4; u++) {
        int i = ch * 1024 + tid + u * 256;
        float c = 0.f;
#pragma unroll
        for (int p = 0; p < GCH; p++) c += d_Cpart[h * GCH + p][i];
        if ((i / DD) != (i % DD)) ssum += c * c;
    }
    __shared__ float sh[8];
    ssum = warpsum(ssum);
    int w = tid >> 5, lane = tid & 31;
    if (lane == 0) sh[w] = ssum;
    __syncthreads();
    if (tid == 0) {
        float S = 0.f;
#pragma unroll
        for (int i = 0; i < 8; i++) S += sh[i];
        d_cred[h][ch] = S;
    }
}

// ---------------- weight-predictor MLP (+ inline creduce2) ----------------
__global__ void wp_kernel(const float* __restrict__ w1, const float* __restrict__ b1,
                          const float* __restrict__ lng, const float* __restrict__ lnb,
                          const float* __restrict__ w2, const float* __restrict__ b2) {
    __shared__ float qg[DIMM], kg[DIMM];
    __shared__ float h1[HH][DD];
    __shared__ float logits[HH][3];
    __shared__ float sdsc[HH];
    int tid = threadIdx.x;
    if (tid < 8) {
        float S = 0.f;
#pragma unroll
        for (int i = 0; i < 16; i++) S += d_cred[tid][i];
        float fro = sqrtf(S) * (1.f / RTOT);
        float score = fro * (1.f / (128.f * 128.f));
        sdsc[tid] = expf(-5.f * score);
    }
    for (int i = tid; i < DIMM; i += 256) {
        float s = 0.f, s2 = 0.f;
        for (int b = 0; b < 256; b++) { s += d_gpart[b][i]; s2 += d_gpart[b][DIMM + i]; }
        qg[i] = s * (1.f / RTOT);
        kg[i] = s2 * (1.f / RTOT);
    }
    __syncthreads();
    for (int idx = tid; idx < HH * DD; idx += 256) {
        int h = idx / DD, i = idx % DD;
        float s = b1[i];
        const float* wr = w1 + i * 256;
#pragma unroll 4
        for (int j = 0; j < 128; j++) s += qg[h * 128 + j] * wr[j];
#pragma unroll 4
        for (int j = 0; j < 128; j++) s += kg[h * 128 + j] * wr[128 + j];
        h1[h][i] = s;
    }
    __syncthreads();
    int w = tid >> 5, lane = tid & 31;
    if (w < 8) {
        float s = 0.f, sq = 0.f;
        for (int i = lane; i < DD; i += 32) { float v = h1[w][i]; s += v; sq += v * v; }
        s = warpsum(s); sq = warpsum(sq);
        float mean = s * (1.f / DD);
        float var = sq * (1.f / DD) - mean * mean;
        float rs = rsqrtf(var + 1e-5f);
        for (int i = lane; i < DD; i += 32) {
            float vv = (h1[w][i] - mean) * rs * lng[i] + lnb[i];
            h1[w][i] = fmaxf(vv, 0.f);
        }
    }
    __syncthreads();
    if (tid < 24) {
        int h = tid / 3, c = tid % 3;
        float s = b2[c];
        const float* wr = w2 + c * DD;
        for (int i = 0; i < DD; i++) s += h1[h][i] * wr[i];
        logits[h][c] = s;
    }
    __syncthreads();
    if (tid < 8) {
        float a = logits[tid][0], b = logits[tid][1], c = logits[tid][2];
        float m = fmaxf(a, fmaxf(b, c));
        float ea = expf(a - m), eb = expf(b - m), ec = expf(c - m);
        float inv = 1.f / (ea + eb + ec);
        d_s1[tid] = ea * inv + eb * inv * sdsc[tid];
        d_wws[tid] = ec * inv;
    }
}

// =====================================================================
//  attout: att[128x128] = f_q @ M (3-term), + rank-1 term -> oh/ol
// =====================================================================
static constexpr int AO_MAT = 128 * 272;       // 34816
static constexpr int AO_SMEM = 4 * AO_MAT;     // 139264

__global__ void __launch_bounds__(256, 1) attout_tc_kernel() {
    int blk = blockIdx.y, mt = blockIdx.x;
    int h = blk >> 4, qi = blk & 15;
    int r0g = qi * NN + mt * 128;
    int co = h * DD;
    extern __shared__ char smem[];
    uint32_t sb = smem_u32(smem);
    int tid = threadIdx.x, lane = tid & 31, wid = tid >> 5;
    int wm = wid >> 2, wn = wid & 3;
    int la7 = lane & 7;

    {
        const __half* Asrc[2] = {d_fqh, d_fql};
#pragma unroll
        for (int p = 0; p < 2; p++) {
            uint32_t base = sb + p * AO_MAT;
            const __half* src = Asrc[p] + (size_t)r0g * DIMM + co;
#pragma unroll
            for (int i = 0; i < 8; i++) {
                int id = tid + i * 256;
                int row = id >> 4, c16 = id & 15;
                cp16(base + row * 272 + c16 * 16, src + (size_t)row * DIMM + c16 * 8);
            }
        }
        const __half* Bsrc[2] = {d_Mh + (size_t)blk * DD * DD,
                                 d_Ml + (size_t)blk * DD * DD};
#pragma unroll
        for (int p = 0; p < 2; p++) {
            uint32_t base = sb + (2 + p) * AO_MAT;
            const __half* src = Bsrc[p];
#pragma unroll
            for (int i = 0; i < 8; i++) {
                int id = tid + i * 256;
                int row = id >> 4, c16 = id & 15;
                cp16(base + row * 272 + c16 * 16, src + row * DD + c16 * 8);
            }
        }
        asm volatile("cp.async.commit_group;\ncp.async.wait_group 0;\n");
        __syncthreads();
    }

    float acc[4][4][4];
#pragma unroll
    for (int i = 0; i < 4; i++)
#pragma unroll
        for (int j = 0; j < 4; j++)
#pragma unroll
            for (int q = 0; q < 4; q++) acc[i][j][q] = 0.f;

    uint32_t bA  = sb;
    uint32_t bAl = sb + AO_MAT;
    uint32_t bB  = sb + 2 * AO_MAT;
    uint32_t bBl = sb + 3 * AO_MAT;
    int brow = (((lane >> 3) & 1) << 3) + la7;
    int bcol = ((lane >> 4) << 3);
#pragma unroll
    for (int kc = 0; kc < 8; kc++) {
        uint32_t ah[4][4], al[4][4];
#pragma unroll
        for (int mi = 0; mi < 4; mi++) {
            uint32_t off = (uint32_t)(wm * 64 + mi * 16 + (lane & 15)) * 272 +
                           (uint32_t)(kc * 16 + ((lane >> 4) << 3)) * 2;
            ldsm_x4(ah[mi], bA + off);
            ldsm_x4(al[mi], bAl + off);
        }
        uint32_t bh[4][2], bl[4][2];
#pragma unroll
        for (int nh = 0; nh < 2; nh++) {
            uint32_t off = (uint32_t)(kc * 16 + brow) * 272 +
                           (uint32_t)(wn * 32 + nh * 16 + bcol) * 2;
            uint32_t r[4];
            ldsm_x4_t(r, bB + off);
            bh[2 * nh][0] = r[0]; bh[2 * nh][1] = r[1];
            bh[2 * nh + 1][0] = r[2]; bh[2 * nh + 1][1] = r[3];
            ldsm_x4_t(r, bBl + off);
            bl[2 * nh][0] = r[0]; bl[2 * nh][1] = r[1];
            bl[2 * nh + 1][0] = r[2]; bl[2 * nh + 1][1] = r[3];
        }
#pragma unroll
        for (int mi = 0; mi < 4; mi++)
#pragma unroll
            for (int ni = 0; ni < 4; ni++) mma_f16(acc[mi][ni], ah[mi], bh[ni]);
#pragma unroll
        for (int mi = 0; mi < 4; mi++)
#pragma unroll
            for (int ni = 0; ni < 4; ni++) mma_f16(acc[mi][ni], al[mi], bh[ni]);
#pragma unroll
        for (int mi = 0; mi < 4; mi++)
#pragma unroll
            for (int ni = 0; ni < 4; ni++) mma_f16(acc[mi][ni], ah[mi], bl[ni]);
    }

    float s1 = d_s1[h], ww = d_wws[h];
#pragma unroll
    for (int mi = 0; mi < 4; mi++) {
        int rA = r0g + wm * 64 + mi * 16 + (lane >> 2);
        int rB = rA + 8;
        float f1a = s1 * d_iqn[h][rA], f2a = ww * d_qr[h][rA];
        float f1b = s1 * d_iqn[h][rB], f2b = ww * d_qr[h][rB];
#pragma unroll
        for (int ni = 0; ni < 4; ni++) {
            int c = wn * 32 + ni * 8 + (lane & 3) * 2;
            float g0 = d_gv[blk][c], g1 = d_gv[blk][c + 1];
            float o0 = f1a * acc[mi][ni][0] + f2a * g0;
            float o1 = f1a * acc[mi][ni][1] + f2a * g1;
            float o2 = f1b * acc[mi][ni][2] + f2b * g0;
            float o3 = f1b * acc[mi][ni][3] + f2b * g1;
            uint32_t hh, ll;
            hsplit2(o0, o1, hh, ll);
            *(uint32_t*)(d_oh + (size_t)rA * DIMM + co + c) = hh;
            *(uint32_t*)(d_ol + (size_t)rA * DIMM + co + c) = ll;
            hsplit2(o2, o3, hh, ll);
            *(uint32_t*)(d_oh + (size_t)rB * DIMM + co + c) = hh;
            *(uint32_t*)(d_ol + (size_t)rB * DIMM + co + c) = ll;
        }
    }
}

// ---------------- launch ----------------
extern "C" void kernel_launch(void* const* d_in, const int* in_sizes, int n_in,
                              void* d_out, int out_size) {
    const float* q      = (const float*)d_in[0];
    const float* k      = (const float*)d_in[1];
    const float* v      = (const float*)d_in[2];
    const float* ln_g   = (const float*)d_in[3];
    const float* ln_b   = (const float*)d_in[4];
    const float* w_in   = (const float*)d_in[5];
    const float* wp_w1  = (const float*)d_in[6];
    const float* wp_b1  = (const float*)d_in[7];
    const float* wp_lng = (const float*)d_in[8];
    const float* wp_lnb = (const float*)d_in[9];
    const float* wp_w2  = (const float*)d_in[10];
    const float* wp_b2  = (const float*)d_in[11];
    const float* w_out  = (const float*)d_in[12];
    const float* b_out  = (const float*)d_in[13];
    float* out = (float*)d_out;

    cudaFuncSetAttribute(mm_proj_kernel, cudaFuncAttributeMaxDynamicSharedMemorySize, MM_SMEM);
    cudaFuncSetAttribute(mm_out_kernel, cudaFuncAttributeMaxDynamicSharedMemorySize, MM_SMEM);
    cudaFuncSetAttribute(mid_kernel, cudaFuncAttributeMaxDynamicSharedMemorySize, MID_SMEM);
    cudaFuncSetAttribute(attout_tc_kernel, cudaFuncAttributeMaxDynamicSharedMemorySize, AO_SMEM);

    lnwconv_kernel<<<3 * RTOT + 2 * DIMM, 256>>>(q, k, v, ln_g, ln_b, w_in, w_out);

    dim3 gproj(DIMM / 256, RTOT / 128, 3);   // (4, 64, 3)
    mm_proj_kernel<<<gproj, 256, MM_SMEM>>>();

    statsprep_kernel<<<RTOT, 256>>>();

    mid_kernel<<<640, 256, MID_SMEM>>>();

    dim3 gcr1(16, HH);
    creduce1_kernel<<<gcr1, 256>>>();
    wp_kernel<<<1, 256>>>(wp_w1, wp_b1, wp_lng, wp_lnb, wp_w2, wp_b2);

    dim3 gatt(4, HH * QBB);
    attout_tc_kernel<<<gatt, 256, AO_SMEM>>>();

    dim3 gout(DIMM / 256, RTOT / 128);       // (4, 64)
    mm_out_kernel<<<gout, 256, MM_SMEM>>>(b_out, out);
}